// round 1
// baseline (speedup 1.0000x reference)
#include <cuda_runtime.h>
#include <math.h>

#define EMB 1024
#define HID 4096
#define NH 16
#define DKH 64
#define BATCH 2
#define SEQ 2048
#define MROWS (BATCH * SEQ)   // 4096

// ---------------- scratch (allocation-free: __device__ globals) ----------------
__device__ float g_xn [MROWS * EMB];   // layernorm output (reused for ln1 and ln2)
__device__ float g_q  [MROWS * EMB];
__device__ float g_k  [MROWS * EMB];
__device__ float g_v  [MROWS * EMB];
__device__ float g_ao [MROWS * EMB];   // attention output (heads concatenated)
__device__ float g_h  [MROWS * EMB];   // residual after attention
__device__ float g_ffa[MROWS * HID];   // relu(ff1) activations

// ---------------- LayerNorm: scalar alpha/bias, Bessel std, /(std+eps) --------
__global__ void ln_kernel(const float* __restrict__ x, float* __restrict__ y,
                          const float* __restrict__ al, const float* __restrict__ be)
{
    int row = blockIdx.x;
    const float4* xr = (const float4*)(x + (size_t)row * EMB);
    float4 v = xr[threadIdx.x];
    float s  = v.x + v.y + v.z + v.w;
    float ss = v.x*v.x + v.y*v.y + v.z*v.z + v.w*v.w;
    #pragma unroll
    for (int off = 16; off; off >>= 1) {
        s  += __shfl_xor_sync(0xffffffffu, s,  off);
        ss += __shfl_xor_sync(0xffffffffu, ss, off);
    }
    __shared__ float rs[8], rss[8];
    int warp = threadIdx.x >> 5, lane = threadIdx.x & 31;
    if (lane == 0) { rs[warp] = s; rss[warp] = ss; }
    __syncthreads();
    if (warp == 0) {
        s  = (lane < 8) ? rs[lane]  : 0.f;
        ss = (lane < 8) ? rss[lane] : 0.f;
        #pragma unroll
        for (int off = 16; off; off >>= 1) {
            s  += __shfl_xor_sync(0xffffffffu, s,  off);
            ss += __shfl_xor_sync(0xffffffffu, ss, off);
        }
        if (lane == 0) { rs[0] = s; rss[0] = ss; }
    }
    __syncthreads();
    s = rs[0]; ss = rss[0];
    float mean = s * (1.0f / EMB);
    float var  = fmaxf(ss - (float)EMB * mean * mean, 0.f) * (1.0f / (EMB - 1));
    float inv  = al[0] / (sqrtf(var) + 1e-6f);
    float bb   = be[0];
    float4 o;
    o.x = (v.x - mean) * inv + bb;
    o.y = (v.y - mean) * inv + bb;
    o.z = (v.z - mean) * inv + bb;
    o.w = (v.w - mean) * inv + bb;
    ((float4*)(y + (size_t)row * EMB))[threadIdx.x] = o;
}

// ---------------- SGEMM: C = [res +] [relu](A[M,K] @ W[K,N] [+ bias]) ---------
// 128x128 tile, BK=16, 256 threads, 8x8 micro-tile.
template<int RELU>
__global__ __launch_bounds__(256)
void sgemm_kernel(const float* __restrict__ A, const float* __restrict__ W,
                  float* __restrict__ C, const float* __restrict__ bias,
                  const float* __restrict__ res, int M, int N, int K)
{
    __shared__ float As[16][128];
    __shared__ float Bs[16][128];
    int tid = threadIdx.x;
    int bm = blockIdx.y, bn = blockIdx.x;
    int ty = tid >> 4, tx = tid & 15;
    int m0 = ty * 8, n0 = tx * 8;

    int rowA = tid >> 2, colA = (tid & 3) * 4;   // A tile loader: 64 rows/pass
    int rowB = tid >> 5, colB = (tid & 31) * 4;  // B tile loader: 8 rows/pass

    const float* Ab = A + (size_t)bm * 128 * K;
    const float* Wb = W + (size_t)bn * 128;

    float acc[8][8];
    #pragma unroll
    for (int i = 0; i < 8; i++)
        #pragma unroll
        for (int j = 0; j < 8; j++) acc[i][j] = 0.f;

    for (int k0 = 0; k0 < K; k0 += 16) {
        float4 a0 = *(const float4*)&Ab[(size_t)rowA        * K + k0 + colA];
        float4 a1 = *(const float4*)&Ab[(size_t)(rowA + 64) * K + k0 + colA];
        float4 b0 = *(const float4*)&Wb[(size_t)(k0 + rowB)     * N + colB];
        float4 b1 = *(const float4*)&Wb[(size_t)(k0 + rowB + 8) * N + colB];
        __syncthreads();
        As[colA + 0][rowA] = a0.x;  As[colA + 1][rowA] = a0.y;
        As[colA + 2][rowA] = a0.z;  As[colA + 3][rowA] = a0.w;
        As[colA + 0][rowA + 64] = a1.x;  As[colA + 1][rowA + 64] = a1.y;
        As[colA + 2][rowA + 64] = a1.z;  As[colA + 3][rowA + 64] = a1.w;
        *(float4*)&Bs[rowB][colB]     = b0;
        *(float4*)&Bs[rowB + 8][colB] = b1;
        __syncthreads();
        #pragma unroll
        for (int kk = 0; kk < 16; kk++) {
            float4 av0 = *(const float4*)&As[kk][m0];
            float4 av1 = *(const float4*)&As[kk][m0 + 4];
            float4 bv0 = *(const float4*)&Bs[kk][n0];
            float4 bv1 = *(const float4*)&Bs[kk][n0 + 4];
            float a[8] = {av0.x, av0.y, av0.z, av0.w, av1.x, av1.y, av1.z, av1.w};
            float b[8] = {bv0.x, bv0.y, bv0.z, bv0.w, bv1.x, bv1.y, bv1.z, bv1.w};
            #pragma unroll
            for (int i = 0; i < 8; i++)
                #pragma unroll
                for (int j = 0; j < 8; j++)
                    acc[i][j] = fmaf(a[i], b[j], acc[i][j]);
        }
    }

    #pragma unroll
    for (int i = 0; i < 8; i++) {
        int r = bm * 128 + m0 + i;
        #pragma unroll
        for (int j = 0; j < 8; j++) {
            int c = bn * 128 + n0 + j;
            float val = acc[i][j];
            if (bias) val += bias[c];
            if (RELU) val = fmaxf(val, 0.f);
            if (res)  val += res[(size_t)r * N + c];
            C[(size_t)r * N + c] = val;
        }
    }
}

// ---------------- Flash attention (fp32, online softmax) ---------------------
// grid: (SEQ/64, BATCH*NH). 64 queries x 64 keys tiles, dk=64.
#define LDW 68   // padded row stride in floats (bank-conflict avoidance)

__global__ __launch_bounds__(256)
void attn_kernel(const float* __restrict__ q, const float* __restrict__ k,
                 const float* __restrict__ v, const int* __restrict__ mask,
                 float* __restrict__ o)
{
    extern __shared__ float sm[];
    float* Qs = sm;
    float* Ks = sm + 64 * LDW;
    float* Vs = sm + 2 * 64 * LDW;
    float* Ps = sm + 3 * 64 * LDW;

    int tid = threadIdx.x;
    int bh = blockIdx.y;
    int b = bh >> 4, h = bh & 15;
    int qbase = blockIdx.x * 64;
    int ty = tid >> 4, tx = tid & 15;
    int ty4 = ty * 4, tx4 = tx * 4;

    int lr = tid >> 4;          // loader row 0..15
    int lc = (tid & 15) * 4;    // loader col 0..60

    const float* qb = q + ((size_t)(b * SEQ + qbase)) * EMB + h * DKH;
    const float* kb = k + ((size_t)(b * SEQ)) * EMB + h * DKH;
    const float* vb = v + ((size_t)(b * SEQ)) * EMB + h * DKH;
    const int*   mb = mask + (size_t)b * SEQ;

    #pragma unroll
    for (int p = 0; p < 4; p++) {
        int r = p * 16 + lr;
        *(float4*)&Qs[r * LDW + lc] = *(const float4*)&qb[(size_t)r * EMB + lc];
    }

    float m_i[4], l_i[4], oacc[4][4];
    #pragma unroll
    for (int ri = 0; ri < 4; ri++) {
        m_i[ri] = -3.0e38f; l_i[ri] = 0.f;
        #pragma unroll
        for (int di = 0; di < 4; di++) oacc[ri][di] = 0.f;
    }

    for (int jt = 0; jt < SEQ / 64; jt++) {
        int jbase = jt * 64;
        __syncthreads();   // previous tile's Vs/Ps reads done; Qs visible on jt=0
        #pragma unroll
        for (int p = 0; p < 4; p++) {
            int r = p * 16 + lr;
            *(float4*)&Ks[r * LDW + lc] = *(const float4*)&kb[(size_t)(jbase + r) * EMB + lc];
            *(float4*)&Vs[r * LDW + lc] = *(const float4*)&vb[(size_t)(jbase + r) * EMB + lc];
        }
        __syncthreads();

        // S tile 4x4 per thread: rows ty4.., cols tx4..
        float s[4][4];
        #pragma unroll
        for (int ri = 0; ri < 4; ri++)
            #pragma unroll
            for (int ci = 0; ci < 4; ci++) s[ri][ci] = 0.f;

        for (int d = 0; d < DKH; d += 4) {
            float4 qa[4], kv[4];
            #pragma unroll
            for (int ri = 0; ri < 4; ri++) qa[ri] = *(const float4*)&Qs[(ty4 + ri) * LDW + d];
            #pragma unroll
            for (int ci = 0; ci < 4; ci++) kv[ci] = *(const float4*)&Ks[(tx4 + ci) * LDW + d];
            #pragma unroll
            for (int ri = 0; ri < 4; ri++)
                #pragma unroll
                for (int ci = 0; ci < 4; ci++)
                    s[ri][ci] += qa[ri].x * kv[ci].x + qa[ri].y * kv[ci].y
                               + qa[ri].z * kv[ci].z + qa[ri].w * kv[ci].w;
        }

        int mv[4];
        #pragma unroll
        for (int ci = 0; ci < 4; ci++) mv[ci] = mb[jbase + tx4 + ci];
        #pragma unroll
        for (int ri = 0; ri < 4; ri++)
            #pragma unroll
            for (int ci = 0; ci < 4; ci++) {
                s[ri][ci] *= 0.125f;                 // 1/sqrt(64)
                if (mv[ci] == 0) s[ri][ci] = -1e30f;
            }

        // online softmax, rows shared across the 16 tx lanes
        #pragma unroll
        for (int ri = 0; ri < 4; ri++) {
            float mx = fmaxf(fmaxf(s[ri][0], s[ri][1]), fmaxf(s[ri][2], s[ri][3]));
            #pragma unroll
            for (int off = 8; off; off >>= 1)
                mx = fmaxf(mx, __shfl_xor_sync(0xffffffffu, mx, off, 16));
            float mnew  = fmaxf(m_i[ri], mx);
            float alpha = __expf(m_i[ri] - mnew);
            float ls = 0.f;
            #pragma unroll
            for (int ci = 0; ci < 4; ci++) {
                float pv = __expf(s[ri][ci] - mnew);
                s[ri][ci] = pv;
                ls += pv;
            }
            #pragma unroll
            for (int off = 8; off; off >>= 1)
                ls += __shfl_xor_sync(0xffffffffu, ls, off, 16);
            l_i[ri] = l_i[ri] * alpha + ls;
            m_i[ri] = mnew;
            #pragma unroll
            for (int di = 0; di < 4; di++) oacc[ri][di] *= alpha;
            #pragma unroll
            for (int ci = 0; ci < 4; ci++)
                Ps[(ty4 + ri) * LDW + tx4 + ci] = s[ri][ci];
        }
        __syncthreads();

        // O += P @ V (thread owns rows ty4.., dims tx4..)
        for (int c = 0; c < 64; c++) {
            float4 vv = *(const float4*)&Vs[c * LDW + tx4];
            float p0 = Ps[(ty4 + 0) * LDW + c];
            float p1 = Ps[(ty4 + 1) * LDW + c];
            float p2 = Ps[(ty4 + 2) * LDW + c];
            float p3 = Ps[(ty4 + 3) * LDW + c];
            oacc[0][0] += p0 * vv.x; oacc[0][1] += p0 * vv.y; oacc[0][2] += p0 * vv.z; oacc[0][3] += p0 * vv.w;
            oacc[1][0] += p1 * vv.x; oacc[1][1] += p1 * vv.y; oacc[1][2] += p1 * vv.z; oacc[1][3] += p1 * vv.w;
            oacc[2][0] += p2 * vv.x; oacc[2][1] += p2 * vv.y; oacc[2][2] += p2 * vv.z; oacc[2][3] += p2 * vv.w;
            oacc[3][0] += p3 * vv.x; oacc[3][1] += p3 * vv.y; oacc[3][2] += p3 * vv.z; oacc[3][3] += p3 * vv.w;
        }
    }

    float* ob = o + ((size_t)(b * SEQ + qbase)) * EMB + h * DKH;
    #pragma unroll
    for (int ri = 0; ri < 4; ri++) {
        float inv = 1.f / l_i[ri];
        float4 w;
        w.x = oacc[ri][0] * inv; w.y = oacc[ri][1] * inv;
        w.z = oacc[ri][2] * inv; w.w = oacc[ri][3] * inv;
        *(float4*)&ob[(size_t)(ty4 + ri) * EMB + tx4] = w;
    }
}

// ---------------- launch ------------------------------------------------------
extern "C" void kernel_launch(void* const* d_in, const int* in_sizes, int n_in,
                              void* d_out, int out_size)
{
    const float* x    = (const float*)d_in[0];
    const int*   mask = (const int*)  d_in[1];
    const float* wq   = (const float*)d_in[2];
    const float* wk   = (const float*)d_in[3];
    const float* wv   = (const float*)d_in[4];
    const float* wo   = (const float*)d_in[5];
    const float* ff1w = (const float*)d_in[6];
    const float* ff1b = (const float*)d_in[7];
    const float* ff2w = (const float*)d_in[8];
    const float* ff2b = (const float*)d_in[9];
    const float* ln1a = (const float*)d_in[10];
    const float* ln1b = (const float*)d_in[11];
    const float* ln2a = (const float*)d_in[12];
    const float* ln2b = (const float*)d_in[13];
    float* out = (float*)d_out;

    float *xn, *q, *k, *v, *ao, *h, *ffa;
    cudaGetSymbolAddress((void**)&xn,  g_xn);
    cudaGetSymbolAddress((void**)&q,   g_q);
    cudaGetSymbolAddress((void**)&k,   g_k);
    cudaGetSymbolAddress((void**)&v,   g_v);
    cudaGetSymbolAddress((void**)&ao,  g_ao);
    cudaGetSymbolAddress((void**)&h,   g_h);
    cudaGetSymbolAddress((void**)&ffa, g_ffa);

    const int attn_smem = 4 * 64 * LDW * sizeof(float);  // 69632 B
    cudaFuncSetAttribute(attn_kernel, cudaFuncAttributeMaxDynamicSharedMemorySize, attn_smem);

    dim3 gE(EMB / 128, MROWS / 128);   // N=1024 gemms
    dim3 gH(HID / 128, MROWS / 128);   // N=4096 gemm

    // 1) ln1(x) -> xn
    ln_kernel<<<MROWS, 256>>>(x, xn, ln1a, ln1b);
    // 2-4) Q/K/V projections
    sgemm_kernel<0><<<gE, 256>>>(xn, wq, q, nullptr, nullptr, MROWS, EMB, EMB);
    sgemm_kernel<0><<<gE, 256>>>(xn, wk, k, nullptr, nullptr, MROWS, EMB, EMB);
    sgemm_kernel<0><<<gE, 256>>>(xn, wv, v, nullptr, nullptr, MROWS, EMB, EMB);
    // 5) attention -> ao (heads concatenated)
    attn_kernel<<<dim3(SEQ / 64, BATCH * NH), 256, attn_smem>>>(q, k, v, mask, ao);
    // 6) output projection + residual: h = x + ao @ wo
    sgemm_kernel<0><<<gE, 256>>>(ao, wo, h, nullptr, x, MROWS, EMB, EMB);
    // 7) ln2(h) -> xn (reuse)
    ln_kernel<<<MROWS, 256>>>(h, xn, ln2a, ln2b);
    // 8) ffa = relu(xn @ ff1_w + ff1_b)
    sgemm_kernel<1><<<gH, 256>>>(xn, ff1w, ffa, ff1b, nullptr, MROWS, HID, EMB);
    // 9) out = h + ffa @ ff2_w + ff2_b
    sgemm_kernel<0><<<gE, 256>>>(ffa, ff2w, out, ff2b, h, MROWS, EMB, HID);
}

// round 4
// speedup vs baseline: 1.3943x; 1.3943x over previous
#include <cuda_runtime.h>
#include <cuda_bf16.h>
#include <math.h>
#include <stdint.h>

#define EMB 1024
#define HID 4096
#define NH 16
#define DKH 64
#define BATCH 2
#define SEQ 2048
#define MROWS (BATCH * SEQ)     // 4096
#define K3E (3 * EMB)           // 3072
#define K3H (3 * HID)           // 12288
#define QKVW (3 * EMB)

// ---------------- scratch (__device__ globals, allocation-free) ---------------
__device__ __nv_bfloat16 g_a3a[MROWS * K3E];
__device__ __nv_bfloat16 g_a3b[MROWS * K3E];
__device__ __nv_bfloat16 g_a3c[(size_t)MROWS * K3H];
__device__ __nv_bfloat16 g_w3 [(size_t)HID * K3E];
__device__ float g_qkv[(size_t)MROWS * QKVW];
__device__ float g_h[MROWS * EMB];

// ---------------- PTX helpers (base ISA only: sm_80-era) ----------------------
__device__ __forceinline__ uint32_t smem_u32(const void* p) {
    return (uint32_t)__cvta_generic_to_shared(p);
}
__device__ __forceinline__ void cp16(uint32_t dst, const void* src) {
    asm volatile("cp.async.cg.shared.global [%0], [%1], 16;" :: "r"(dst), "l"(src));
}
__device__ __forceinline__ void cp_commit() {
    asm volatile("cp.async.commit_group;");
}
template<int N> __device__ __forceinline__ void cp_wait() {
    asm volatile("cp.async.wait_group %0;" :: "n"(N));
}
__device__ __forceinline__ void ldsm_x4(uint32_t* r, uint32_t addr) {
    asm volatile("ldmatrix.sync.aligned.m8n8.x4.shared.b16 {%0,%1,%2,%3}, [%4];"
                 : "=r"(r[0]), "=r"(r[1]), "=r"(r[2]), "=r"(r[3]) : "r"(addr));
}
__device__ __forceinline__ void mma16816(float* d, const uint32_t* a, const uint32_t* b) {
    asm volatile(
        "mma.sync.aligned.m16n8k16.row.col.f32.bf16.bf16.f32 "
        "{%0,%1,%2,%3}, {%4,%5,%6,%7}, {%8,%9}, {%0,%1,%2,%3};"
        : "+f"(d[0]), "+f"(d[1]), "+f"(d[2]), "+f"(d[3])
        : "r"(a[0]), "r"(a[1]), "r"(a[2]), "r"(a[3]), "r"(b[0]), "r"(b[1]));
}

// ---------------- LayerNorm -> split-bf16 [hi | lo | hi] ----------------------
__global__ void ln_split_kernel(const float* __restrict__ x, __nv_bfloat16* __restrict__ y3,
                                const float* __restrict__ al, const float* __restrict__ be)
{
    int row = blockIdx.x;
    const float4* xr = (const float4*)(x + (size_t)row * EMB);
    float4 v = xr[threadIdx.x];
    float s  = v.x + v.y + v.z + v.w;
    float ss = v.x*v.x + v.y*v.y + v.z*v.z + v.w*v.w;
    #pragma unroll
    for (int off = 16; off; off >>= 1) {
        s  += __shfl_xor_sync(0xffffffffu, s,  off);
        ss += __shfl_xor_sync(0xffffffffu, ss, off);
    }
    __shared__ float rs[8], rss[8];
    int warp = threadIdx.x >> 5, lane = threadIdx.x & 31;
    if (lane == 0) { rs[warp] = s; rss[warp] = ss; }
    __syncthreads();
    if (warp == 0) {
        s  = (lane < 8) ? rs[lane]  : 0.f;
        ss = (lane < 8) ? rss[lane] : 0.f;
        #pragma unroll
        for (int off = 16; off; off >>= 1) {
            s  += __shfl_xor_sync(0xffffffffu, s,  off);
            ss += __shfl_xor_sync(0xffffffffu, ss, off);
        }
        if (lane == 0) { rs[0] = s; rss[0] = ss; }
    }
    __syncthreads();
    s = rs[0]; ss = rss[0];
    float mean = s * (1.0f / EMB);
    float var  = fmaxf(ss - (float)EMB * mean * mean, 0.f) * (1.0f / (EMB - 1));
    float inv  = al[0] / (sqrtf(var) + 1e-6f);
    float bb   = be[0];
    float o[4] = { (v.x - mean) * inv + bb, (v.y - mean) * inv + bb,
                   (v.z - mean) * inv + bb, (v.w - mean) * inv + bb };
    int col = threadIdx.x * 4;
    __nv_bfloat16* rowp = y3 + (size_t)row * K3E;
    #pragma unroll
    for (int p = 0; p < 2; p++) {
        __nv_bfloat162 hh, ll;
        float a0 = o[p*2], a1 = o[p*2+1];
        __nv_bfloat16 h0 = __float2bfloat16_rn(a0);
        __nv_bfloat16 h1 = __float2bfloat16_rn(a1);
        hh.x = h0; hh.y = h1;
        ll.x = __float2bfloat16_rn(a0 - __bfloat162float(h0));
        ll.y = __float2bfloat16_rn(a1 - __bfloat162float(h1));
        *(__nv_bfloat162*)(rowp + col + p*2)         = hh;
        *(__nv_bfloat162*)(rowp + EMB + col + p*2)   = ll;
        *(__nv_bfloat162*)(rowp + 2*EMB + col + p*2) = hh;
    }
}

// ---------------- weight transpose + split: W[K,N] -> WT3[N, 3K] --------------
__global__ void wt_split_kernel(const float* __restrict__ W, __nv_bfloat16* __restrict__ WT3,
                                int K, int N)
{
    __shared__ float t[32][33];
    int n0 = blockIdx.x * 32, k0 = blockIdx.y * 32;
    #pragma unroll
    for (int i = 0; i < 4; i++)
        t[threadIdx.y + 8*i][threadIdx.x] = W[(size_t)(k0 + threadIdx.y + 8*i) * N + n0 + threadIdx.x];
    __syncthreads();
    #pragma unroll
    for (int i = 0; i < 4; i++) {
        int n = n0 + threadIdx.y + 8*i;
        int k = k0 + threadIdx.x;
        float v = t[threadIdx.x][threadIdx.y + 8*i];
        __nv_bfloat16 hi = __float2bfloat16_rn(v);
        __nv_bfloat16 lo = __float2bfloat16_rn(v - __bfloat162float(hi));
        size_t rb = (size_t)n * (3 * (size_t)K);
        WT3[rb + k]       = hi;
        WT3[rb + K + k]   = hi;
        WT3[rb + 2*K + k] = lo;
    }
}

// ---------------- bf16 mma.sync GEMM: C[M,N] = A3[M,K3] @ BT3[N,K3]^T ---------
// 128x128 CTA tile, BK=32, 8 warps (2x4), warp tile 64x32, 3-stage cp.async.
#define ASTR 80                 // bytes per smem row (32 bf16 padded to 40)
#define STAGE_BYTES (2 * 128 * ASTR)   // A + B per stage = 20480
#define GSM_TOTAL (3 * STAGE_BYTES)    // 61440

template<int FF1>
__global__ void __launch_bounds__(256, 1)
gemm_mma(const __nv_bfloat16* __restrict__ A3, const __nv_bfloat16* __restrict__ BT3,
         float* __restrict__ C, __nv_bfloat16* __restrict__ Cs,
         const float* __restrict__ bias, const float* __restrict__ res,
         int M, int N, int K3)
{
    extern __shared__ char smem[];
    uint32_t sb = smem_u32(smem);
    int tid = threadIdx.x, wid = tid >> 5, lane = tid & 31;
    int bm = blockIdx.y, bn = blockIdx.x;
    int warp_m = wid >> 2, warp_n = wid & 3;

    const int nk = K3 / 32;

    // stage loader: 512 A-chunks + 512 B-chunks of 16B; 256 threads x 2 each
    auto load_stage = [&](int k0, int st) {
        uint32_t base = sb + st * STAGE_BYTES;
        #pragma unroll
        for (int hh = 0; hh < 2; hh++) {
            int c = tid + hh * 256;
            int row = c >> 2, kc = c & 3;
            cp16(base + row * ASTR + kc * 16,
                 A3 + (size_t)(bm * 128 + row) * K3 + k0 + kc * 8);
            cp16(base + 128 * ASTR + row * ASTR + kc * 16,
                 BT3 + (size_t)(bn * 128 + row) * K3 + k0 + kc * 8);
        }
        cp_commit();
    };

    load_stage(0, 0);
    load_stage(32, 1);

    float acc[4][4][4];
    #pragma unroll
    for (int i = 0; i < 4; i++)
        #pragma unroll
        for (int j = 0; j < 4; j++)
            #pragma unroll
            for (int r = 0; r < 4; r++) acc[i][j][r] = 0.f;

    // ldmatrix address bases (per-lane), relative to stage base
    // A (x4): lanes 0-15 -> m rows 0-15 khalf0; 16-31 -> m rows 0-15 khalf1
    uint32_t aBase = (uint32_t)((warp_m * 64 + (lane & 15)) * ASTR + (lane >> 4) * 16);
    // B (x4): group g=lane>>3: n = (g>>1)*8 + (lane&7), khalf = g&1
    uint32_t bBase = (uint32_t)(128 * ASTR +
                     (warp_n * 32 + ((lane >> 4) << 3) + (lane & 7)) * ASTR +
                     ((lane >> 3) & 1) * 16);

    for (int kt = 0; kt < nk; kt++) {
        cp_wait<1>();
        __syncthreads();
        int nxt = kt + 2;
        if (nxt < nk) load_stage(nxt * 32, nxt % 3);

        uint32_t stb = sb + (kt % 3) * STAGE_BYTES;
        #pragma unroll
        for (int s = 0; s < 2; s++) {
            uint32_t afr[4][4], bfr[2][4];
            #pragma unroll
            for (int i = 0; i < 4; i++)
                ldsm_x4(afr[i], stb + aBase + i * 16 * ASTR + s * 32);
            #pragma unroll
            for (int jj = 0; jj < 2; jj++)
                ldsm_x4(bfr[jj], stb + bBase + jj * 16 * ASTR + s * 32);
            #pragma unroll
            for (int i = 0; i < 4; i++) {
                #pragma unroll
                for (int j = 0; j < 4; j++)
                    mma16816(acc[i][j], afr[i], &bfr[j >> 1][(j & 1) * 2]);
            }
        }
        __syncthreads();
    }

    // epilogue
    int g = lane >> 2, tig = lane & 3;
    #pragma unroll
    for (int i = 0; i < 4; i++) {
        #pragma unroll
        for (int half = 0; half < 2; half++) {
            int row = bm * 128 + warp_m * 64 + i * 16 + g + half * 8;
            #pragma unroll
            for (int j = 0; j < 4; j++) {
                int col = bn * 128 + warp_n * 32 + j * 8 + tig * 2;
                float v0 = acc[i][j][half * 2];
                float v1 = acc[i][j][half * 2 + 1];
                if (FF1) {
                    v0 = fmaxf(v0 + bias[col], 0.f);
                    v1 = fmaxf(v1 + bias[col + 1], 0.f);
                    __nv_bfloat16 h0 = __float2bfloat16_rn(v0);
                    __nv_bfloat16 h1 = __float2bfloat16_rn(v1);
                    __nv_bfloat162 hh; hh.x = h0; hh.y = h1;
                    __nv_bfloat162 ll;
                    ll.x = __float2bfloat16_rn(v0 - __bfloat162float(h0));
                    ll.y = __float2bfloat16_rn(v1 - __bfloat162float(h1));
                    size_t rb = (size_t)row * (3 * (size_t)N);
                    *(__nv_bfloat162*)(Cs + rb + col)                 = hh;
                    *(__nv_bfloat162*)(Cs + rb + N + col)             = ll;
                    *(__nv_bfloat162*)(Cs + rb + 2 * (size_t)N + col) = hh;
                } else {
                    if (bias) { v0 += bias[col]; v1 += bias[col + 1]; }
                    size_t rb = (size_t)row * N;
                    if (res) {
                        float2 rr = *(const float2*)(res + rb + col);
                        v0 += rr.x; v1 += rr.y;
                    }
                    float2 o; o.x = v0; o.y = v1;
                    *(float2*)(C + rb + col) = o;
                }
            }
        }
    }
}

// ---------------- Flash attention (fp32, packed qkv) -> split-bf16 ------------
#define LDW 68

__global__ __launch_bounds__(256)
void attn_kernel(const float* __restrict__ qkv, const int* __restrict__ mask,
                 __nv_bfloat16* __restrict__ o3)
{
    extern __shared__ float sm[];
    float* Qs = sm;
    float* Ks = sm + 64 * LDW;
    float* Vs = sm + 2 * 64 * LDW;
    float* Ps = sm + 3 * 64 * LDW;

    int tid = threadIdx.x;
    int bh = blockIdx.y;
    int b = bh >> 4, hd = bh & 15;
    int qbase = blockIdx.x * 64;
    int ty = tid >> 4, tx = tid & 15;
    int ty4 = ty * 4, tx4 = tx * 4;

    int lr = tid >> 4;
    int lc = (tid & 15) * 4;

    const float* qb = qkv + ((size_t)(b * SEQ + qbase)) * QKVW + hd * DKH;
    const float* kb = qkv + ((size_t)(b * SEQ)) * QKVW + EMB + hd * DKH;
    const float* vb = qkv + ((size_t)(b * SEQ)) * QKVW + 2 * EMB + hd * DKH;
    const int*   mb = mask + (size_t)b * SEQ;

    #pragma unroll
    for (int p = 0; p < 4; p++) {
        int r = p * 16 + lr;
        *(float4*)&Qs[r * LDW + lc] = *(const float4*)&qb[(size_t)r * QKVW + lc];
    }

    float m_i[4], l_i[4], oacc[4][4];
    #pragma unroll
    for (int ri = 0; ri < 4; ri++) {
        m_i[ri] = -3.0e38f; l_i[ri] = 0.f;
        #pragma unroll
        for (int di = 0; di < 4; di++) oacc[ri][di] = 0.f;
    }

    for (int jt = 0; jt < SEQ / 64; jt++) {
        int jbase = jt * 64;
        __syncthreads();
        #pragma unroll
        for (int p = 0; p < 4; p++) {
            int r = p * 16 + lr;
            *(float4*)&Ks[r * LDW + lc] = *(const float4*)&kb[(size_t)(jbase + r) * QKVW + lc];
            *(float4*)&Vs[r * LDW + lc] = *(const float4*)&vb[(size_t)(jbase + r) * QKVW + lc];
        }
        __syncthreads();

        float s[4][4];
        #pragma unroll
        for (int ri = 0; ri < 4; ri++)
            #pragma unroll
            for (int ci = 0; ci < 4; ci++) s[ri][ci] = 0.f;

        for (int d = 0; d < DKH; d += 4) {
            float4 qa[4], kv[4];
            #pragma unroll
            for (int ri = 0; ri < 4; ri++) qa[ri] = *(const float4*)&Qs[(ty4 + ri) * LDW + d];
            #pragma unroll
            for (int ci = 0; ci < 4; ci++) kv[ci] = *(const float4*)&Ks[(tx4 + ci) * LDW + d];
            #pragma unroll
            for (int ri = 0; ri < 4; ri++)
                #pragma unroll
                for (int ci = 0; ci < 4; ci++)
                    s[ri][ci] += qa[ri].x * kv[ci].x + qa[ri].y * kv[ci].y
                               + qa[ri].z * kv[ci].z + qa[ri].w * kv[ci].w;
        }

        int mv[4];
        #pragma unroll
        for (int ci = 0; ci < 4; ci++) mv[ci] = mb[jbase + tx4 + ci];
        #pragma unroll
        for (int ri = 0; ri < 4; ri++)
            #pragma unroll
            for (int ci = 0; ci < 4; ci++) {
                s[ri][ci] *= 0.125f;
                if (mv[ci] == 0) s[ri][ci] = -1e30f;
            }

        #pragma unroll
        for (int ri = 0; ri < 4; ri++) {
            float mx = fmaxf(fmaxf(s[ri][0], s[ri][1]), fmaxf(s[ri][2], s[ri][3]));
            #pragma unroll
            for (int off = 8; off; off >>= 1)
                mx = fmaxf(mx, __shfl_xor_sync(0xffffffffu, mx, off, 16));
            float mnew  = fmaxf(m_i[ri], mx);
            float alpha = __expf(m_i[ri] - mnew);
            float ls = 0.f;
            #pragma unroll
            for (int ci = 0; ci < 4; ci++) {
                float pv = __expf(s[ri][ci] - mnew);
                s[ri][ci] = pv;
                ls += pv;
            }
            #pragma unroll
            for (int off = 8; off; off >>= 1)
                ls += __shfl_xor_sync(0xffffffffu, ls, off, 16);
            l_i[ri] = l_i[ri] * alpha + ls;
            m_i[ri] = mnew;
            #pragma unroll
            for (int di = 0; di < 4; di++) oacc[ri][di] *= alpha;
            #pragma unroll
            for (int ci = 0; ci < 4; ci++)
                Ps[(ty4 + ri) * LDW + tx4 + ci] = s[ri][ci];
        }
        __syncthreads();

        for (int c = 0; c < 64; c++) {
            float4 vv = *(const float4*)&Vs[c * LDW + tx4];
            float p0 = Ps[(ty4 + 0) * LDW + c];
            float p1 = Ps[(ty4 + 1) * LDW + c];
            float p2 = Ps[(ty4 + 2) * LDW + c];
            float p3 = Ps[(ty4 + 3) * LDW + c];
            oacc[0][0] += p0 * vv.x; oacc[0][1] += p0 * vv.y; oacc[0][2] += p0 * vv.z; oacc[0][3] += p0 * vv.w;
            oacc[1][0] += p1 * vv.x; oacc[1][1] += p1 * vv.y; oacc[1][2] += p1 * vv.z; oacc[1][3] += p1 * vv.w;
            oacc[2][0] += p2 * vv.x; oacc[2][1] += p2 * vv.y; oacc[2][2] += p2 * vv.z; oacc[2][3] += p2 * vv.w;
            oacc[3][0] += p3 * vv.x; oacc[3][1] += p3 * vv.y; oacc[3][2] += p3 * vv.z; oacc[3][3] += p3 * vv.w;
        }
    }

    #pragma unroll
    for (int ri = 0; ri < 4; ri++) {
        float inv = 1.f / l_i[ri];
        int grow = b * SEQ + qbase + ty4 + ri;
        __nv_bfloat16* base = o3 + (size_t)grow * K3E + hd * DKH + tx4;
        float w0 = oacc[ri][0] * inv, w1 = oacc[ri][1] * inv;
        float w2 = oacc[ri][2] * inv, w3 = oacc[ri][3] * inv;
        __nv_bfloat16 h0 = __float2bfloat16_rn(w0), h1 = __float2bfloat16_rn(w1);
        __nv_bfloat16 h2 = __float2bfloat16_rn(w2), h3 = __float2bfloat16_rn(w3);
        __nv_bfloat162 ha; ha.x = h0; ha.y = h1;
        __nv_bfloat162 hb; hb.x = h2; hb.y = h3;
        __nv_bfloat162 la, lb;
        la.x = __float2bfloat16_rn(w0 - __bfloat162float(h0));
        la.y = __float2bfloat16_rn(w1 - __bfloat162float(h1));
        lb.x = __float2bfloat16_rn(w2 - __bfloat162float(h2));
        lb.y = __float2bfloat16_rn(w3 - __bfloat162float(h3));
        *(__nv_bfloat162*)(base)             = ha;
        *(__nv_bfloat162*)(base + 2)         = hb;
        *(__nv_bfloat162*)(base + EMB)       = la;
        *(__nv_bfloat162*)(base + EMB + 2)   = lb;
        *(__nv_bfloat162*)(base + 2*EMB)     = ha;
        *(__nv_bfloat162*)(base + 2*EMB + 2) = hb;
    }
}

// ---------------- launch ------------------------------------------------------
extern "C" void kernel_launch(void* const* d_in, const int* in_sizes, int n_in,
                              void* d_out, int out_size)
{
    const float* x    = (const float*)d_in[0];
    const int*   mask = (const int*)  d_in[1];
    const float* wq   = (const float*)d_in[2];
    const float* wk   = (const float*)d_in[3];
    const float* wv   = (const float*)d_in[4];
    const float* wo   = (const float*)d_in[5];
    const float* ff1w = (const float*)d_in[6];
    const float* ff1b = (const float*)d_in[7];
    const float* ff2w = (const float*)d_in[8];
    const float* ff2b = (const float*)d_in[9];
    const float* ln1a = (const float*)d_in[10];
    const float* ln1b = (const float*)d_in[11];
    const float* ln2a = (const float*)d_in[12];
    const float* ln2b = (const float*)d_in[13];
    float* out = (float*)d_out;

    __nv_bfloat16 *a3a, *a3b, *a3c, *w3;
    float *qkv, *h;
    cudaGetSymbolAddress((void**)&a3a, g_a3a);
    cudaGetSymbolAddress((void**)&a3b, g_a3b);
    cudaGetSymbolAddress((void**)&a3c, g_a3c);
    cudaGetSymbolAddress((void**)&w3,  g_w3);
    cudaGetSymbolAddress((void**)&qkv, g_qkv);
    cudaGetSymbolAddress((void**)&h,   g_h);

    const int attn_smem = 4 * 64 * LDW * sizeof(float);
    cudaFuncSetAttribute(attn_kernel, cudaFuncAttributeMaxDynamicSharedMemorySize, attn_smem);
    cudaFuncSetAttribute(gemm_mma<0>, cudaFuncAttributeMaxDynamicSharedMemorySize, GSM_TOTAL);
    cudaFuncSetAttribute(gemm_mma<1>, cudaFuncAttributeMaxDynamicSharedMemorySize, GSM_TOTAL);

    dim3 tb(32, 8);
    dim3 gQKV(QKVW / 128, MROWS / 128);  // (24, 32)
    dim3 gE(EMB / 128, MROWS / 128);     // (8, 32)
    dim3 gH(HID / 128, MROWS / 128);     // (32, 32)

    // 1) ln1(x) -> a3a (split)
    ln_split_kernel<<<MROWS, 256>>>(x, a3a, ln1a, ln1b);
    // 2) pack split+transposed wq|wk|wv into w3
    wt_split_kernel<<<dim3(EMB/32, EMB/32), tb>>>(wq, w3, EMB, EMB);
    wt_split_kernel<<<dim3(EMB/32, EMB/32), tb>>>(wk, w3 + (size_t)EMB * K3E, EMB, EMB);
    wt_split_kernel<<<dim3(EMB/32, EMB/32), tb>>>(wv, w3 + (size_t)(2 * EMB) * K3E, EMB, EMB);
    // 3) fused QKV projection
    gemm_mma<0><<<gQKV, 256, GSM_TOTAL>>>(a3a, w3, qkv, nullptr, nullptr, nullptr, MROWS, QKVW, K3E);
    // 4) attention -> a3b (split)
    attn_kernel<<<dim3(SEQ / 64, BATCH * NH), 256, attn_smem>>>(qkv, mask, a3b);
    // 5) h = x + ao @ wo
    wt_split_kernel<<<dim3(EMB/32, EMB/32), tb>>>(wo, w3, EMB, EMB);
    gemm_mma<0><<<gE, 256, GSM_TOTAL>>>(a3b, w3, h, nullptr, nullptr, x, MROWS, EMB, K3E);
    // 6) ln2(h) -> a3a (split)
    ln_split_kernel<<<MROWS, 256>>>(h, a3a, ln2a, ln2b);
    // 7) a3c = split(relu(ln2 @ ff1_w + ff1_b))
    wt_split_kernel<<<dim3(HID/32, EMB/32), tb>>>(ff1w, w3, EMB, HID);
    gemm_mma<1><<<gH, 256, GSM_TOTAL>>>(a3a, w3, nullptr, a3c, ff1b, nullptr, MROWS, HID, K3E);
    // 8) out = h + ffa @ ff2_w + ff2_b
    wt_split_kernel<<<dim3(EMB/32, HID/32), tb>>>(ff2w, w3, HID, EMB);
    gemm_mma<0><<<gE, 256, GSM_TOTAL>>>(a3c, w3, out, nullptr, ff2b, h, MROWS, EMB, K3H);
}

// round 5
// speedup vs baseline: 2.5457x; 1.8257x over previous
#include <cuda_runtime.h>
#include <cuda_bf16.h>
#include <math.h>
#include <stdint.h>

#define EMB 1024
#define HID 4096
#define NH 16
#define DKH 64
#define BATCH 2
#define SEQ 2048
#define MROWS (BATCH * SEQ)     // 4096
#define K3E (3 * EMB)           // 3072
#define K3H (3 * HID)           // 12288
#define QKVW (3 * EMB)

// ---------------- scratch (__device__ globals, allocation-free) ---------------
__device__ __nv_bfloat16 g_a3a[MROWS * K3E];
__device__ __nv_bfloat16 g_a3b[MROWS * K3E];
__device__ __nv_bfloat16 g_a3c[(size_t)MROWS * K3H];
__device__ __nv_bfloat16 g_w3 [(size_t)HID * K3E];
__device__ __nv_bfloat16 g_qkvh[(size_t)MROWS * QKVW];   // packed q|k|v bf16
__device__ float g_h[MROWS * EMB];

// ---------------- PTX helpers (base ISA only) ----------------------------------
__device__ __forceinline__ uint32_t smem_u32(const void* p) {
    return (uint32_t)__cvta_generic_to_shared(p);
}
__device__ __forceinline__ void cp16(uint32_t dst, const void* src) {
    asm volatile("cp.async.cg.shared.global [%0], [%1], 16;" :: "r"(dst), "l"(src));
}
__device__ __forceinline__ void cp_commit() {
    asm volatile("cp.async.commit_group;");
}
template<int N> __device__ __forceinline__ void cp_wait() {
    asm volatile("cp.async.wait_group %0;" :: "n"(N));
}
__device__ __forceinline__ void ldsm_x4(uint32_t* r, uint32_t addr) {
    asm volatile("ldmatrix.sync.aligned.m8n8.x4.shared.b16 {%0,%1,%2,%3}, [%4];"
                 : "=r"(r[0]), "=r"(r[1]), "=r"(r[2]), "=r"(r[3]) : "r"(addr));
}
__device__ __forceinline__ void ldsm_x4t(uint32_t* r, uint32_t addr) {
    asm volatile("ldmatrix.sync.aligned.m8n8.x4.trans.shared.b16 {%0,%1,%2,%3}, [%4];"
                 : "=r"(r[0]), "=r"(r[1]), "=r"(r[2]), "=r"(r[3]) : "r"(addr));
}
__device__ __forceinline__ void mma16816(float* d, const uint32_t* a, const uint32_t* b) {
    asm volatile(
        "mma.sync.aligned.m16n8k16.row.col.f32.bf16.bf16.f32 "
        "{%0,%1,%2,%3}, {%4,%5,%6,%7}, {%8,%9}, {%0,%1,%2,%3};"
        : "+f"(d[0]), "+f"(d[1]), "+f"(d[2]), "+f"(d[3])
        : "r"(a[0]), "r"(a[1]), "r"(a[2]), "r"(a[3]), "r"(b[0]), "r"(b[1]));
}
__device__ __forceinline__ uint32_t packbf(float a, float b) {
    __nv_bfloat162 h = __floats2bfloat162_rn(a, b);
    return *(uint32_t*)&h;
}

// ---------------- LayerNorm -> split-bf16 [hi | lo | hi] ----------------------
__global__ void ln_split_kernel(const float* __restrict__ x, __nv_bfloat16* __restrict__ y3,
                                const float* __restrict__ al, const float* __restrict__ be)
{
    int row = blockIdx.x;
    const float4* xr = (const float4*)(x + (size_t)row * EMB);
    float4 v = xr[threadIdx.x];
    float s  = v.x + v.y + v.z + v.w;
    float ss = v.x*v.x + v.y*v.y + v.z*v.z + v.w*v.w;
    #pragma unroll
    for (int off = 16; off; off >>= 1) {
        s  += __shfl_xor_sync(0xffffffffu, s,  off);
        ss += __shfl_xor_sync(0xffffffffu, ss, off);
    }
    __shared__ float rs[8], rss[8];
    int warp = threadIdx.x >> 5, lane = threadIdx.x & 31;
    if (lane == 0) { rs[warp] = s; rss[warp] = ss; }
    __syncthreads();
    if (warp == 0) {
        s  = (lane < 8) ? rs[lane]  : 0.f;
        ss = (lane < 8) ? rss[lane] : 0.f;
        #pragma unroll
        for (int off = 16; off; off >>= 1) {
            s  += __shfl_xor_sync(0xffffffffu, s,  off);
            ss += __shfl_xor_sync(0xffffffffu, ss, off);
        }
        if (lane == 0) { rs[0] = s; rss[0] = ss; }
    }
    __syncthreads();
    s = rs[0]; ss = rss[0];
    float mean = s * (1.0f / EMB);
    float var  = fmaxf(ss - (float)EMB * mean * mean, 0.f) * (1.0f / (EMB - 1));
    float inv  = al[0] / (sqrtf(var) + 1e-6f);
    float bb   = be[0];
    float o[4] = { (v.x - mean) * inv + bb, (v.y - mean) * inv + bb,
                   (v.z - mean) * inv + bb, (v.w - mean) * inv + bb };
    int col = threadIdx.x * 4;
    __nv_bfloat16* rowp = y3 + (size_t)row * K3E;
    #pragma unroll
    for (int p = 0; p < 2; p++) {
        __nv_bfloat162 hh, ll;
        float a0 = o[p*2], a1 = o[p*2+1];
        __nv_bfloat16 h0 = __float2bfloat16_rn(a0);
        __nv_bfloat16 h1 = __float2bfloat16_rn(a1);
        hh.x = h0; hh.y = h1;
        ll.x = __float2bfloat16_rn(a0 - __bfloat162float(h0));
        ll.y = __float2bfloat16_rn(a1 - __bfloat162float(h1));
        *(__nv_bfloat162*)(rowp + col + p*2)         = hh;
        *(__nv_bfloat162*)(rowp + EMB + col + p*2)   = ll;
        *(__nv_bfloat162*)(rowp + 2*EMB + col + p*2) = hh;
    }
}

// ---------------- weight transpose + split: W[K,N] -> WT3[N, 3K] --------------
__global__ void wt_split_kernel(const float* __restrict__ W, __nv_bfloat16* __restrict__ WT3,
                                int K, int N)
{
    __shared__ float t[32][33];
    int n0 = blockIdx.x * 32, k0 = blockIdx.y * 32;
    #pragma unroll
    for (int i = 0; i < 4; i++)
        t[threadIdx.y + 8*i][threadIdx.x] = W[(size_t)(k0 + threadIdx.y + 8*i) * N + n0 + threadIdx.x];
    __syncthreads();
    #pragma unroll
    for (int i = 0; i < 4; i++) {
        int n = n0 + threadIdx.y + 8*i;
        int k = k0 + threadIdx.x;
        float v = t[threadIdx.x][threadIdx.y + 8*i];
        __nv_bfloat16 hi = __float2bfloat16_rn(v);
        __nv_bfloat16 lo = __float2bfloat16_rn(v - __bfloat162float(hi));
        size_t rb = (size_t)n * (3 * (size_t)K);
        WT3[rb + k]       = hi;
        WT3[rb + K + k]   = hi;
        WT3[rb + 2*K + k] = lo;
    }
}

// ---------------- bf16 mma.sync GEMM ------------------------------------------
// MODE 0: fp32 out (+bias/res). MODE 1: split-bf16 relu(x+bias). MODE 2: plain bf16.
#define ASTR 80
#define STAGE_BYTES (2 * 128 * ASTR)
#define GSM_TOTAL (3 * STAGE_BYTES)

template<int MODE>
__global__ void __launch_bounds__(256, 1)
gemm_mma(const __nv_bfloat16* __restrict__ A3, const __nv_bfloat16* __restrict__ BT3,
         float* __restrict__ C, __nv_bfloat16* __restrict__ Cs,
         const float* __restrict__ bias, const float* __restrict__ res,
         int M, int N, int K3)
{
    extern __shared__ char smem[];
    uint32_t sb = smem_u32(smem);
    int tid = threadIdx.x, wid = tid >> 5, lane = tid & 31;
    int bm = blockIdx.y, bn = blockIdx.x;
    int warp_m = wid >> 2, warp_n = wid & 3;

    const int nk = K3 / 32;

    auto load_stage = [&](int k0, int st) {
        uint32_t base = sb + st * STAGE_BYTES;
        #pragma unroll
        for (int hh = 0; hh < 2; hh++) {
            int c = tid + hh * 256;
            int row = c >> 2, kc = c & 3;
            cp16(base + row * ASTR + kc * 16,
                 A3 + (size_t)(bm * 128 + row) * K3 + k0 + kc * 8);
            cp16(base + 128 * ASTR + row * ASTR + kc * 16,
                 BT3 + (size_t)(bn * 128 + row) * K3 + k0 + kc * 8);
        }
        cp_commit();
    };

    load_stage(0, 0);
    load_stage(32, 1);

    float acc[4][4][4];
    #pragma unroll
    for (int i = 0; i < 4; i++)
        #pragma unroll
        for (int j = 0; j < 4; j++)
            #pragma unroll
            for (int r = 0; r < 4; r++) acc[i][j][r] = 0.f;

    uint32_t aBase = (uint32_t)((warp_m * 64 + (lane & 15)) * ASTR + (lane >> 4) * 16);
    uint32_t bBase = (uint32_t)(128 * ASTR +
                     (warp_n * 32 + ((lane >> 4) << 3) + (lane & 7)) * ASTR +
                     ((lane >> 3) & 1) * 16);

    for (int kt = 0; kt < nk; kt++) {
        cp_wait<1>();
        __syncthreads();
        int nxt = kt + 2;
        if (nxt < nk) load_stage(nxt * 32, nxt % 3);

        uint32_t stb = sb + (kt % 3) * STAGE_BYTES;
        #pragma unroll
        for (int s = 0; s < 2; s++) {
            uint32_t afr[4][4], bfr[2][4];
            #pragma unroll
            for (int i = 0; i < 4; i++)
                ldsm_x4(afr[i], stb + aBase + i * 16 * ASTR + s * 32);
            #pragma unroll
            for (int jj = 0; jj < 2; jj++)
                ldsm_x4(bfr[jj], stb + bBase + jj * 16 * ASTR + s * 32);
            #pragma unroll
            for (int i = 0; i < 4; i++) {
                #pragma unroll
                for (int j = 0; j < 4; j++)
                    mma16816(acc[i][j], afr[i], &bfr[j >> 1][(j & 1) * 2]);
            }
        }
        __syncthreads();
    }

    int g = lane >> 2, tig = lane & 3;
    #pragma unroll
    for (int i = 0; i < 4; i++) {
        #pragma unroll
        for (int half = 0; half < 2; half++) {
            int row = bm * 128 + warp_m * 64 + i * 16 + g + half * 8;
            #pragma unroll
            for (int j = 0; j < 4; j++) {
                int col = bn * 128 + warp_n * 32 + j * 8 + tig * 2;
                float v0 = acc[i][j][half * 2];
                float v1 = acc[i][j][half * 2 + 1];
                if (MODE == 1) {
                    v0 = fmaxf(v0 + bias[col], 0.f);
                    v1 = fmaxf(v1 + bias[col + 1], 0.f);
                    __nv_bfloat16 h0 = __float2bfloat16_rn(v0);
                    __nv_bfloat16 h1 = __float2bfloat16_rn(v1);
                    __nv_bfloat162 hh; hh.x = h0; hh.y = h1;
                    __nv_bfloat162 ll;
                    ll.x = __float2bfloat16_rn(v0 - __bfloat162float(h0));
                    ll.y = __float2bfloat16_rn(v1 - __bfloat162float(h1));
                    size_t rb = (size_t)row * (3 * (size_t)N);
                    *(__nv_bfloat162*)(Cs + rb + col)                 = hh;
                    *(__nv_bfloat162*)(Cs + rb + N + col)             = ll;
                    *(__nv_bfloat162*)(Cs + rb + 2 * (size_t)N + col) = hh;
                } else if (MODE == 2) {
                    __nv_bfloat162 hh;
                    hh.x = __float2bfloat16_rn(v0);
                    hh.y = __float2bfloat16_rn(v1);
                    *(__nv_bfloat162*)(Cs + (size_t)row * N + col) = hh;
                } else {
                    if (bias) { v0 += bias[col]; v1 += bias[col + 1]; }
                    size_t rb = (size_t)row * N;
                    if (res) {
                        float2 rr = *(const float2*)(res + rb + col);
                        v0 += rr.x; v1 += rr.y;
                    }
                    float2 o; o.x = v0; o.y = v1;
                    *(float2*)(C + rb + col) = o;
                }
            }
        }
    }
}

// ---------------- Tensor-core flash attention (bf16, fp32 softmax) ------------
// grid (SEQ/128, BATCH*NH), 256 threads (8 warps x m16). 64-key tiles.
#define TSTR 144                       // smem row stride bytes (64 bf16 + pad)
#define AQOFF 0                        // Q: 128 rows  -> 18432 B
#define AKOFF 18432                    // K: 2 x 64 rows -> 18432 B
#define AVOFF 36864                    // V: 2 x 64 rows -> 18432 B
#define AMOFF 55296                    // mask: 2048 ints -> 8192 B
#define ATT_SMEM 63488

__global__ void __launch_bounds__(256, 1)
attn_tc(const __nv_bfloat16* __restrict__ qkv, const int* __restrict__ mask,
        __nv_bfloat16* __restrict__ o3)
{
    extern __shared__ char smem[];
    uint32_t sb = smem_u32(smem);
    int tid = threadIdx.x, wid = tid >> 5, lane = tid & 31;
    int g = lane >> 2, tig = lane & 3;
    int bh = blockIdx.y;
    int b = bh >> 4, hd = bh & 15;
    int q0 = blockIdx.x * 128;

    const __nv_bfloat16* qg = qkv + (size_t)(b * SEQ) * QKVW + hd * DKH;

    // prologue: Q tile + mask + KV tile 0 (one commit group)
    #pragma unroll
    for (int i = 0; i < 4; i++) {
        int c = tid + i * 256;            // 1024 chunks
        int row = c >> 3, kc = c & 7;
        cp16(sb + AQOFF + row * TSTR + kc * 16,
             qg + (size_t)(q0 + row) * QKVW + kc * 8);
    }
    #pragma unroll
    for (int i = 0; i < 2; i++) {
        int c = tid + i * 256;            // 512 chunks of 4 ints
        cp16(sb + AMOFF + c * 16, mask + (size_t)b * SEQ + c * 4);
    }
    auto load_kv = [&](int jt, int buf) {
        #pragma unroll
        for (int i = 0; i < 2; i++) {
            int c = tid + i * 256;        // 512 chunks
            int row = c >> 3, kc = c & 7;
            cp16(sb + AKOFF + buf * 9216 + row * TSTR + kc * 16,
                 qg + (size_t)(jt * 64 + row) * QKVW + EMB + kc * 8);
            cp16(sb + AVOFF + buf * 9216 + row * TSTR + kc * 16,
                 qg + (size_t)(jt * 64 + row) * QKVW + 2 * EMB + kc * 8);
        }
    };
    load_kv(0, 0);
    cp_commit();

    uint32_t qfr[4][4];
    float ofr[8][4];
    #pragma unroll
    for (int j = 0; j < 8; j++)
        #pragma unroll
        for (int r = 0; r < 4; r++) ofr[j][r] = 0.f;
    float m0 = -3.0e38f, m1 = -3.0e38f, l0 = 0.f, l1 = 0.f;

    uint32_t aQ = (uint32_t)(AQOFF + (wid * 16 + (lane & 15)) * TSTR + (lane >> 4) * 16);
    uint32_t bK = (uint32_t)((((lane >> 4) << 3) + (lane & 7)) * TSTR + ((lane >> 3) & 1) * 16);
    uint32_t bV = (uint32_t)((((lane >> 3) & 1) * 8 + (lane & 7)) * TSTR + (lane >> 4) * 16);

    const int NJT = SEQ / 64;
    for (int jt = 0; jt < NJT; jt++) {
        cp_wait<0>();
        __syncthreads();
        if (jt == 0) {
            #pragma unroll
            for (int ks = 0; ks < 4; ks++) ldsm_x4(qfr[ks], sb + aQ + ks * 32);
        }
        if (jt + 1 < NJT) { load_kv(jt + 1, (jt + 1) & 1); cp_commit(); }

        uint32_t kb = sb + AKOFF + (jt & 1) * 9216;
        uint32_t vb = sb + AVOFF + (jt & 1) * 9216;

        // S = Q @ K^T   (m16 x n64, fp32 accum)
        float sfr[8][4];
        #pragma unroll
        for (int j = 0; j < 8; j++)
            #pragma unroll
            for (int r = 0; r < 4; r++) sfr[j][r] = 0.f;
        #pragma unroll
        for (int ks = 0; ks < 4; ks++) {
            uint32_t bfr[4][4];
            #pragma unroll
            for (int ng = 0; ng < 4; ng++)
                ldsm_x4(bfr[ng], kb + bK + ng * 16 * TSTR + ks * 32);
            #pragma unroll
            for (int j = 0; j < 8; j++)
                mma16816(sfr[j], qfr[ks], &bfr[j >> 1][(j & 1) * 2]);
        }

        // scale + mask
        #pragma unroll
        for (int j = 0; j < 8; j++) {
            int2 mv = *(const int2*)(smem + AMOFF + (jt * 64 + j * 8 + tig * 2) * 4);
            sfr[j][0] = (mv.x == 0) ? -1e30f : sfr[j][0] * 0.125f;
            sfr[j][1] = (mv.y == 0) ? -1e30f : sfr[j][1] * 0.125f;
            sfr[j][2] = (mv.x == 0) ? -1e30f : sfr[j][2] * 0.125f;
            sfr[j][3] = (mv.y == 0) ? -1e30f : sfr[j][3] * 0.125f;
        }

        // online softmax (rows g and g+8; stats across tig lanes)
        float mx0 = -3.0e38f, mx1 = -3.0e38f;
        #pragma unroll
        for (int j = 0; j < 8; j++) {
            mx0 = fmaxf(mx0, fmaxf(sfr[j][0], sfr[j][1]));
            mx1 = fmaxf(mx1, fmaxf(sfr[j][2], sfr[j][3]));
        }
        #pragma unroll
        for (int off = 1; off < 4; off <<= 1) {
            mx0 = fmaxf(mx0, __shfl_xor_sync(0xffffffffu, mx0, off));
            mx1 = fmaxf(mx1, __shfl_xor_sync(0xffffffffu, mx1, off));
        }
        float mn0 = fmaxf(m0, mx0), mn1 = fmaxf(m1, mx1);
        float al0 = __expf(m0 - mn0), al1 = __expf(m1 - mn1);
        float ls0 = 0.f, ls1 = 0.f;
        #pragma unroll
        for (int j = 0; j < 8; j++) {
            sfr[j][0] = __expf(sfr[j][0] - mn0);
            sfr[j][1] = __expf(sfr[j][1] - mn0);
            sfr[j][2] = __expf(sfr[j][2] - mn1);
            sfr[j][3] = __expf(sfr[j][3] - mn1);
            ls0 += sfr[j][0] + sfr[j][1];
            ls1 += sfr[j][2] + sfr[j][3];
        }
        #pragma unroll
        for (int off = 1; off < 4; off <<= 1) {
            ls0 += __shfl_xor_sync(0xffffffffu, ls0, off);
            ls1 += __shfl_xor_sync(0xffffffffu, ls1, off);
        }
        l0 = l0 * al0 + ls0; l1 = l1 * al1 + ls1;
        m0 = mn0; m1 = mn1;
        #pragma unroll
        for (int j = 0; j < 8; j++) {
            ofr[j][0] *= al0; ofr[j][1] *= al0;
            ofr[j][2] *= al1; ofr[j][3] *= al1;
        }

        // O += P @ V  (P frags from S regs; V via trans ldmatrix)
        #pragma unroll
        for (int ks = 0; ks < 4; ks++) {
            uint32_t pa[4];
            pa[0] = packbf(sfr[2*ks][0],   sfr[2*ks][1]);
            pa[1] = packbf(sfr[2*ks][2],   sfr[2*ks][3]);
            pa[2] = packbf(sfr[2*ks+1][0], sfr[2*ks+1][1]);
            pa[3] = packbf(sfr[2*ks+1][2], sfr[2*ks+1][3]);
            #pragma unroll
            for (int jp = 0; jp < 4; jp++) {
                uint32_t vfr[4];
                ldsm_x4t(vfr, vb + bV + ks * 16 * TSTR + jp * 32);
                mma16816(ofr[2*jp],     pa, &vfr[0]);
                mma16816(ofr[2*jp + 1], pa, &vfr[2]);
            }
        }
        __syncthreads();
    }

    // epilogue: normalize, write split-bf16 [hi | lo | hi] to o3
    float inv0 = 1.f / l0, inv1 = 1.f / l1;
    int r0 = b * SEQ + q0 + wid * 16 + g;
    #pragma unroll
    for (int half = 0; half < 2; half++) {
        int grow = r0 + half * 8;
        float inv = half ? inv1 : inv0;
        __nv_bfloat16* base = o3 + (size_t)grow * K3E + hd * DKH;
        #pragma unroll
        for (int j = 0; j < 8; j++) {
            int col = j * 8 + tig * 2;
            float v0 = ofr[j][half * 2]     * inv;
            float v1 = ofr[j][half * 2 + 1] * inv;
            __nv_bfloat16 h0 = __float2bfloat16_rn(v0);
            __nv_bfloat16 h1 = __float2bfloat16_rn(v1);
            __nv_bfloat162 hh; hh.x = h0; hh.y = h1;
            __nv_bfloat162 ll;
            ll.x = __float2bfloat16_rn(v0 - __bfloat162float(h0));
            ll.y = __float2bfloat16_rn(v1 - __bfloat162float(h1));
            *(__nv_bfloat162*)(base + col)           = hh;
            *(__nv_bfloat162*)(base + EMB + col)     = ll;
            *(__nv_bfloat162*)(base + 2*EMB + col)   = hh;
        }
    }
}

// ---------------- launch ------------------------------------------------------
extern "C" void kernel_launch(void* const* d_in, const int* in_sizes, int n_in,
                              void* d_out, int out_size)
{
    const float* x    = (const float*)d_in[0];
    const int*   mask = (const int*)  d_in[1];
    const float* wq   = (const float*)d_in[2];
    const float* wk   = (const float*)d_in[3];
    const float* wv   = (const float*)d_in[4];
    const float* wo   = (const float*)d_in[5];
    const float* ff1w = (const float*)d_in[6];
    const float* ff1b = (const float*)d_in[7];
    const float* ff2w = (const float*)d_in[8];
    const float* ff2b = (const float*)d_in[9];
    const float* ln1a = (const float*)d_in[10];
    const float* ln1b = (const float*)d_in[11];
    const float* ln2a = (const float*)d_in[12];
    const float* ln2b = (const float*)d_in[13];
    float* out = (float*)d_out;

    __nv_bfloat16 *a3a, *a3b, *a3c, *w3, *qkvh;
    float *h;
    cudaGetSymbolAddress((void**)&a3a,  g_a3a);
    cudaGetSymbolAddress((void**)&a3b,  g_a3b);
    cudaGetSymbolAddress((void**)&a3c,  g_a3c);
    cudaGetSymbolAddress((void**)&w3,   g_w3);
    cudaGetSymbolAddress((void**)&qkvh, g_qkvh);
    cudaGetSymbolAddress((void**)&h,    g_h);

    cudaFuncSetAttribute(attn_tc, cudaFuncAttributeMaxDynamicSharedMemorySize, ATT_SMEM);
    cudaFuncSetAttribute(gemm_mma<0>, cudaFuncAttributeMaxDynamicSharedMemorySize, GSM_TOTAL);
    cudaFuncSetAttribute(gemm_mma<1>, cudaFuncAttributeMaxDynamicSharedMemorySize, GSM_TOTAL);
    cudaFuncSetAttribute(gemm_mma<2>, cudaFuncAttributeMaxDynamicSharedMemorySize, GSM_TOTAL);

    dim3 tb(32, 8);
    dim3 gQKV(QKVW / 128, MROWS / 128);  // (24, 32)
    dim3 gE(EMB / 128, MROWS / 128);     // (8, 32)
    dim3 gH(HID / 128, MROWS / 128);     // (32, 32)

    // 1) ln1(x) -> a3a (split)
    ln_split_kernel<<<MROWS, 256>>>(x, a3a, ln1a, ln1b);
    // 2) pack split+transposed wq|wk|wv into w3
    wt_split_kernel<<<dim3(EMB/32, EMB/32), tb>>>(wq, w3, EMB, EMB);
    wt_split_kernel<<<dim3(EMB/32, EMB/32), tb>>>(wk, w3 + (size_t)EMB * K3E, EMB, EMB);
    wt_split_kernel<<<dim3(EMB/32, EMB/32), tb>>>(wv, w3 + (size_t)(2 * EMB) * K3E, EMB, EMB);
    // 3) fused QKV projection -> bf16 packed qkv
    gemm_mma<2><<<gQKV, 256, GSM_TOTAL>>>(a3a, w3, nullptr, qkvh, nullptr, nullptr, MROWS, QKVW, K3E);
    // 4) tensor-core attention -> a3b (split)
    attn_tc<<<dim3(SEQ / 128, BATCH * NH), 256, ATT_SMEM>>>(qkvh, mask, a3b);
    // 5) h = x + ao @ wo
    wt_split_kernel<<<dim3(EMB/32, EMB/32), tb>>>(wo, w3, EMB, EMB);
    gemm_mma<0><<<gE, 256, GSM_TOTAL>>>(a3b, w3, h, nullptr, nullptr, x, MROWS, EMB, K3E);
    // 6) ln2(h) -> a3a (split)
    ln_split_kernel<<<MROWS, 256>>>(h, a3a, ln2a, ln2b);
    // 7) a3c = split(relu(ln2 @ ff1_w + ff1_b))
    wt_split_kernel<<<dim3(HID/32, EMB/32), tb>>>(ff1w, w3, EMB, HID);
    gemm_mma<1><<<gH, 256, GSM_TOTAL>>>(a3a, w3, nullptr, a3c, ff1b, nullptr, MROWS, HID, K3E);
    // 8) out = h + ffa @ ff2_w + ff2_b
    wt_split_kernel<<<dim3(EMB/32, HID/32), tb>>>(ff2w, w3, HID, EMB);
    gemm_mma<0><<<gE, 256, GSM_TOTAL>>>(a3c, w3, out, nullptr, ff2b, h, MROWS, EMB, K3H);
}

// round 6
// speedup vs baseline: 3.1792x; 1.2489x over previous
#include <cuda_runtime.h>
#include <cuda_bf16.h>
#include <math.h>
#include <stdint.h>

#define EMB 1024
#define HID 4096
#define NH 16
#define DKH 64
#define BATCH 2
#define SEQ 2048
#define MROWS (BATCH * SEQ)     // 4096
#define K3E (3 * EMB)           // 3072
#define K3H (3 * HID)           // 12288
#define QKVW (3 * EMB)

// ---------------- scratch (__device__ globals, allocation-free) ---------------
__device__ __nv_bfloat16 g_ab  [MROWS * EMB];          // ln1 out, later attention out
__device__ __nv_bfloat16 g_a3a [MROWS * K3E];          // ln2 out (split)
__device__ __nv_bfloat16 g_a3c [(size_t)MROWS * K3H];  // relu(ff1) (split)
__device__ __nv_bfloat16 g_w3  [(size_t)HID * K3E];    // split weights (ff1/ff2)
__device__ __nv_bfloat16 g_wp  [(size_t)QKVW * EMB];   // plain transposed weights (qkv/wo)
__device__ __nv_bfloat16 g_qkvh[(size_t)MROWS * QKVW]; // packed q|k|v bf16
__device__ float g_h[MROWS * EMB];

// ---------------- PTX helpers (base ISA only) ----------------------------------
__device__ __forceinline__ uint32_t smem_u32(const void* p) {
    return (uint32_t)__cvta_generic_to_shared(p);
}
__device__ __forceinline__ void cp16(uint32_t dst, const void* src) {
    asm volatile("cp.async.cg.shared.global [%0], [%1], 16;" :: "r"(dst), "l"(src));
}
__device__ __forceinline__ void cp_commit() {
    asm volatile("cp.async.commit_group;");
}
template<int N> __device__ __forceinline__ void cp_wait() {
    asm volatile("cp.async.wait_group %0;" :: "n"(N));
}
__device__ __forceinline__ void ldsm_x4(uint32_t* r, uint32_t addr) {
    asm volatile("ldmatrix.sync.aligned.m8n8.x4.shared.b16 {%0,%1,%2,%3}, [%4];"
                 : "=r"(r[0]), "=r"(r[1]), "=r"(r[2]), "=r"(r[3]) : "r"(addr));
}
__device__ __forceinline__ void ldsm_x4t(uint32_t* r, uint32_t addr) {
    asm volatile("ldmatrix.sync.aligned.m8n8.x4.trans.shared.b16 {%0,%1,%2,%3}, [%4];"
                 : "=r"(r[0]), "=r"(r[1]), "=r"(r[2]), "=r"(r[3]) : "r"(addr));
}
__device__ __forceinline__ void mma16816(float* d, const uint32_t* a, const uint32_t* b) {
    asm volatile(
        "mma.sync.aligned.m16n8k16.row.col.f32.bf16.bf16.f32 "
        "{%0,%1,%2,%3}, {%4,%5,%6,%7}, {%8,%9}, {%0,%1,%2,%3};"
        : "+f"(d[0]), "+f"(d[1]), "+f"(d[2]), "+f"(d[3])
        : "r"(a[0]), "r"(a[1]), "r"(a[2]), "r"(a[3]), "r"(b[0]), "r"(b[1]));
}
__device__ __forceinline__ uint32_t packbf(float a, float b) {
    __nv_bfloat162 h = __floats2bfloat162_rn(a, b);
    return *(uint32_t*)&h;
}

// ---------------- LayerNorm helpers -------------------------------------------
__device__ __forceinline__ void ln_stats(float4 v, float& mean, float& inv,
                                         const float* al) {
    float s  = v.x + v.y + v.z + v.w;
    float ss = v.x*v.x + v.y*v.y + v.z*v.z + v.w*v.w;
    #pragma unroll
    for (int off = 16; off; off >>= 1) {
        s  += __shfl_xor_sync(0xffffffffu, s,  off);
        ss += __shfl_xor_sync(0xffffffffu, ss, off);
    }
    __shared__ float rs[8], rss[8];
    int warp = threadIdx.x >> 5, lane = threadIdx.x & 31;
    if (lane == 0) { rs[warp] = s; rss[warp] = ss; }
    __syncthreads();
    if (warp == 0) {
        s  = (lane < 8) ? rs[lane]  : 0.f;
        ss = (lane < 8) ? rss[lane] : 0.f;
        #pragma unroll
        for (int off = 16; off; off >>= 1) {
            s  += __shfl_xor_sync(0xffffffffu, s,  off);
            ss += __shfl_xor_sync(0xffffffffu, ss, off);
        }
        if (lane == 0) { rs[0] = s; rss[0] = ss; }
    }
    __syncthreads();
    s = rs[0]; ss = rss[0];
    mean = s * (1.0f / EMB);
    float var = fmaxf(ss - (float)EMB * mean * mean, 0.f) * (1.0f / (EMB - 1));
    inv = al[0] / (sqrtf(var) + 1e-6f);
}

// ln1: fp32 -> plain bf16 [EMB]
__global__ void ln_plain_kernel(const float* __restrict__ x, __nv_bfloat16* __restrict__ y,
                                const float* __restrict__ al, const float* __restrict__ be)
{
    int row = blockIdx.x;
    float4 v = ((const float4*)(x + (size_t)row * EMB))[threadIdx.x];
    float mean, inv;
    ln_stats(v, mean, inv, al);
    float bb = be[0];
    int col = threadIdx.x * 4;
    __nv_bfloat16* rowp = y + (size_t)row * EMB;
    __nv_bfloat162 h0 = __floats2bfloat162_rn((v.x - mean) * inv + bb, (v.y - mean) * inv + bb);
    __nv_bfloat162 h1 = __floats2bfloat162_rn((v.z - mean) * inv + bb, (v.w - mean) * inv + bb);
    *(__nv_bfloat162*)(rowp + col)     = h0;
    *(__nv_bfloat162*)(rowp + col + 2) = h1;
}

// ln2: fp32 -> split bf16 [hi | lo | hi] (3*EMB)
__global__ void ln_split_kernel(const float* __restrict__ x, __nv_bfloat16* __restrict__ y3,
                                const float* __restrict__ al, const float* __restrict__ be)
{
    int row = blockIdx.x;
    float4 v = ((const float4*)(x + (size_t)row * EMB))[threadIdx.x];
    float mean, inv;
    ln_stats(v, mean, inv, al);
    float bb = be[0];
    float o[4] = { (v.x - mean) * inv + bb, (v.y - mean) * inv + bb,
                   (v.z - mean) * inv + bb, (v.w - mean) * inv + bb };
    int col = threadIdx.x * 4;
    __nv_bfloat16* rowp = y3 + (size_t)row * K3E;
    #pragma unroll
    for (int p = 0; p < 2; p++) {
        float a0 = o[p*2], a1 = o[p*2+1];
        __nv_bfloat16 h0 = __float2bfloat16_rn(a0);
        __nv_bfloat16 h1 = __float2bfloat16_rn(a1);
        __nv_bfloat162 hh; hh.x = h0; hh.y = h1;
        __nv_bfloat162 ll;
        ll.x = __float2bfloat16_rn(a0 - __bfloat162float(h0));
        ll.y = __float2bfloat16_rn(a1 - __bfloat162float(h1));
        *(__nv_bfloat162*)(rowp + col + p*2)         = hh;
        *(__nv_bfloat162*)(rowp + EMB + col + p*2)   = ll;
        *(__nv_bfloat162*)(rowp + 2*EMB + col + p*2) = hh;
    }
}

// ---------------- weight transposes -------------------------------------------
// plain: W[K,N] -> WT[N,K] bf16
__global__ void wt_plain_kernel(const float* __restrict__ W, __nv_bfloat16* __restrict__ WT,
                                int K, int N)
{
    __shared__ float t[32][33];
    int n0 = blockIdx.x * 32, k0 = blockIdx.y * 32;
    #pragma unroll
    for (int i = 0; i < 4; i++)
        t[threadIdx.y + 8*i][threadIdx.x] = W[(size_t)(k0 + threadIdx.y + 8*i) * N + n0 + threadIdx.x];
    __syncthreads();
    #pragma unroll
    for (int i = 0; i < 4; i++) {
        int n = n0 + threadIdx.y + 8*i;
        int k = k0 + threadIdx.x;
        WT[(size_t)n * K + k] = __float2bfloat16_rn(t[threadIdx.x][threadIdx.y + 8*i]);
    }
}

// split: W[K,N] -> WT3[N, 3K] = [hi | hi | lo]
__global__ void wt_split_kernel(const float* __restrict__ W, __nv_bfloat16* __restrict__ WT3,
                                int K, int N)
{
    __shared__ float t[32][33];
    int n0 = blockIdx.x * 32, k0 = blockIdx.y * 32;
    #pragma unroll
    for (int i = 0; i < 4; i++)
        t[threadIdx.y + 8*i][threadIdx.x] = W[(size_t)(k0 + threadIdx.y + 8*i) * N + n0 + threadIdx.x];
    __syncthreads();
    #pragma unroll
    for (int i = 0; i < 4; i++) {
        int n = n0 + threadIdx.y + 8*i;
        int k = k0 + threadIdx.x;
        float v = t[threadIdx.x][threadIdx.y + 8*i];
        __nv_bfloat16 hi = __float2bfloat16_rn(v);
        __nv_bfloat16 lo = __float2bfloat16_rn(v - __bfloat162float(hi));
        size_t rb = (size_t)n * (3 * (size_t)K);
        WT3[rb + k]       = hi;
        WT3[rb + K + k]   = hi;
        WT3[rb + 2*K + k] = lo;
    }
}

// ---------------- bf16 mma.sync GEMM ------------------------------------------
// MODE 0: fp32 out (+bias/res). MODE 1: split-bf16 relu(x+bias). MODE 2: plain bf16.
#define ASTR 80
#define STAGE_BYTES (2 * 128 * ASTR)
#define GSM_TOTAL (3 * STAGE_BYTES)

template<int MODE>
__global__ void __launch_bounds__(256, 1)
gemm_mma(const __nv_bfloat16* __restrict__ A3, const __nv_bfloat16* __restrict__ BT3,
         float* __restrict__ C, __nv_bfloat16* __restrict__ Cs,
         const float* __restrict__ bias, const float* __restrict__ res,
         int M, int N, int K3)
{
    extern __shared__ char smem[];
    uint32_t sb = smem_u32(smem);
    int tid = threadIdx.x, wid = tid >> 5, lane = tid & 31;
    int bm = blockIdx.y, bn = blockIdx.x;
    int warp_m = wid >> 2, warp_n = wid & 3;

    const int nk = K3 / 32;

    auto load_stage = [&](int k0, int st) {
        uint32_t base = sb + st * STAGE_BYTES;
        #pragma unroll
        for (int hh = 0; hh < 2; hh++) {
            int c = tid + hh * 256;
            int row = c >> 2, kc = c & 3;
            cp16(base + row * ASTR + kc * 16,
                 A3 + (size_t)(bm * 128 + row) * K3 + k0 + kc * 8);
            cp16(base + 128 * ASTR + row * ASTR + kc * 16,
                 BT3 + (size_t)(bn * 128 + row) * K3 + k0 + kc * 8);
        }
        cp_commit();
    };

    load_stage(0, 0);
    load_stage(32, 1);

    float acc[4][4][4];
    #pragma unroll
    for (int i = 0; i < 4; i++)
        #pragma unroll
        for (int j = 0; j < 4; j++)
            #pragma unroll
            for (int r = 0; r < 4; r++) acc[i][j][r] = 0.f;

    uint32_t aBase = (uint32_t)((warp_m * 64 + (lane & 15)) * ASTR + (lane >> 4) * 16);
    uint32_t bBase = (uint32_t)(128 * ASTR +
                     (warp_n * 32 + ((lane >> 4) << 3) + (lane & 7)) * ASTR +
                     ((lane >> 3) & 1) * 16);

    for (int kt = 0; kt < nk; kt++) {
        cp_wait<1>();
        __syncthreads();
        int nxt = kt + 2;
        if (nxt < nk) load_stage(nxt * 32, nxt % 3);

        uint32_t stb = sb + (kt % 3) * STAGE_BYTES;
        #pragma unroll
        for (int s = 0; s < 2; s++) {
            uint32_t afr[4][4], bfr[2][4];
            #pragma unroll
            for (int i = 0; i < 4; i++)
                ldsm_x4(afr[i], stb + aBase + i * 16 * ASTR + s * 32);
            #pragma unroll
            for (int jj = 0; jj < 2; jj++)
                ldsm_x4(bfr[jj], stb + bBase + jj * 16 * ASTR + s * 32);
            #pragma unroll
            for (int i = 0; i < 4; i++) {
                #pragma unroll
                for (int j = 0; j < 4; j++)
                    mma16816(acc[i][j], afr[i], &bfr[j >> 1][(j & 1) * 2]);
            }
        }
        __syncthreads();
    }

    int g = lane >> 2, tig = lane & 3;
    #pragma unroll
    for (int i = 0; i < 4; i++) {
        #pragma unroll
        for (int half = 0; half < 2; half++) {
            int row = bm * 128 + warp_m * 64 + i * 16 + g + half * 8;
            #pragma unroll
            for (int j = 0; j < 4; j++) {
                int col = bn * 128 + warp_n * 32 + j * 8 + tig * 2;
                float v0 = acc[i][j][half * 2];
                float v1 = acc[i][j][half * 2 + 1];
                if (MODE == 1) {
                    v0 = fmaxf(v0 + bias[col], 0.f);
                    v1 = fmaxf(v1 + bias[col + 1], 0.f);
                    __nv_bfloat16 h0 = __float2bfloat16_rn(v0);
                    __nv_bfloat16 h1 = __float2bfloat16_rn(v1);
                    __nv_bfloat162 hh; hh.x = h0; hh.y = h1;
                    __nv_bfloat162 ll;
                    ll.x = __float2bfloat16_rn(v0 - __bfloat162float(h0));
                    ll.y = __float2bfloat16_rn(v1 - __bfloat162float(h1));
                    size_t rb = (size_t)row * (3 * (size_t)N);
                    *(__nv_bfloat162*)(Cs + rb + col)                 = hh;
                    *(__nv_bfloat162*)(Cs + rb + N + col)             = ll;
                    *(__nv_bfloat162*)(Cs + rb + 2 * (size_t)N + col) = hh;
                } else if (MODE == 2) {
                    __nv_bfloat162 hh;
                    hh.x = __float2bfloat16_rn(v0);
                    hh.y = __float2bfloat16_rn(v1);
                    *(__nv_bfloat162*)(Cs + (size_t)row * N + col) = hh;
                } else {
                    if (bias) { v0 += bias[col]; v1 += bias[col + 1]; }
                    size_t rb = (size_t)row * N;
                    if (res) {
                        float2 rr = *(const float2*)(res + rb + col);
                        v0 += rr.x; v1 += rr.y;
                    }
                    float2 o; o.x = v0; o.y = v1;
                    *(float2*)(C + rb + col) = o;
                }
            }
        }
    }
}

// ---------------- Tensor-core flash attention (bf16, fp32 softmax) ------------
#define TSTR 144
#define AQOFF 0
#define AKOFF 18432
#define AVOFF 36864
#define AMOFF 55296
#define ATT_SMEM 63488

__global__ void __launch_bounds__(256, 1)
attn_tc(const __nv_bfloat16* __restrict__ qkv, const int* __restrict__ mask,
        __nv_bfloat16* __restrict__ ao)
{
    extern __shared__ char smem[];
    uint32_t sb = smem_u32(smem);
    int tid = threadIdx.x, wid = tid >> 5, lane = tid & 31;
    int g = lane >> 2, tig = lane & 3;
    int bh = blockIdx.y;
    int b = bh >> 4, hd = bh & 15;
    int q0 = blockIdx.x * 128;

    const __nv_bfloat16* qg = qkv + (size_t)(b * SEQ) * QKVW + hd * DKH;

    #pragma unroll
    for (int i = 0; i < 4; i++) {
        int c = tid + i * 256;
        int row = c >> 3, kc = c & 7;
        cp16(sb + AQOFF + row * TSTR + kc * 16,
             qg + (size_t)(q0 + row) * QKVW + kc * 8);
    }
    #pragma unroll
    for (int i = 0; i < 2; i++) {
        int c = tid + i * 256;
        cp16(sb + AMOFF + c * 16, mask + (size_t)b * SEQ + c * 4);
    }
    auto load_kv = [&](int jt, int buf) {
        #pragma unroll
        for (int i = 0; i < 2; i++) {
            int c = tid + i * 256;
            int row = c >> 3, kc = c & 7;
            cp16(sb + AKOFF + buf * 9216 + row * TSTR + kc * 16,
                 qg + (size_t)(jt * 64 + row) * QKVW + EMB + kc * 8);
            cp16(sb + AVOFF + buf * 9216 + row * TSTR + kc * 16,
                 qg + (size_t)(jt * 64 + row) * QKVW + 2 * EMB + kc * 8);
        }
    };
    load_kv(0, 0);
    cp_commit();

    uint32_t qfr[4][4];
    float ofr[8][4];
    #pragma unroll
    for (int j = 0; j < 8; j++)
        #pragma unroll
        for (int r = 0; r < 4; r++) ofr[j][r] = 0.f;
    float m0 = -3.0e38f, m1 = -3.0e38f, l0 = 0.f, l1 = 0.f;

    uint32_t aQ = (uint32_t)(AQOFF + (wid * 16 + (lane & 15)) * TSTR + (lane >> 4) * 16);
    uint32_t bK = (uint32_t)((((lane >> 4) << 3) + (lane & 7)) * TSTR + ((lane >> 3) & 1) * 16);
    uint32_t bV = (uint32_t)((((lane >> 3) & 1) * 8 + (lane & 7)) * TSTR + (lane >> 4) * 16);

    const int NJT = SEQ / 64;
    for (int jt = 0; jt < NJT; jt++) {
        cp_wait<0>();
        __syncthreads();
        if (jt == 0) {
            #pragma unroll
            for (int ks = 0; ks < 4; ks++) ldsm_x4(qfr[ks], sb + aQ + ks * 32);
        }
        if (jt + 1 < NJT) { load_kv(jt + 1, (jt + 1) & 1); cp_commit(); }

        uint32_t kb = sb + AKOFF + (jt & 1) * 9216;
        uint32_t vb = sb + AVOFF + (jt & 1) * 9216;

        float sfr[8][4];
        #pragma unroll
        for (int j = 0; j < 8; j++)
            #pragma unroll
            for (int r = 0; r < 4; r++) sfr[j][r] = 0.f;
        #pragma unroll
        for (int ks = 0; ks < 4; ks++) {
            uint32_t bfr[4][4];
            #pragma unroll
            for (int ng = 0; ng < 4; ng++)
                ldsm_x4(bfr[ng], kb + bK + ng * 16 * TSTR + ks * 32);
            #pragma unroll
            for (int j = 0; j < 8; j++)
                mma16816(sfr[j], qfr[ks], &bfr[j >> 1][(j & 1) * 2]);
        }

        #pragma unroll
        for (int j = 0; j < 8; j++) {
            int2 mv = *(const int2*)(smem + AMOFF + (jt * 64 + j * 8 + tig * 2) * 4);
            sfr[j][0] = (mv.x == 0) ? -1e30f : sfr[j][0] * 0.125f;
            sfr[j][1] = (mv.y == 0) ? -1e30f : sfr[j][1] * 0.125f;
            sfr[j][2] = (mv.x == 0) ? -1e30f : sfr[j][2] * 0.125f;
            sfr[j][3] = (mv.y == 0) ? -1e30f : sfr[j][3] * 0.125f;
        }

        float mx0 = -3.0e38f, mx1 = -3.0e38f;
        #pragma unroll
        for (int j = 0; j < 8; j++) {
            mx0 = fmaxf(mx0, fmaxf(sfr[j][0], sfr[j][1]));
            mx1 = fmaxf(mx1, fmaxf(sfr[j][2], sfr[j][3]));
        }
        #pragma unroll
        for (int off = 1; off < 4; off <<= 1) {
            mx0 = fmaxf(mx0, __shfl_xor_sync(0xffffffffu, mx0, off));
            mx1 = fmaxf(mx1, __shfl_xor_sync(0xffffffffu, mx1, off));
        }
        float mn0 = fmaxf(m0, mx0), mn1 = fmaxf(m1, mx1);
        float al0 = __expf(m0 - mn0), al1 = __expf(m1 - mn1);
        float ls0 = 0.f, ls1 = 0.f;
        #pragma unroll
        for (int j = 0; j < 8; j++) {
            sfr[j][0] = __expf(sfr[j][0] - mn0);
            sfr[j][1] = __expf(sfr[j][1] - mn0);
            sfr[j][2] = __expf(sfr[j][2] - mn1);
            sfr[j][3] = __expf(sfr[j][3] - mn1);
            ls0 += sfr[j][0] + sfr[j][1];
            ls1 += sfr[j][2] + sfr[j][3];
        }
        #pragma unroll
        for (int off = 1; off < 4; off <<= 1) {
            ls0 += __shfl_xor_sync(0xffffffffu, ls0, off);
            ls1 += __shfl_xor_sync(0xffffffffu, ls1, off);
        }
        l0 = l0 * al0 + ls0; l1 = l1 * al1 + ls1;
        m0 = mn0; m1 = mn1;
        #pragma unroll
        for (int j = 0; j < 8; j++) {
            ofr[j][0] *= al0; ofr[j][1] *= al0;
            ofr[j][2] *= al1; ofr[j][3] *= al1;
        }

        #pragma unroll
        for (int ks = 0; ks < 4; ks++) {
            uint32_t pa[4];
            pa[0] = packbf(sfr[2*ks][0],   sfr[2*ks][1]);
            pa[1] = packbf(sfr[2*ks][2],   sfr[2*ks][3]);
            pa[2] = packbf(sfr[2*ks+1][0], sfr[2*ks+1][1]);
            pa[3] = packbf(sfr[2*ks+1][2], sfr[2*ks+1][3]);
            #pragma unroll
            for (int jp = 0; jp < 4; jp++) {
                uint32_t vfr[4];
                ldsm_x4t(vfr, vb + bV + ks * 16 * TSTR + jp * 32);
                mma16816(ofr[2*jp],     pa, &vfr[0]);
                mma16816(ofr[2*jp + 1], pa, &vfr[2]);
            }
        }
        __syncthreads();
    }

    // epilogue: normalize, write plain bf16 ao [row, EMB]
    float inv0 = 1.f / l0, inv1 = 1.f / l1;
    int r0 = b * SEQ + q0 + wid * 16 + g;
    #pragma unroll
    for (int half = 0; half < 2; half++) {
        int grow = r0 + half * 8;
        float inv = half ? inv1 : inv0;
        __nv_bfloat16* base = ao + (size_t)grow * EMB + hd * DKH;
        #pragma unroll
        for (int j = 0; j < 8; j++) {
            int col = j * 8 + tig * 2;
            __nv_bfloat162 hh = __floats2bfloat162_rn(ofr[j][half * 2] * inv,
                                                      ofr[j][half * 2 + 1] * inv);
            *(__nv_bfloat162*)(base + col) = hh;
        }
    }
}

// ---------------- launch ------------------------------------------------------
extern "C" void kernel_launch(void* const* d_in, const int* in_sizes, int n_in,
                              void* d_out, int out_size)
{
    const float* x    = (const float*)d_in[0];
    const int*   mask = (const int*)  d_in[1];
    const float* wq   = (const float*)d_in[2];
    const float* wk   = (const float*)d_in[3];
    const float* wv   = (const float*)d_in[4];
    const float* wo   = (const float*)d_in[5];
    const float* ff1w = (const float*)d_in[6];
    const float* ff1b = (const float*)d_in[7];
    const float* ff2w = (const float*)d_in[8];
    const float* ff2b = (const float*)d_in[9];
    const float* ln1a = (const float*)d_in[10];
    const float* ln1b = (const float*)d_in[11];
    const float* ln2a = (const float*)d_in[12];
    const float* ln2b = (const float*)d_in[13];
    float* out = (float*)d_out;

    __nv_bfloat16 *ab, *a3a, *a3c, *w3, *wp, *qkvh;
    float *h;
    cudaGetSymbolAddress((void**)&ab,   g_ab);
    cudaGetSymbolAddress((void**)&a3a,  g_a3a);
    cudaGetSymbolAddress((void**)&a3c,  g_a3c);
    cudaGetSymbolAddress((void**)&w3,   g_w3);
    cudaGetSymbolAddress((void**)&wp,   g_wp);
    cudaGetSymbolAddress((void**)&qkvh, g_qkvh);
    cudaGetSymbolAddress((void**)&h,    g_h);

    cudaFuncSetAttribute(attn_tc, cudaFuncAttributeMaxDynamicSharedMemorySize, ATT_SMEM);
    cudaFuncSetAttribute(gemm_mma<0>, cudaFuncAttributeMaxDynamicSharedMemorySize, GSM_TOTAL);
    cudaFuncSetAttribute(gemm_mma<1>, cudaFuncAttributeMaxDynamicSharedMemorySize, GSM_TOTAL);
    cudaFuncSetAttribute(gemm_mma<2>, cudaFuncAttributeMaxDynamicSharedMemorySize, GSM_TOTAL);

    dim3 tb(32, 8);
    dim3 gQKV(QKVW / 128, MROWS / 128);  // (24, 32)
    dim3 gE(EMB / 128, MROWS / 128);     // (8, 32)
    dim3 gH(HID / 128, MROWS / 128);     // (32, 32)

    // 1) ln1(x) -> ab (plain bf16)
    ln_plain_kernel<<<MROWS, 256>>>(x, ab, ln1a, ln1b);
    // 2) plain transposed wq|wk|wv packed into wp [3072, 1024]
    wt_plain_kernel<<<dim3(EMB/32, EMB/32), tb>>>(wq, wp, EMB, EMB);
    wt_plain_kernel<<<dim3(EMB/32, EMB/32), tb>>>(wk, wp + (size_t)EMB * EMB, EMB, EMB);
    wt_plain_kernel<<<dim3(EMB/32, EMB/32), tb>>>(wv, wp + (size_t)(2 * EMB) * EMB, EMB, EMB);
    // 3) fused QKV projection (plain bf16, K=1024)
    gemm_mma<2><<<gQKV, 256, GSM_TOTAL>>>(ab, wp, nullptr, qkvh, nullptr, nullptr, MROWS, QKVW, EMB);
    // 4) attention -> ab (plain bf16, reuse)
    attn_tc<<<dim3(SEQ / 128, BATCH * NH), 256, ATT_SMEM>>>(qkvh, mask, ab);
    // 5) h = x + ao @ wo (plain bf16, K=1024)
    wt_plain_kernel<<<dim3(EMB/32, EMB/32), tb>>>(wo, wp, EMB, EMB);
    gemm_mma<0><<<gE, 256, GSM_TOTAL>>>(ab, wp, h, nullptr, nullptr, x, MROWS, EMB, EMB);
    // 6) ln2(h) -> a3a (split)
    ln_split_kernel<<<MROWS, 256>>>(h, a3a, ln2a, ln2b);
    // 7) a3c = split(relu(ln2 @ ff1_w + ff1_b))  (split, K=3072)
    wt_split_kernel<<<dim3(HID/32, EMB/32), tb>>>(ff1w, w3, EMB, HID);
    gemm_mma<1><<<gH, 256, GSM_TOTAL>>>(a3a, w3, nullptr, a3c, ff1b, nullptr, MROWS, HID, K3E);
    // 8) out = h + ffa @ ff2_w + ff2_b  (split, K=12288)
    wt_split_kernel<<<dim3(EMB/32, HID/32), tb>>>(ff2w, w3, HID, EMB);
    gemm_mma<0><<<gE, 256, GSM_TOTAL>>>(a3c, w3, out, nullptr, ff2b, h, MROWS, EMB, K3H);
}

// round 7
// speedup vs baseline: 3.4500x; 1.0852x over previous
#include <cuda_runtime.h>
#include <cuda_bf16.h>
#include <math.h>
#include <stdint.h>

#define EMB 1024
#define HID 4096
#define NH 16
#define DKH 64
#define BATCH 2
#define SEQ 2048
#define MROWS (BATCH * SEQ)     // 4096
#define K3E (3 * EMB)           // 3072
#define K3H (3 * HID)           // 12288
#define QKVW (3 * EMB)

// ---------------- scratch (__device__ globals, allocation-free) ---------------
__device__ __nv_bfloat16 g_ab  [MROWS * EMB];          // ln1 out, later attention out
__device__ __nv_bfloat16 g_a3a [MROWS * K3E];          // ln2 out (split)
__device__ __nv_bfloat16 g_a3c [(size_t)MROWS * K3H];  // relu(ff1) (split)
__device__ __nv_bfloat16 g_w3  [(size_t)HID * K3E];    // split weights (ff1/ff2)
__device__ __nv_bfloat16 g_wp  [(size_t)(4 * EMB) * EMB]; // plain transposed qkv|wo
__device__ __nv_bfloat16 g_qkvh[(size_t)MROWS * QKVW]; // packed q|k|v bf16
__device__ float g_h[MROWS * EMB];

// ---------------- PTX helpers (base ISA only) ----------------------------------
__device__ __forceinline__ uint32_t smem_u32(const void* p) {
    return (uint32_t)__cvta_generic_to_shared(p);
}
__device__ __forceinline__ void cp16(uint32_t dst, const void* src) {
    asm volatile("cp.async.cg.shared.global [%0], [%1], 16;" :: "r"(dst), "l"(src));
}
__device__ __forceinline__ void cp_commit() {
    asm volatile("cp.async.commit_group;");
}
template<int N> __device__ __forceinline__ void cp_wait() {
    asm volatile("cp.async.wait_group %0;" :: "n"(N));
}
__device__ __forceinline__ void ldsm_x4(uint32_t* r, uint32_t addr) {
    asm volatile("ldmatrix.sync.aligned.m8n8.x4.shared.b16 {%0,%1,%2,%3}, [%4];"
                 : "=r"(r[0]), "=r"(r[1]), "=r"(r[2]), "=r"(r[3]) : "r"(addr));
}
__device__ __forceinline__ void ldsm_x4t(uint32_t* r, uint32_t addr) {
    asm volatile("ldmatrix.sync.aligned.m8n8.x4.trans.shared.b16 {%0,%1,%2,%3}, [%4];"
                 : "=r"(r[0]), "=r"(r[1]), "=r"(r[2]), "=r"(r[3]) : "r"(addr));
}
__device__ __forceinline__ void mma16816(float* d, const uint32_t* a, const uint32_t* b) {
    asm volatile(
        "mma.sync.aligned.m16n8k16.row.col.f32.bf16.bf16.f32 "
        "{%0,%1,%2,%3}, {%4,%5,%6,%7}, {%8,%9}, {%0,%1,%2,%3};"
        : "+f"(d[0]), "+f"(d[1]), "+f"(d[2]), "+f"(d[3])
        : "r"(a[0]), "r"(a[1]), "r"(a[2]), "r"(a[3]), "r"(b[0]), "r"(b[1]));
}
__device__ __forceinline__ uint32_t packbf(float a, float b) {
    __nv_bfloat162 h = __floats2bfloat162_rn(a, b);
    return *(uint32_t*)&h;
}

// ---------------- LayerNorm helpers -------------------------------------------
__device__ __forceinline__ void ln_stats(float4 v, float& mean, float& inv,
                                         const float* al) {
    float s  = v.x + v.y + v.z + v.w;
    float ss = v.x*v.x + v.y*v.y + v.z*v.z + v.w*v.w;
    #pragma unroll
    for (int off = 16; off; off >>= 1) {
        s  += __shfl_xor_sync(0xffffffffu, s,  off);
        ss += __shfl_xor_sync(0xffffffffu, ss, off);
    }
    __shared__ float rs[8], rss[8];
    int warp = threadIdx.x >> 5, lane = threadIdx.x & 31;
    if (lane == 0) { rs[warp] = s; rss[warp] = ss; }
    __syncthreads();
    if (warp == 0) {
        s  = (lane < 8) ? rs[lane]  : 0.f;
        ss = (lane < 8) ? rss[lane] : 0.f;
        #pragma unroll
        for (int off = 16; off; off >>= 1) {
            s  += __shfl_xor_sync(0xffffffffu, s,  off);
            ss += __shfl_xor_sync(0xffffffffu, ss, off);
        }
        if (lane == 0) { rs[0] = s; rss[0] = ss; }
    }
    __syncthreads();
    s = rs[0]; ss = rss[0];
    mean = s * (1.0f / EMB);
    float var = fmaxf(ss - (float)EMB * mean * mean, 0.f) * (1.0f / (EMB - 1));
    inv = al[0] / (sqrtf(var) + 1e-6f);
}

__global__ void ln_plain_kernel(const float* __restrict__ x, __nv_bfloat16* __restrict__ y,
                                const float* __restrict__ al, const float* __restrict__ be)
{
    int row = blockIdx.x;
    float4 v = ((const float4*)(x + (size_t)row * EMB))[threadIdx.x];
    float mean, inv;
    ln_stats(v, mean, inv, al);
    float bb = be[0];
    int col = threadIdx.x * 4;
    __nv_bfloat16* rowp = y + (size_t)row * EMB;
    __nv_bfloat162 h0 = __floats2bfloat162_rn((v.x - mean) * inv + bb, (v.y - mean) * inv + bb);
    __nv_bfloat162 h1 = __floats2bfloat162_rn((v.z - mean) * inv + bb, (v.w - mean) * inv + bb);
    *(__nv_bfloat162*)(rowp + col)     = h0;
    *(__nv_bfloat162*)(rowp + col + 2) = h1;
}

__global__ void ln_split_kernel(const float* __restrict__ x, __nv_bfloat16* __restrict__ y3,
                                const float* __restrict__ al, const float* __restrict__ be)
{
    int row = blockIdx.x;
    float4 v = ((const float4*)(x + (size_t)row * EMB))[threadIdx.x];
    float mean, inv;
    ln_stats(v, mean, inv, al);
    float bb = be[0];
    float o[4] = { (v.x - mean) * inv + bb, (v.y - mean) * inv + bb,
                   (v.z - mean) * inv + bb, (v.w - mean) * inv + bb };
    int col = threadIdx.x * 4;
    __nv_bfloat16* rowp = y3 + (size_t)row * K3E;
    #pragma unroll
    for (int p = 0; p < 2; p++) {
        float a0 = o[p*2], a1 = o[p*2+1];
        __nv_bfloat16 h0 = __float2bfloat16_rn(a0);
        __nv_bfloat16 h1 = __float2bfloat16_rn(a1);
        __nv_bfloat162 hh; hh.x = h0; hh.y = h1;
        __nv_bfloat162 ll;
        ll.x = __float2bfloat16_rn(a0 - __bfloat162float(h0));
        ll.y = __float2bfloat16_rn(a1 - __bfloat162float(h1));
        *(__nv_bfloat162*)(rowp + col + p*2)         = hh;
        *(__nv_bfloat162*)(rowp + EMB + col + p*2)   = ll;
        *(__nv_bfloat162*)(rowp + 2*EMB + col + p*2) = hh;
    }
}

// ---------------- weight transposes -------------------------------------------
__global__ void wt_plain_kernel(const float* __restrict__ W, __nv_bfloat16* __restrict__ WT,
                                int K, int N)
{
    __shared__ float t[32][33];
    int n0 = blockIdx.x * 32, k0 = blockIdx.y * 32;
    #pragma unroll
    for (int i = 0; i < 4; i++)
        t[threadIdx.y + 8*i][threadIdx.x] = W[(size_t)(k0 + threadIdx.y + 8*i) * N + n0 + threadIdx.x];
    __syncthreads();
    #pragma unroll
    for (int i = 0; i < 4; i++) {
        int n = n0 + threadIdx.y + 8*i;
        int k = k0 + threadIdx.x;
        WT[(size_t)n * K + k] = __float2bfloat16_rn(t[threadIdx.x][threadIdx.y + 8*i]);
    }
}

__global__ void wt_split_kernel(const float* __restrict__ W, __nv_bfloat16* __restrict__ WT3,
                                int K, int N)
{
    __shared__ float t[32][33];
    int n0 = blockIdx.x * 32, k0 = blockIdx.y * 32;
    #pragma unroll
    for (int i = 0; i < 4; i++)
        t[threadIdx.y + 8*i][threadIdx.x] = W[(size_t)(k0 + threadIdx.y + 8*i) * N + n0 + threadIdx.x];
    __syncthreads();
    #pragma unroll
    for (int i = 0; i < 4; i++) {
        int n = n0 + threadIdx.y + 8*i;
        int k = k0 + threadIdx.x;
        float v = t[threadIdx.x][threadIdx.y + 8*i];
        __nv_bfloat16 hi = __float2bfloat16_rn(v);
        __nv_bfloat16 lo = __float2bfloat16_rn(v - __bfloat162float(hi));
        size_t rb = (size_t)n * (3 * (size_t)K);
        WT3[rb + k]       = hi;
        WT3[rb + K + k]   = hi;
        WT3[rb + 2*K + k] = lo;
    }
}

// ---------------- bf16 mma.sync GEMM (256x128 CTA, 64x64 warp) ----------------
// MODE 0: fp32 out (+bias/res). MODE 1: split-bf16 relu(x+bias). MODE 2: plain bf16.
#define ASTR 80
#define A_STAGE (256 * ASTR)                 // 20480
#define B_STAGE (128 * ASTR)                 // 10240
#define STAGE_BYTES (A_STAGE + B_STAGE)      // 30720
#define GSM_TOTAL (3 * STAGE_BYTES)          // 92160

template<int MODE>
__global__ void __launch_bounds__(256, 1)
gemm_mma(const __nv_bfloat16* __restrict__ A3, const __nv_bfloat16* __restrict__ BT3,
         float* __restrict__ C, __nv_bfloat16* __restrict__ Cs,
         const float* __restrict__ bias, const float* __restrict__ res,
         int M, int N, int K3)
{
    extern __shared__ char smem[];
    uint32_t sb = smem_u32(smem);
    int tid = threadIdx.x, wid = tid >> 5, lane = tid & 31;
    int bm = blockIdx.y, bn = blockIdx.x;
    int warp_m = wid >> 1, warp_n = wid & 1;    // 4 x 2

    const int nk = K3 / 32;

    auto load_stage = [&](int k0, int st) {
        uint32_t base = sb + st * STAGE_BYTES;
        #pragma unroll
        for (int i = 0; i < 4; i++) {            // A: 1024 chunks
            int c = tid + i * 256;
            int row = c >> 2, kc = c & 3;
            cp16(base + row * ASTR + kc * 16,
                 A3 + (size_t)(bm * 256 + row) * K3 + k0 + kc * 8);
        }
        #pragma unroll
        for (int i = 0; i < 2; i++) {            // B: 512 chunks
            int c = tid + i * 256;
            int row = c >> 2, kc = c & 3;
            cp16(base + A_STAGE + row * ASTR + kc * 16,
                 BT3 + (size_t)(bn * 128 + row) * K3 + k0 + kc * 8);
        }
        cp_commit();
    };

    load_stage(0, 0);
    load_stage(32, 1);

    float acc[4][8][4];
    #pragma unroll
    for (int i = 0; i < 4; i++)
        #pragma unroll
        for (int j = 0; j < 8; j++)
            #pragma unroll
            for (int r = 0; r < 4; r++) acc[i][j][r] = 0.f;

    uint32_t aBase = (uint32_t)((warp_m * 64 + (lane & 15)) * ASTR + (lane >> 4) * 16);
    uint32_t bBase = (uint32_t)(A_STAGE +
                     (warp_n * 64 + ((lane >> 4) << 3) + (lane & 7)) * ASTR +
                     ((lane >> 3) & 1) * 16);

    for (int kt = 0; kt < nk; kt++) {
        cp_wait<1>();
        __syncthreads();
        int nxt = kt + 2;
        if (nxt < nk) load_stage(nxt * 32, nxt % 3);

        uint32_t stb = sb + (kt % 3) * STAGE_BYTES;
        #pragma unroll
        for (int s = 0; s < 2; s++) {
            uint32_t afr[4][4], bfr[4][4];
            #pragma unroll
            for (int i = 0; i < 4; i++)
                ldsm_x4(afr[i], stb + aBase + i * 16 * ASTR + s * 32);
            #pragma unroll
            for (int ng = 0; ng < 4; ng++)
                ldsm_x4(bfr[ng], stb + bBase + ng * 16 * ASTR + s * 32);
            #pragma unroll
            for (int i = 0; i < 4; i++) {
                #pragma unroll
                for (int j = 0; j < 8; j++)
                    mma16816(acc[i][j], afr[i], &bfr[j >> 1][(j & 1) * 2]);
            }
        }
        __syncthreads();
    }

    int g = lane >> 2, tig = lane & 3;
    #pragma unroll
    for (int i = 0; i < 4; i++) {
        #pragma unroll
        for (int half = 0; half < 2; half++) {
            int row = bm * 256 + warp_m * 64 + i * 16 + g + half * 8;
            #pragma unroll
            for (int j = 0; j < 8; j++) {
                int col = bn * 128 + warp_n * 64 + j * 8 + tig * 2;
                float v0 = acc[i][j][half * 2];
                float v1 = acc[i][j][half * 2 + 1];
                if (MODE == 1) {
                    v0 = fmaxf(v0 + bias[col], 0.f);
                    v1 = fmaxf(v1 + bias[col + 1], 0.f);
                    __nv_bfloat16 h0 = __float2bfloat16_rn(v0);
                    __nv_bfloat16 h1 = __float2bfloat16_rn(v1);
                    __nv_bfloat162 hh; hh.x = h0; hh.y = h1;
                    __nv_bfloat162 ll;
                    ll.x = __float2bfloat16_rn(v0 - __bfloat162float(h0));
                    ll.y = __float2bfloat16_rn(v1 - __bfloat162float(h1));
                    size_t rb = (size_t)row * (3 * (size_t)N);
                    *(__nv_bfloat162*)(Cs + rb + col)                 = hh;
                    *(__nv_bfloat162*)(Cs + rb + N + col)             = ll;
                    *(__nv_bfloat162*)(Cs + rb + 2 * (size_t)N + col) = hh;
                } else if (MODE == 2) {
                    __nv_bfloat162 hh;
                    hh.x = __float2bfloat16_rn(v0);
                    hh.y = __float2bfloat16_rn(v1);
                    *(__nv_bfloat162*)(Cs + (size_t)row * N + col) = hh;
                } else {
                    if (bias) { v0 += bias[col]; v1 += bias[col + 1]; }
                    size_t rb = (size_t)row * N;
                    if (res) {
                        float2 rr = *(const float2*)(res + rb + col);
                        v0 += rr.x; v1 += rr.y;
                    }
                    float2 o; o.x = v0; o.y = v1;
                    *(float2*)(C + rb + col) = o;
                }
            }
        }
    }
}

// ---------------- Tensor-core flash attention (bf16, fp32 softmax) ------------
#define TSTR 144
#define AQOFF 0
#define AKOFF 18432
#define AVOFF 36864
#define AMOFF 55296
#define ATT_SMEM 63488

__global__ void __launch_bounds__(256, 1)
attn_tc(const __nv_bfloat16* __restrict__ qkv, const int* __restrict__ mask,
        __nv_bfloat16* __restrict__ ao)
{
    extern __shared__ char smem[];
    uint32_t sb = smem_u32(smem);
    int tid = threadIdx.x, wid = tid >> 5, lane = tid & 31;
    int g = lane >> 2, tig = lane & 3;
    int bh = blockIdx.y;
    int b = bh >> 4, hd = bh & 15;
    int q0 = blockIdx.x * 128;

    const __nv_bfloat16* qg = qkv + (size_t)(b * SEQ) * QKVW + hd * DKH;

    #pragma unroll
    for (int i = 0; i < 4; i++) {
        int c = tid + i * 256;
        int row = c >> 3, kc = c & 7;
        cp16(sb + AQOFF + row * TSTR + kc * 16,
             qg + (size_t)(q0 + row) * QKVW + kc * 8);
    }
    #pragma unroll
    for (int i = 0; i < 2; i++) {
        int c = tid + i * 256;
        cp16(sb + AMOFF + c * 16, mask + (size_t)b * SEQ + c * 4);
    }
    auto load_kv = [&](int jt, int buf) {
        #pragma unroll
        for (int i = 0; i < 2; i++) {
            int c = tid + i * 256;
            int row = c >> 3, kc = c & 7;
            cp16(sb + AKOFF + buf * 9216 + row * TSTR + kc * 16,
                 qg + (size_t)(jt * 64 + row) * QKVW + EMB + kc * 8);
            cp16(sb + AVOFF + buf * 9216 + row * TSTR + kc * 16,
                 qg + (size_t)(jt * 64 + row) * QKVW + 2 * EMB + kc * 8);
        }
    };
    load_kv(0, 0);
    cp_commit();

    uint32_t qfr[4][4];
    float ofr[8][4];
    #pragma unroll
    for (int j = 0; j < 8; j++)
        #pragma unroll
        for (int r = 0; r < 4; r++) ofr[j][r] = 0.f;
    float m0 = -3.0e38f, m1 = -3.0e38f, l0 = 0.f, l1 = 0.f;

    uint32_t aQ = (uint32_t)(AQOFF + (wid * 16 + (lane & 15)) * TSTR + (lane >> 4) * 16);
    uint32_t bK = (uint32_t)((((lane >> 4) << 3) + (lane & 7)) * TSTR + ((lane >> 3) & 1) * 16);
    uint32_t bV = (uint32_t)((((lane >> 3) & 1) * 8 + (lane & 7)) * TSTR + (lane >> 4) * 16);

    const int NJT = SEQ / 64;
    for (int jt = 0; jt < NJT; jt++) {
        cp_wait<0>();
        __syncthreads();
        if (jt == 0) {
            #pragma unroll
            for (int ks = 0; ks < 4; ks++) ldsm_x4(qfr[ks], sb + aQ + ks * 32);
        }
        if (jt + 1 < NJT) { load_kv(jt + 1, (jt + 1) & 1); cp_commit(); }

        uint32_t kb = sb + AKOFF + (jt & 1) * 9216;
        uint32_t vb = sb + AVOFF + (jt & 1) * 9216;

        float sfr[8][4];
        #pragma unroll
        for (int j = 0; j < 8; j++)
            #pragma unroll
            for (int r = 0; r < 4; r++) sfr[j][r] = 0.f;
        #pragma unroll
        for (int ks = 0; ks < 4; ks++) {
            uint32_t bfr[4][4];
            #pragma unroll
            for (int ng = 0; ng < 4; ng++)
                ldsm_x4(bfr[ng], kb + bK + ng * 16 * TSTR + ks * 32);
            #pragma unroll
            for (int j = 0; j < 8; j++)
                mma16816(sfr[j], qfr[ks], &bfr[j >> 1][(j & 1) * 2]);
        }

        #pragma unroll
        for (int j = 0; j < 8; j++) {
            int2 mv = *(const int2*)(smem + AMOFF + (jt * 64 + j * 8 + tig * 2) * 4);
            sfr[j][0] = (mv.x == 0) ? -1e30f : sfr[j][0] * 0.125f;
            sfr[j][1] = (mv.y == 0) ? -1e30f : sfr[j][1] * 0.125f;
            sfr[j][2] = (mv.x == 0) ? -1e30f : sfr[j][2] * 0.125f;
            sfr[j][3] = (mv.y == 0) ? -1e30f : sfr[j][3] * 0.125f;
        }

        float mx0 = -3.0e38f, mx1 = -3.0e38f;
        #pragma unroll
        for (int j = 0; j < 8; j++) {
            mx0 = fmaxf(mx0, fmaxf(sfr[j][0], sfr[j][1]));
            mx1 = fmaxf(mx1, fmaxf(sfr[j][2], sfr[j][3]));
        }
        #pragma unroll
        for (int off = 1; off < 4; off <<= 1) {
            mx0 = fmaxf(mx0, __shfl_xor_sync(0xffffffffu, mx0, off));
            mx1 = fmaxf(mx1, __shfl_xor_sync(0xffffffffu, mx1, off));
        }
        float mn0 = fmaxf(m0, mx0), mn1 = fmaxf(m1, mx1);
        float al0 = __expf(m0 - mn0), al1 = __expf(m1 - mn1);
        float ls0 = 0.f, ls1 = 0.f;
        #pragma unroll
        for (int j = 0; j < 8; j++) {
            sfr[j][0] = __expf(sfr[j][0] - mn0);
            sfr[j][1] = __expf(sfr[j][1] - mn0);
            sfr[j][2] = __expf(sfr[j][2] - mn1);
            sfr[j][3] = __expf(sfr[j][3] - mn1);
            ls0 += sfr[j][0] + sfr[j][1];
            ls1 += sfr[j][2] + sfr[j][3];
        }
        #pragma unroll
        for (int off = 1; off < 4; off <<= 1) {
            ls0 += __shfl_xor_sync(0xffffffffu, ls0, off);
            ls1 += __shfl_xor_sync(0xffffffffu, ls1, off);
        }
        l0 = l0 * al0 + ls0; l1 = l1 * al1 + ls1;
        m0 = mn0; m1 = mn1;
        #pragma unroll
        for (int j = 0; j < 8; j++) {
            ofr[j][0] *= al0; ofr[j][1] *= al0;
            ofr[j][2] *= al1; ofr[j][3] *= al1;
        }

        #pragma unroll
        for (int ks = 0; ks < 4; ks++) {
            uint32_t pa[4];
            pa[0] = packbf(sfr[2*ks][0],   sfr[2*ks][1]);
            pa[1] = packbf(sfr[2*ks][2],   sfr[2*ks][3]);
            pa[2] = packbf(sfr[2*ks+1][0], sfr[2*ks+1][1]);
            pa[3] = packbf(sfr[2*ks+1][2], sfr[2*ks+1][3]);
            #pragma unroll
            for (int jp = 0; jp < 4; jp++) {
                uint32_t vfr[4];
                ldsm_x4t(vfr, vb + bV + ks * 16 * TSTR + jp * 32);
                mma16816(ofr[2*jp],     pa, &vfr[0]);
                mma16816(ofr[2*jp + 1], pa, &vfr[2]);
            }
        }
        __syncthreads();
    }

    float inv0 = 1.f / l0, inv1 = 1.f / l1;
    int r0 = b * SEQ + q0 + wid * 16 + g;
    #pragma unroll
    for (int half = 0; half < 2; half++) {
        int grow = r0 + half * 8;
        float inv = half ? inv1 : inv0;
        __nv_bfloat16* base = ao + (size_t)grow * EMB + hd * DKH;
        #pragma unroll
        for (int j = 0; j < 8; j++) {
            int col = j * 8 + tig * 2;
            __nv_bfloat162 hh = __floats2bfloat162_rn(ofr[j][half * 2] * inv,
                                                      ofr[j][half * 2 + 1] * inv);
            *(__nv_bfloat162*)(base + col) = hh;
        }
    }
}

// ---------------- launch ------------------------------------------------------
extern "C" void kernel_launch(void* const* d_in, const int* in_sizes, int n_in,
                              void* d_out, int out_size)
{
    const float* x    = (const float*)d_in[0];
    const int*   mask = (const int*)  d_in[1];
    const float* wq   = (const float*)d_in[2];
    const float* wk   = (const float*)d_in[3];
    const float* wv   = (const float*)d_in[4];
    const float* wo   = (const float*)d_in[5];
    const float* ff1w = (const float*)d_in[6];
    const float* ff1b = (const float*)d_in[7];
    const float* ff2w = (const float*)d_in[8];
    const float* ff2b = (const float*)d_in[9];
    const float* ln1a = (const float*)d_in[10];
    const float* ln1b = (const float*)d_in[11];
    const float* ln2a = (const float*)d_in[12];
    const float* ln2b = (const float*)d_in[13];
    float* out = (float*)d_out;

    __nv_bfloat16 *ab, *a3a, *a3c, *w3, *wp, *qkvh;
    float *h;
    cudaGetSymbolAddress((void**)&ab,   g_ab);
    cudaGetSymbolAddress((void**)&a3a,  g_a3a);
    cudaGetSymbolAddress((void**)&a3c,  g_a3c);
    cudaGetSymbolAddress((void**)&w3,   g_w3);
    cudaGetSymbolAddress((void**)&wp,   g_wp);
    cudaGetSymbolAddress((void**)&qkvh, g_qkvh);
    cudaGetSymbolAddress((void**)&h,    g_h);
    __nv_bfloat16* wpo = wp + (size_t)(3 * EMB) * EMB;   // wo slot

    cudaFuncSetAttribute(attn_tc, cudaFuncAttributeMaxDynamicSharedMemorySize, ATT_SMEM);
    cudaFuncSetAttribute(gemm_mma<0>, cudaFuncAttributeMaxDynamicSharedMemorySize, GSM_TOTAL);
    cudaFuncSetAttribute(gemm_mma<1>, cudaFuncAttributeMaxDynamicSharedMemorySize, GSM_TOTAL);
    cudaFuncSetAttribute(gemm_mma<2>, cudaFuncAttributeMaxDynamicSharedMemorySize, GSM_TOTAL);

    dim3 tb(32, 8);
    dim3 gQKV(QKVW / 128, MROWS / 256);  // (24, 16)
    dim3 gE(EMB / 128, MROWS / 256);     // (8, 16)
    dim3 gH(HID / 128, MROWS / 256);     // (32, 16)

    // 0-4) ln1 + all plain weight transposes (wo hoisted so ncu slot 5 = QKV GEMM)
    ln_plain_kernel<<<MROWS, 256>>>(x, ab, ln1a, ln1b);
    wt_plain_kernel<<<dim3(EMB/32, EMB/32), tb>>>(wq, wp, EMB, EMB);
    wt_plain_kernel<<<dim3(EMB/32, EMB/32), tb>>>(wk, wp + (size_t)EMB * EMB, EMB, EMB);
    wt_plain_kernel<<<dim3(EMB/32, EMB/32), tb>>>(wv, wp + (size_t)(2 * EMB) * EMB, EMB, EMB);
    wt_plain_kernel<<<dim3(EMB/32, EMB/32), tb>>>(wo, wpo, EMB, EMB);
    // 5) fused QKV projection (plain bf16, K=1024)
    gemm_mma<2><<<gQKV, 256, GSM_TOTAL>>>(ab, wp, nullptr, qkvh, nullptr, nullptr, MROWS, QKVW, EMB);
    // 6) attention -> ab (plain bf16, reuse)
    attn_tc<<<dim3(SEQ / 128, BATCH * NH), 256, ATT_SMEM>>>(qkvh, mask, ab);
    // 7) h = x + ao @ wo (plain bf16, K=1024)
    gemm_mma<0><<<gE, 256, GSM_TOTAL>>>(ab, wpo, h, nullptr, nullptr, x, MROWS, EMB, EMB);
    // 8) ln2(h) -> a3a (split)
    ln_split_kernel<<<MROWS, 256>>>(h, a3a, ln2a, ln2b);
    // 9) a3c = split(relu(ln2 @ ff1_w + ff1_b))  (split, K=3072)
    wt_split_kernel<<<dim3(HID/32, EMB/32), tb>>>(ff1w, w3, EMB, HID);
    gemm_mma<1><<<gH, 256, GSM_TOTAL>>>(a3a, w3, nullptr, a3c, ff1b, nullptr, MROWS, HID, K3E);
    // 10) out = h + ffa @ ff2_w + ff2_b  (split, K=12288)
    wt_split_kernel<<<dim3(EMB/32, HID/32), tb>>>(ff2w, w3, HID, EMB);
    gemm_mma<0><<<gE, 256, GSM_TOTAL>>>(a3c, w3, out, nullptr, ff2b, h, MROWS, EMB, K3H);
}

// round 8
// speedup vs baseline: 3.7116x; 1.0758x over previous
#include <cuda_runtime.h>
#include <cuda_bf16.h>
#include <math.h>
#include <stdint.h>

#define EMB 1024
#define HID 4096
#define NH 16
#define DKH 64
#define BATCH 2
#define SEQ 2048
#define MROWS (BATCH * SEQ)     // 4096
#define K3E (3 * EMB)           // 3072
#define K3H (3 * HID)           // 12288
#define QKVW (3 * EMB)

// ---------------- scratch (__device__ globals, allocation-free) ---------------
__device__ __nv_bfloat16 g_ab  [MROWS * EMB];            // ln1 out, later attn out
__device__ __nv_bfloat16 g_a3a [MROWS * K3E];            // ln2 out (split)
__device__ __nv_bfloat16 g_a3c [(size_t)MROWS * K3H];    // relu(ff1) (split)
__device__ __nv_bfloat16 g_w3  [(size_t)HID * K3E];      // split weights (ff1/ff2)
__device__ __nv_bfloat16 g_wp  [(size_t)(4 * EMB) * EMB];// plain transposed qkv|wo
__device__ __nv_bfloat16 g_qkvh[(size_t)MROWS * QKVW];   // packed q|k|v bf16
__device__ float g_h   [MROWS * EMB];
__device__ float g_part[(size_t)3 * MROWS * EMB];        // split-K partials

// ---------------- PTX helpers (base ISA only) ----------------------------------
__device__ __forceinline__ uint32_t smem_u32(const void* p) {
    return (uint32_t)__cvta_generic_to_shared(p);
}
__device__ __forceinline__ void cp16(uint32_t dst, const void* src) {
    asm volatile("cp.async.cg.shared.global [%0], [%1], 16;" :: "r"(dst), "l"(src));
}
__device__ __forceinline__ void cp_commit() {
    asm volatile("cp.async.commit_group;");
}
template<int N> __device__ __forceinline__ void cp_wait() {
    asm volatile("cp.async.wait_group %0;" :: "n"(N));
}
__device__ __forceinline__ void ldsm_x4(uint32_t* r, uint32_t addr) {
    asm volatile("ldmatrix.sync.aligned.m8n8.x4.shared.b16 {%0,%1,%2,%3}, [%4];"
                 : "=r"(r[0]), "=r"(r[1]), "=r"(r[2]), "=r"(r[3]) : "r"(addr));
}
__device__ __forceinline__ void ldsm_x4t(uint32_t* r, uint32_t addr) {
    asm volatile("ldmatrix.sync.aligned.m8n8.x4.trans.shared.b16 {%0,%1,%2,%3}, [%4];"
                 : "=r"(r[0]), "=r"(r[1]), "=r"(r[2]), "=r"(r[3]) : "r"(addr));
}
__device__ __forceinline__ void mma16816(float* d, const uint32_t* a, const uint32_t* b) {
    asm volatile(
        "mma.sync.aligned.m16n8k16.row.col.f32.bf16.bf16.f32 "
        "{%0,%1,%2,%3}, {%4,%5,%6,%7}, {%8,%9}, {%0,%1,%2,%3};"
        : "+f"(d[0]), "+f"(d[1]), "+f"(d[2]), "+f"(d[3])
        : "r"(a[0]), "r"(a[1]), "r"(a[2]), "r"(a[3]), "r"(b[0]), "r"(b[1]));
}
__device__ __forceinline__ uint32_t packbf(float a, float b) {
    __nv_bfloat162 h = __floats2bfloat162_rn(a, b);
    return *(uint32_t*)&h;
}

// ---------------- LayerNorm ----------------------------------------------------
__device__ __forceinline__ void ln_stats(float4 v, float& mean, float& inv,
                                         const float* al) {
    float s  = v.x + v.y + v.z + v.w;
    float ss = v.x*v.x + v.y*v.y + v.z*v.z + v.w*v.w;
    #pragma unroll
    for (int off = 16; off; off >>= 1) {
        s  += __shfl_xor_sync(0xffffffffu, s,  off);
        ss += __shfl_xor_sync(0xffffffffu, ss, off);
    }
    __shared__ float rs[8], rss[8];
    int warp = threadIdx.x >> 5, lane = threadIdx.x & 31;
    if (lane == 0) { rs[warp] = s; rss[warp] = ss; }
    __syncthreads();
    if (warp == 0) {
        s  = (lane < 8) ? rs[lane]  : 0.f;
        ss = (lane < 8) ? rss[lane] : 0.f;
        #pragma unroll
        for (int off = 16; off; off >>= 1) {
            s  += __shfl_xor_sync(0xffffffffu, s,  off);
            ss += __shfl_xor_sync(0xffffffffu, ss, off);
        }
        if (lane == 0) { rs[0] = s; rss[0] = ss; }
    }
    __syncthreads();
    s = rs[0]; ss = rss[0];
    mean = s * (1.0f / EMB);
    float var = fmaxf(ss - (float)EMB * mean * mean, 0.f) * (1.0f / (EMB - 1));
    inv = al[0] / (sqrtf(var) + 1e-6f);
}

__global__ void ln_plain_kernel(const float* __restrict__ x, __nv_bfloat16* __restrict__ y,
                                const float* __restrict__ al, const float* __restrict__ be)
{
    int row = blockIdx.x;
    float4 v = ((const float4*)(x + (size_t)row * EMB))[threadIdx.x];
    float mean, inv;
    ln_stats(v, mean, inv, al);
    float bb = be[0];
    int col = threadIdx.x * 4;
    __nv_bfloat16* rowp = y + (size_t)row * EMB;
    __nv_bfloat162 h0 = __floats2bfloat162_rn((v.x - mean) * inv + bb, (v.y - mean) * inv + bb);
    __nv_bfloat162 h1 = __floats2bfloat162_rn((v.z - mean) * inv + bb, (v.w - mean) * inv + bb);
    *(__nv_bfloat162*)(rowp + col)     = h0;
    *(__nv_bfloat162*)(rowp + col + 2) = h1;
}

__global__ void ln_split_kernel(const float* __restrict__ x, __nv_bfloat16* __restrict__ y3,
                                const float* __restrict__ al, const float* __restrict__ be)
{
    int row = blockIdx.x;
    float4 v = ((const float4*)(x + (size_t)row * EMB))[threadIdx.x];
    float mean, inv;
    ln_stats(v, mean, inv, al);
    float bb = be[0];
    float o[4] = { (v.x - mean) * inv + bb, (v.y - mean) * inv + bb,
                   (v.z - mean) * inv + bb, (v.w - mean) * inv + bb };
    int col = threadIdx.x * 4;
    __nv_bfloat16* rowp = y3 + (size_t)row * K3E;
    #pragma unroll
    for (int p = 0; p < 2; p++) {
        float a0 = o[p*2], a1 = o[p*2+1];
        __nv_bfloat16 h0 = __float2bfloat16_rn(a0);
        __nv_bfloat16 h1 = __float2bfloat16_rn(a1);
        __nv_bfloat162 hh; hh.x = h0; hh.y = h1;
        __nv_bfloat162 ll;
        ll.x = __float2bfloat16_rn(a0 - __bfloat162float(h0));
        ll.y = __float2bfloat16_rn(a1 - __bfloat162float(h1));
        *(__nv_bfloat162*)(rowp + col + p*2)         = hh;
        *(__nv_bfloat162*)(rowp + EMB + col + p*2)   = ll;
        *(__nv_bfloat162*)(rowp + 2*EMB + col + p*2) = hh;
    }
}

// ---------------- weight transposes (vectorized: 32k x 128n tiles) ------------
__global__ void wt_plain_kernel(const float* __restrict__ W, __nv_bfloat16* __restrict__ WT,
                                int K, int N)
{
    __shared__ float t[32][132];
    int k0 = blockIdx.y * 32, n0 = blockIdx.x * 128;
    int tid = threadIdx.x;
    int lr = tid >> 5, lc = (tid & 31) * 4;
    #pragma unroll
    for (int i = 0; i < 4; i++) {
        float4 v = *(const float4*)&W[(size_t)(k0 + lr + 8*i) * N + n0 + lc];
        t[lr + 8*i][lc]     = v.x;
        t[lr + 8*i][lc + 1] = v.y;
        t[lr + 8*i][lc + 2] = v.z;
        t[lr + 8*i][lc + 3] = v.w;
    }
    __syncthreads();
    int n = tid >> 1, ks = (tid & 1) * 16;
    __nv_bfloat16* dst = WT + (size_t)(n0 + n) * K + k0 + ks;
    #pragma unroll
    for (int j = 0; j < 8; j++) {
        int k = ks + 2*j;
        *(__nv_bfloat162*)(dst + 2*j - ks + ks) =
            __floats2bfloat162_rn(t[k][n], t[k + 1][n]);
    }
}

__global__ void wt_split_kernel(const float* __restrict__ W, __nv_bfloat16* __restrict__ WT3,
                                int K, int N)
{
    __shared__ float t[32][132];
    int k0 = blockIdx.y * 32, n0 = blockIdx.x * 128;
    int tid = threadIdx.x;
    int lr = tid >> 5, lc = (tid & 31) * 4;
    #pragma unroll
    for (int i = 0; i < 4; i++) {
        float4 v = *(const float4*)&W[(size_t)(k0 + lr + 8*i) * N + n0 + lc];
        t[lr + 8*i][lc]     = v.x;
        t[lr + 8*i][lc + 1] = v.y;
        t[lr + 8*i][lc + 2] = v.z;
        t[lr + 8*i][lc + 3] = v.w;
    }
    __syncthreads();
    int n = tid >> 1, ks = (tid & 1) * 16;
    size_t rb = (size_t)(n0 + n) * (3 * (size_t)K) + k0 + ks;
    #pragma unroll
    for (int j = 0; j < 8; j++) {
        int k = ks + 2*j;
        float a0 = t[k][n], a1 = t[k + 1][n];
        __nv_bfloat16 h0 = __float2bfloat16_rn(a0);
        __nv_bfloat16 h1 = __float2bfloat16_rn(a1);
        __nv_bfloat162 hh; hh.x = h0; hh.y = h1;
        __nv_bfloat162 ll;
        ll.x = __float2bfloat16_rn(a0 - __bfloat162float(h0));
        ll.y = __float2bfloat16_rn(a1 - __bfloat162float(h1));
        *(__nv_bfloat162*)(WT3 + rb + 2*j)         = hh;
        *(__nv_bfloat162*)(WT3 + rb + K + 2*j)     = hh;
        *(__nv_bfloat162*)(WT3 + rb + 2*K + 2*j)   = ll;
    }
}

// ---------------- split-K reduce: out = res + bias + sum(parts) ---------------
template<int NP>
__global__ void reduce_kernel(const float* __restrict__ parts, const float* __restrict__ res,
                              const float* __restrict__ bias, float* __restrict__ out)
{
    int row = blockIdx.x, col = threadIdx.x * 4;
    size_t idx = (size_t)row * EMB + col;
    float4 a = *(const float4*)(res + idx);
    if (bias) {
        float4 bb = *(const float4*)(bias + col);
        a.x += bb.x; a.y += bb.y; a.z += bb.z; a.w += bb.w;
    }
    #pragma unroll
    for (int p = 0; p < NP; p++) {
        float4 pv = *(const float4*)(parts + (size_t)p * MROWS * EMB + idx);
        a.x += pv.x; a.y += pv.y; a.z += pv.z; a.w += pv.w;
    }
    *(float4*)(out + idx) = a;
}

// ---------------- bf16 mma.sync GEMM (256x128 CTA, 64x64 warp, BK=64) ---------
// MODE 0: fp32 out (+bias/res, +split-K via blockIdx.z). MODE 1: split-bf16 relu.
// MODE 2: plain bf16.
#define ASTR 144
#define A_STAGE (256 * ASTR)                 // 36864
#define B_STAGE (128 * ASTR)                 // 18432
#define STAGE_BYTES (A_STAGE + B_STAGE)      // 55296
#define GSM_TOTAL (3 * STAGE_BYTES)          // 165888

template<int MODE>
__global__ void __launch_bounds__(256, 1)
gemm_mma(const __nv_bfloat16* __restrict__ A3, const __nv_bfloat16* __restrict__ BT3,
         float* __restrict__ C, __nv_bfloat16* __restrict__ Cs,
         const float* __restrict__ bias, const float* __restrict__ res,
         int M, int N, int K3, int ksplit)
{
    extern __shared__ char smem[];
    uint32_t sb = smem_u32(smem);
    int tid = threadIdx.x, wid = tid >> 5, lane = tid & 31;
    int bm = blockIdx.y, bn = blockIdx.x;
    int warp_m = wid >> 1, warp_n = wid & 1;    // 4 x 2

    const int Kc = K3 / ksplit;
    const int kbase = blockIdx.z * Kc;
    const int nk = Kc / 64;

    auto load_stage = [&](int k0, int st) {
        uint32_t base = sb + st * STAGE_BYTES;
        #pragma unroll
        for (int i = 0; i < 8; i++) {            // A: 2048 chunks
            int c = tid + i * 256;
            int row = c >> 3, kc = c & 7;
            cp16(base + row * ASTR + kc * 16,
                 A3 + (size_t)(bm * 256 + row) * K3 + k0 + kc * 8);
        }
        #pragma unroll
        for (int i = 0; i < 4; i++) {            // B: 1024 chunks
            int c = tid + i * 256;
            int row = c >> 3, kc = c & 7;
            cp16(base + A_STAGE + row * ASTR + kc * 16,
                 BT3 + (size_t)(bn * 128 + row) * K3 + k0 + kc * 8);
        }
        cp_commit();
    };

    load_stage(kbase, 0);
    load_stage(kbase + 64, 1);

    float acc[4][8][4];
    #pragma unroll
    for (int i = 0; i < 4; i++)
        #pragma unroll
        for (int j = 0; j < 8; j++)
            #pragma unroll
            for (int r = 0; r < 4; r++) acc[i][j][r] = 0.f;

    uint32_t aBase = (uint32_t)((warp_m * 64 + (lane & 15)) * ASTR + (lane >> 4) * 16);
    uint32_t bBase = (uint32_t)(A_STAGE +
                     (warp_n * 64 + ((lane >> 4) << 3) + (lane & 7)) * ASTR +
                     ((lane >> 3) & 1) * 16);

    for (int kt = 0; kt < nk; kt++) {
        cp_wait<1>();
        __syncthreads();
        int nxt = kt + 2;
        if (nxt < nk) load_stage(kbase + nxt * 64, nxt % 3);

        uint32_t stb = sb + (kt % 3) * STAGE_BYTES;
        #pragma unroll
        for (int s = 0; s < 4; s++) {
            uint32_t afr[4][4], bfr[4][4];
            #pragma unroll
            for (int i = 0; i < 4; i++)
                ldsm_x4(afr[i], stb + aBase + i * 16 * ASTR + s * 32);
            #pragma unroll
            for (int ng = 0; ng < 4; ng++)
                ldsm_x4(bfr[ng], stb + bBase + ng * 16 * ASTR + s * 32);
            #pragma unroll
            for (int i = 0; i < 4; i++) {
                #pragma unroll
                for (int j = 0; j < 8; j++)
                    mma16816(acc[i][j], afr[i], &bfr[j >> 1][(j & 1) * 2]);
            }
        }
        __syncthreads();
    }

    int g = lane >> 2, tig = lane & 3;
    float* Cz = C + (size_t)blockIdx.z * M * N;   // split-K partial target (z=0 if no split)
    #pragma unroll
    for (int i = 0; i < 4; i++) {
        #pragma unroll
        for (int half = 0; half < 2; half++) {
            int row = bm * 256 + warp_m * 64 + i * 16 + g + half * 8;
            #pragma unroll
            for (int j = 0; j < 8; j++) {
                int col = bn * 128 + warp_n * 64 + j * 8 + tig * 2;
                float v0 = acc[i][j][half * 2];
                float v1 = acc[i][j][half * 2 + 1];
                if (MODE == 1) {
                    v0 = fmaxf(v0 + bias[col], 0.f);
                    v1 = fmaxf(v1 + bias[col + 1], 0.f);
                    __nv_bfloat16 h0 = __float2bfloat16_rn(v0);
                    __nv_bfloat16 h1 = __float2bfloat16_rn(v1);
                    __nv_bfloat162 hh; hh.x = h0; hh.y = h1;
                    __nv_bfloat162 ll;
                    ll.x = __float2bfloat16_rn(v0 - __bfloat162float(h0));
                    ll.y = __float2bfloat16_rn(v1 - __bfloat162float(h1));
                    size_t rb = (size_t)row * (3 * (size_t)N);
                    *(__nv_bfloat162*)(Cs + rb + col)                 = hh;
                    *(__nv_bfloat162*)(Cs + rb + N + col)             = ll;
                    *(__nv_bfloat162*)(Cs + rb + 2 * (size_t)N + col) = hh;
                } else if (MODE == 2) {
                    __nv_bfloat162 hh;
                    hh.x = __float2bfloat16_rn(v0);
                    hh.y = __float2bfloat16_rn(v1);
                    *(__nv_bfloat162*)(Cs + (size_t)row * N + col) = hh;
                } else {
                    if (bias) { v0 += bias[col]; v1 += bias[col + 1]; }
                    size_t rb = (size_t)row * N;
                    if (res) {
                        float2 rr = *(const float2*)(res + rb + col);
                        v0 += rr.x; v1 += rr.y;
                    }
                    float2 o; o.x = v0; o.y = v1;
                    *(float2*)(Cz + rb + col) = o;
                }
            }
        }
    }
}

// ---------------- Tensor-core flash attention (unchanged from R7) --------------
#define TSTR 144
#define AQOFF 0
#define AKOFF 18432
#define AVOFF 36864
#define AMOFF 55296
#define ATT_SMEM 63488

__global__ void __launch_bounds__(256, 1)
attn_tc(const __nv_bfloat16* __restrict__ qkv, const int* __restrict__ mask,
        __nv_bfloat16* __restrict__ ao)
{
    extern __shared__ char smem[];
    uint32_t sb = smem_u32(smem);
    int tid = threadIdx.x, wid = tid >> 5, lane = tid & 31;
    int g = lane >> 2, tig = lane & 3;
    int bh = blockIdx.y;
    int b = bh >> 4, hd = bh & 15;
    int q0 = blockIdx.x * 128;

    const __nv_bfloat16* qg = qkv + (size_t)(b * SEQ) * QKVW + hd * DKH;

    #pragma unroll
    for (int i = 0; i < 4; i++) {
        int c = tid + i * 256;
        int row = c >> 3, kc = c & 7;
        cp16(sb + AQOFF + row * TSTR + kc * 16,
             qg + (size_t)(q0 + row) * QKVW + kc * 8);
    }
    #pragma unroll
    for (int i = 0; i < 2; i++) {
        int c = tid + i * 256;
        cp16(sb + AMOFF + c * 16, mask + (size_t)b * SEQ + c * 4);
    }
    auto load_kv = [&](int jt, int buf) {
        #pragma unroll
        for (int i = 0; i < 2; i++) {
            int c = tid + i * 256;
            int row = c >> 3, kc = c & 7;
            cp16(sb + AKOFF + buf * 9216 + row * TSTR + kc * 16,
                 qg + (size_t)(jt * 64 + row) * QKVW + EMB + kc * 8);
            cp16(sb + AVOFF + buf * 9216 + row * TSTR + kc * 16,
                 qg + (size_t)(jt * 64 + row) * QKVW + 2 * EMB + kc * 8);
        }
    };
    load_kv(0, 0);
    cp_commit();

    uint32_t qfr[4][4];
    float ofr[8][4];
    #pragma unroll
    for (int j = 0; j < 8; j++)
        #pragma unroll
        for (int r = 0; r < 4; r++) ofr[j][r] = 0.f;
    float m0 = -3.0e38f, m1 = -3.0e38f, l0 = 0.f, l1 = 0.f;

    uint32_t aQ = (uint32_t)(AQOFF + (wid * 16 + (lane & 15)) * TSTR + (lane >> 4) * 16);
    uint32_t bK = (uint32_t)((((lane >> 4) << 3) + (lane & 7)) * TSTR + ((lane >> 3) & 1) * 16);
    uint32_t bV = (uint32_t)((((lane >> 3) & 1) * 8 + (lane & 7)) * TSTR + (lane >> 4) * 16);

    const int NJT = SEQ / 64;
    for (int jt = 0; jt < NJT; jt++) {
        cp_wait<0>();
        __syncthreads();
        if (jt == 0) {
            #pragma unroll
            for (int ks = 0; ks < 4; ks++) ldsm_x4(qfr[ks], sb + aQ + ks * 32);
        }
        if (jt + 1 < NJT) { load_kv(jt + 1, (jt + 1) & 1); cp_commit(); }

        uint32_t kb = sb + AKOFF + (jt & 1) * 9216;
        uint32_t vb = sb + AVOFF + (jt & 1) * 9216;

        float sfr[8][4];
        #pragma unroll
        for (int j = 0; j < 8; j++)
            #pragma unroll
            for (int r = 0; r < 4; r++) sfr[j][r] = 0.f;
        #pragma unroll
        for (int ks = 0; ks < 4; ks++) {
            uint32_t bfr[4][4];
            #pragma unroll
            for (int ng = 0; ng < 4; ng++)
                ldsm_x4(bfr[ng], kb + bK + ng * 16 * TSTR + ks * 32);
            #pragma unroll
            for (int j = 0; j < 8; j++)
                mma16816(sfr[j], qfr[ks], &bfr[j >> 1][(j & 1) * 2]);
        }

        #pragma unroll
        for (int j = 0; j < 8; j++) {
            int2 mv = *(const int2*)(smem + AMOFF + (jt * 64 + j * 8 + tig * 2) * 4);
            sfr[j][0] = (mv.x == 0) ? -1e30f : sfr[j][0] * 0.125f;
            sfr[j][1] = (mv.y == 0) ? -1e30f : sfr[j][1] * 0.125f;
            sfr[j][2] = (mv.x == 0) ? -1e30f : sfr[j][2] * 0.125f;
            sfr[j][3] = (mv.y == 0) ? -1e30f : sfr[j][3] * 0.125f;
        }

        float mx0 = -3.0e38f, mx1 = -3.0e38f;
        #pragma unroll
        for (int j = 0; j < 8; j++) {
            mx0 = fmaxf(mx0, fmaxf(sfr[j][0], sfr[j][1]));
            mx1 = fmaxf(mx1, fmaxf(sfr[j][2], sfr[j][3]));
        }
        #pragma unroll
        for (int off = 1; off < 4; off <<= 1) {
            mx0 = fmaxf(mx0, __shfl_xor_sync(0xffffffffu, mx0, off));
            mx1 = fmaxf(mx1, __shfl_xor_sync(0xffffffffu, mx1, off));
        }
        float mn0 = fmaxf(m0, mx0), mn1 = fmaxf(m1, mx1);
        float al0 = __expf(m0 - mn0), al1 = __expf(m1 - mn1);
        float ls0 = 0.f, ls1 = 0.f;
        #pragma unroll
        for (int j = 0; j < 8; j++) {
            sfr[j][0] = __expf(sfr[j][0] - mn0);
            sfr[j][1] = __expf(sfr[j][1] - mn0);
            sfr[j][2] = __expf(sfr[j][2] - mn1);
            sfr[j][3] = __expf(sfr[j][3] - mn1);
            ls0 += sfr[j][0] + sfr[j][1];
            ls1 += sfr[j][2] + sfr[j][3];
        }
        #pragma unroll
        for (int off = 1; off < 4; off <<= 1) {
            ls0 += __shfl_xor_sync(0xffffffffu, ls0, off);
            ls1 += __shfl_xor_sync(0xffffffffu, ls1, off);
        }
        l0 = l0 * al0 + ls0; l1 = l1 * al1 + ls1;
        m0 = mn0; m1 = mn1;
        #pragma unroll
        for (int j = 0; j < 8; j++) {
            ofr[j][0] *= al0; ofr[j][1] *= al0;
            ofr[j][2] *= al1; ofr[j][3] *= al1;
        }

        #pragma unroll
        for (int ks = 0; ks < 4; ks++) {
            uint32_t pa[4];
            pa[0] = packbf(sfr[2*ks][0],   sfr[2*ks][1]);
            pa[1] = packbf(sfr[2*ks][2],   sfr[2*ks][3]);
            pa[2] = packbf(sfr[2*ks+1][0], sfr[2*ks+1][1]);
            pa[3] = packbf(sfr[2*ks+1][2], sfr[2*ks+1][3]);
            #pragma unroll
            for (int jp = 0; jp < 4; jp++) {
                uint32_t vfr[4];
                ldsm_x4t(vfr, vb + bV + ks * 16 * TSTR + jp * 32);
                mma16816(ofr[2*jp],     pa, &vfr[0]);
                mma16816(ofr[2*jp + 1], pa, &vfr[2]);
            }
        }
        __syncthreads();
    }

    float inv0 = 1.f / l0, inv1 = 1.f / l1;
    int r0 = b * SEQ + q0 + wid * 16 + g;
    #pragma unroll
    for (int half = 0; half < 2; half++) {
        int grow = r0 + half * 8;
        float inv = half ? inv1 : inv0;
        __nv_bfloat16* base = ao + (size_t)grow * EMB + hd * DKH;
        #pragma unroll
        for (int j = 0; j < 8; j++) {
            int col = j * 8 + tig * 2;
            __nv_bfloat162 hh = __floats2bfloat162_rn(ofr[j][half * 2] * inv,
                                                      ofr[j][half * 2 + 1] * inv);
            *(__nv_bfloat162*)(base + col) = hh;
        }
    }
}

// ---------------- launch ------------------------------------------------------
extern "C" void kernel_launch(void* const* d_in, const int* in_sizes, int n_in,
                              void* d_out, int out_size)
{
    const float* x    = (const float*)d_in[0];
    const int*   mask = (const int*)  d_in[1];
    const float* wq   = (const float*)d_in[2];
    const float* wk   = (const float*)d_in[3];
    const float* wv   = (const float*)d_in[4];
    const float* wo   = (const float*)d_in[5];
    const float* ff1w = (const float*)d_in[6];
    const float* ff1b = (const float*)d_in[7];
    const float* ff2w = (const float*)d_in[8];
    const float* ff2b = (const float*)d_in[9];
    const float* ln1a = (const float*)d_in[10];
    const float* ln1b = (const float*)d_in[11];
    const float* ln2a = (const float*)d_in[12];
    const float* ln2b = (const float*)d_in[13];
    float* out = (float*)d_out;

    __nv_bfloat16 *ab, *a3a, *a3c, *w3, *wp, *qkvh;
    float *h, *part;
    cudaGetSymbolAddress((void**)&ab,   g_ab);
    cudaGetSymbolAddress((void**)&a3a,  g_a3a);
    cudaGetSymbolAddress((void**)&a3c,  g_a3c);
    cudaGetSymbolAddress((void**)&w3,   g_w3);
    cudaGetSymbolAddress((void**)&wp,   g_wp);
    cudaGetSymbolAddress((void**)&qkvh, g_qkvh);
    cudaGetSymbolAddress((void**)&h,    g_h);
    cudaGetSymbolAddress((void**)&part, g_part);
    __nv_bfloat16* wpo = wp + (size_t)(3 * EMB) * EMB;   // wo slot

    cudaFuncSetAttribute(attn_tc, cudaFuncAttributeMaxDynamicSharedMemorySize, ATT_SMEM);
    cudaFuncSetAttribute(gemm_mma<0>, cudaFuncAttributeMaxDynamicSharedMemorySize, GSM_TOTAL);
    cudaFuncSetAttribute(gemm_mma<1>, cudaFuncAttributeMaxDynamicSharedMemorySize, GSM_TOTAL);
    cudaFuncSetAttribute(gemm_mma<2>, cudaFuncAttributeMaxDynamicSharedMemorySize, GSM_TOTAL);

    dim3 gQKV(QKVW / 128, MROWS / 256, 1);   // (24, 16)
    dim3 gWO (EMB / 128,  MROWS / 256, 2);   // (8, 16, 2) split-K
    dim3 gFF1(HID / 128,  MROWS / 256, 1);   // (32, 16)
    dim3 gFF2(EMB / 128,  MROWS / 256, 3);   // (8, 16, 3) split-K

    // 1) ln1(x) -> ab (plain bf16)
    ln_plain_kernel<<<MROWS, 256>>>(x, ab, ln1a, ln1b);
    // 2-5) plain transposed wq|wk|wv|wo
    wt_plain_kernel<<<dim3(EMB/128, EMB/32), 256>>>(wq, wp, EMB, EMB);
    wt_plain_kernel<<<dim3(EMB/128, EMB/32), 256>>>(wk, wp + (size_t)EMB * EMB, EMB, EMB);
    wt_plain_kernel<<<dim3(EMB/128, EMB/32), 256>>>(wv, wp + (size_t)(2 * EMB) * EMB, EMB, EMB);
    wt_plain_kernel<<<dim3(EMB/128, EMB/32), 256>>>(wo, wpo, EMB, EMB);
    // 6) fused QKV projection (plain bf16, K=1024)
    gemm_mma<2><<<gQKV, 256, GSM_TOTAL>>>(ab, wp, nullptr, qkvh, nullptr, nullptr, MROWS, QKVW, EMB, 1);
    // 7) attention -> ab (plain bf16, reuse)
    attn_tc<<<dim3(SEQ / 128, BATCH * NH), 256, ATT_SMEM>>>(qkvh, mask, ab);
    // 8) wo partials (split-K=2) -> part ; 9) h = x + p0 + p1
    gemm_mma<0><<<gWO, 256, GSM_TOTAL>>>(ab, wpo, part, nullptr, nullptr, nullptr, MROWS, EMB, EMB, 2);
    reduce_kernel<2><<<MROWS, 256>>>(part, x, nullptr, h);
    // 10) ln2(h) -> a3a (split)
    ln_split_kernel<<<MROWS, 256>>>(h, a3a, ln2a, ln2b);
    // 11-12) ff1 (split weights, K=3072)
    wt_split_kernel<<<dim3(HID/128, EMB/32), 256>>>(ff1w, w3, EMB, HID);
    gemm_mma<1><<<gFF1, 256, GSM_TOTAL>>>(a3a, w3, nullptr, a3c, ff1b, nullptr, MROWS, HID, K3E, 1);
    // 13-14) ff2 partials (split weights, K=12288, split-K=3); 15) out = h + b + parts
    wt_split_kernel<<<dim3(EMB/128, HID/32), 256>>>(ff2w, w3, HID, EMB);
    gemm_mma<0><<<gFF2, 256, GSM_TOTAL>>>(a3c, w3, part, nullptr, nullptr, nullptr, MROWS, EMB, K3H, 3);
    reduce_kernel<3><<<MROWS, 256>>>(part, h, ff2b, out);
}

// round 10
// speedup vs baseline: 4.8953x; 1.3189x over previous
#include <cuda_runtime.h>
#include <cuda_bf16.h>
#include <math.h>
#include <stdint.h>

#define EMB 1024
#define HID 4096
#define NH 16
#define DKH 64
#define BATCH 2
#define SEQ 2048
#define MROWS (BATCH * SEQ)     // 4096
#define QKVW (3 * EMB)

// ---------------- scratch (__device__ globals, allocation-free) ---------------
__device__ __nv_bfloat16 g_ab  [MROWS * EMB];            // ln1 out, later attn out
__device__ float         g_xn2 [MROWS * EMB];            // ln2 out (tf32)
__device__ float         g_ffa [(size_t)MROWS * HID];    // relu(ff1) (tf32)
__device__ float         g_wt32[(size_t)HID * EMB];      // tf32 transposed ff1/ff2
__device__ __nv_bfloat16 g_wp  [(size_t)(4 * EMB) * EMB];// plain transposed qkv|wo
__device__ __nv_bfloat16 g_qkvh[(size_t)MROWS * QKVW];   // packed q|k|v bf16
__device__ float g_h   [MROWS * EMB];
__device__ float g_part[(size_t)4 * MROWS * EMB];        // split-K partials

// ---------------- PTX helpers (base ISA only) ----------------------------------
__device__ __forceinline__ uint32_t smem_u32(const void* p) {
    return (uint32_t)__cvta_generic_to_shared(p);
}
__device__ __forceinline__ void cp16(uint32_t dst, const void* src) {
    asm volatile("cp.async.cg.shared.global [%0], [%1], 16;" :: "r"(dst), "l"(src));
}
__device__ __forceinline__ void cp_commit() {
    asm volatile("cp.async.commit_group;");
}
template<int N> __device__ __forceinline__ void cp_wait() {
    asm volatile("cp.async.wait_group %0;" :: "n"(N));
}
__device__ __forceinline__ void ldsm_x4(uint32_t* r, uint32_t addr) {
    asm volatile("ldmatrix.sync.aligned.m8n8.x4.shared.b16 {%0,%1,%2,%3}, [%4];"
                 : "=r"(r[0]), "=r"(r[1]), "=r"(r[2]), "=r"(r[3]) : "r"(addr));
}
__device__ __forceinline__ void ldsm_x4t(uint32_t* r, uint32_t addr) {
    asm volatile("ldmatrix.sync.aligned.m8n8.x4.trans.shared.b16 {%0,%1,%2,%3}, [%4];"
                 : "=r"(r[0]), "=r"(r[1]), "=r"(r[2]), "=r"(r[3]) : "r"(addr));
}
__device__ __forceinline__ void mma16816(float* d, const uint32_t* a, const uint32_t* b) {
    asm volatile(
        "mma.sync.aligned.m16n8k16.row.col.f32.bf16.bf16.f32 "
        "{%0,%1,%2,%3}, {%4,%5,%6,%7}, {%8,%9}, {%0,%1,%2,%3};"
        : "+f"(d[0]), "+f"(d[1]), "+f"(d[2]), "+f"(d[3])
        : "r"(a[0]), "r"(a[1]), "r"(a[2]), "r"(a[3]), "r"(b[0]), "r"(b[1]));
}
__device__ __forceinline__ void mma1688tf(float* d, const uint32_t* a, const uint32_t* b) {
    asm volatile(
        "mma.sync.aligned.m16n8k8.row.col.f32.tf32.tf32.f32 "
        "{%0,%1,%2,%3}, {%4,%5,%6,%7}, {%8,%9}, {%0,%1,%2,%3};"
        : "+f"(d[0]), "+f"(d[1]), "+f"(d[2]), "+f"(d[3])
        : "r"(a[0]), "r"(a[1]), "r"(a[2]), "r"(a[3]), "r"(b[0]), "r"(b[1]));
}
__device__ __forceinline__ uint32_t packbf(float a, float b) {
    __nv_bfloat162 h = __floats2bfloat162_rn(a, b);
    return *(uint32_t*)&h;
}
__device__ __forceinline__ float tf32r(float f) {
    uint32_t u;
    asm("cvt.rna.tf32.f32 %0, %1;" : "=r"(u) : "f"(f));
    return __uint_as_float(u);
}

// ---------------- LayerNorm ----------------------------------------------------
__device__ __forceinline__ void ln_stats(float4 v, float& mean, float& inv,
                                         const float* al) {
    float s  = v.x + v.y + v.z + v.w;
    float ss = v.x*v.x + v.y*v.y + v.z*v.z + v.w*v.w;
    #pragma unroll
    for (int off = 16; off; off >>= 1) {
        s  += __shfl_xor_sync(0xffffffffu, s,  off);
        ss += __shfl_xor_sync(0xffffffffu, ss, off);
    }
    __shared__ float rs[8], rss[8];
    int warp = threadIdx.x >> 5, lane = threadIdx.x & 31;
    if (lane == 0) { rs[warp] = s; rss[warp] = ss; }
    __syncthreads();
    if (warp == 0) {
        s  = (lane < 8) ? rs[lane]  : 0.f;
        ss = (lane < 8) ? rss[lane] : 0.f;
        #pragma unroll
        for (int off = 16; off; off >>= 1) {
            s  += __shfl_xor_sync(0xffffffffu, s,  off);
            ss += __shfl_xor_sync(0xffffffffu, ss, off);
        }
        if (lane == 0) { rs[0] = s; rss[0] = ss; }
    }
    __syncthreads();
    s = rs[0]; ss = rss[0];
    mean = s * (1.0f / EMB);
    float var = fmaxf(ss - (float)EMB * mean * mean, 0.f) * (1.0f / (EMB - 1));
    inv = al[0] / (sqrtf(var) + 1e-6f);
}

__global__ void ln_plain_kernel(const float* __restrict__ x, __nv_bfloat16* __restrict__ y,
                                const float* __restrict__ al, const float* __restrict__ be)
{
    int row = blockIdx.x;
    float4 v = ((const float4*)(x + (size_t)row * EMB))[threadIdx.x];
    float mean, inv;
    ln_stats(v, mean, inv, al);
    float bb = be[0];
    int col = threadIdx.x * 4;
    __nv_bfloat16* rowp = y + (size_t)row * EMB;
    __nv_bfloat162 h0 = __floats2bfloat162_rn((v.x - mean) * inv + bb, (v.y - mean) * inv + bb);
    __nv_bfloat162 h1 = __floats2bfloat162_rn((v.z - mean) * inv + bb, (v.w - mean) * inv + bb);
    *(__nv_bfloat162*)(rowp + col)     = h0;
    *(__nv_bfloat162*)(rowp + col + 2) = h1;
}

__global__ void ln_tf32_kernel(const float* __restrict__ x, float* __restrict__ y,
                               const float* __restrict__ al, const float* __restrict__ be)
{
    int row = blockIdx.x;
    float4 v = ((const float4*)(x + (size_t)row * EMB))[threadIdx.x];
    float mean, inv;
    ln_stats(v, mean, inv, al);
    float bb = be[0];
    float4 o;
    o.x = tf32r((v.x - mean) * inv + bb);
    o.y = tf32r((v.y - mean) * inv + bb);
    o.z = tf32r((v.z - mean) * inv + bb);
    o.w = tf32r((v.w - mean) * inv + bb);
    ((float4*)(y + (size_t)row * EMB))[threadIdx.x] = o;
}

// ---------------- weight transposes (vectorized: 32k x 128n tiles) ------------
__global__ void wt_plain_kernel(const float* __restrict__ W, __nv_bfloat16* __restrict__ WT,
                                int K, int N)
{
    __shared__ float t[32][132];
    int k0 = blockIdx.y * 32, n0 = blockIdx.x * 128;
    int tid = threadIdx.x;
    int lr = tid >> 5, lc = (tid & 31) * 4;
    #pragma unroll
    for (int i = 0; i < 4; i++) {
        float4 v = *(const float4*)&W[(size_t)(k0 + lr + 8*i) * N + n0 + lc];
        t[lr + 8*i][lc]     = v.x;
        t[lr + 8*i][lc + 1] = v.y;
        t[lr + 8*i][lc + 2] = v.z;
        t[lr + 8*i][lc + 3] = v.w;
    }
    __syncthreads();
    int n = tid >> 1, ks = (tid & 1) * 16;
    __nv_bfloat16* dst = WT + (size_t)(n0 + n) * K + k0 + ks;
    #pragma unroll
    for (int j = 0; j < 8; j++) {
        int k = ks + 2*j;
        *(__nv_bfloat162*)(dst + 2*j) = __floats2bfloat162_rn(t[k][n], t[k + 1][n]);
    }
}

__global__ void wt_tf32_kernel(const float* __restrict__ W, float* __restrict__ WT,
                               int K, int N)
{
    __shared__ float t[32][132];
    int k0 = blockIdx.y * 32, n0 = blockIdx.x * 128;
    int tid = threadIdx.x;
    int lr = tid >> 5, lc = (tid & 31) * 4;
    #pragma unroll
    for (int i = 0; i < 4; i++) {
        float4 v = *(const float4*)&W[(size_t)(k0 + lr + 8*i) * N + n0 + lc];
        t[lr + 8*i][lc]     = v.x;
        t[lr + 8*i][lc + 1] = v.y;
        t[lr + 8*i][lc + 2] = v.z;
        t[lr + 8*i][lc + 3] = v.w;
    }
    __syncthreads();
    int n = tid >> 1, ks = (tid & 1) * 16;
    float* dst = WT + (size_t)(n0 + n) * K + k0 + ks;
    #pragma unroll
    for (int j = 0; j < 4; j++) {
        int k = ks + 4*j;
        float4 o;
        o.x = tf32r(t[k][n]);     o.y = tf32r(t[k + 1][n]);
        o.z = tf32r(t[k + 2][n]); o.w = tf32r(t[k + 3][n]);
        *(float4*)(dst + 4*j) = o;
    }
}

// ---------------- split-K reduce: out = res + bias + sum(parts) ---------------
template<int NP>
__global__ void reduce_kernel(const float* __restrict__ parts, const float* __restrict__ res,
                              const float* __restrict__ bias, float* __restrict__ out)
{
    int row = blockIdx.x, col = threadIdx.x * 4;
    size_t idx = (size_t)row * EMB + col;
    float4 a = *(const float4*)(res + idx);
    if (bias) {
        float4 bb = *(const float4*)(bias + col);
        a.x += bb.x; a.y += bb.y; a.z += bb.z; a.w += bb.w;
    }
    #pragma unroll
    for (int p = 0; p < NP; p++) {
        float4 pv = *(const float4*)(parts + (size_t)p * MROWS * EMB + idx);
        a.x += pv.x; a.y += pv.y; a.z += pv.z; a.w += pv.w;
    }
    *(float4*)(out + idx) = a;
}

// ---------------- bf16 mma.sync GEMM (256x128 CTA, 64x64 warp, BK=64) ---------
// MODE 0: fp32 out (+bias/res, split-K via blockIdx.z). MODE 2: plain bf16 out.
#define ASTR 144
#define A_STAGE (256 * ASTR)
#define B_STAGE (128 * ASTR)
#define STAGE_BYTES (A_STAGE + B_STAGE)      // 55296
#define GSM_TOTAL (3 * STAGE_BYTES)          // 165888

template<int MODE>
__global__ void __launch_bounds__(256, 1)
gemm_mma(const __nv_bfloat16* __restrict__ A3, const __nv_bfloat16* __restrict__ BT3,
         float* __restrict__ C, __nv_bfloat16* __restrict__ Cs,
         const float* __restrict__ bias, const float* __restrict__ res,
         int M, int N, int K3, int ksplit)
{
    extern __shared__ char smem[];
    uint32_t sb = smem_u32(smem);
    int tid = threadIdx.x, wid = tid >> 5, lane = tid & 31;
    int bm = blockIdx.y, bn = blockIdx.x;
    int warp_m = wid >> 1, warp_n = wid & 1;

    const int Kc = K3 / ksplit;
    const int kbase = blockIdx.z * Kc;
    const int nk = Kc / 64;

    auto load_stage = [&](int k0, int st) {
        uint32_t base = sb + st * STAGE_BYTES;
        #pragma unroll
        for (int i = 0; i < 8; i++) {
            int c = tid + i * 256;
            int row = c >> 3, kc = c & 7;
            cp16(base + row * ASTR + kc * 16,
                 A3 + (size_t)(bm * 256 + row) * K3 + k0 + kc * 8);
        }
        #pragma unroll
        for (int i = 0; i < 4; i++) {
            int c = tid + i * 256;
            int row = c >> 3, kc = c & 7;
            cp16(base + A_STAGE + row * ASTR + kc * 16,
                 BT3 + (size_t)(bn * 128 + row) * K3 + k0 + kc * 8);
        }
        cp_commit();
    };

    load_stage(kbase, 0);
    load_stage(kbase + 64, 1);

    float acc[4][8][4];
    #pragma unroll
    for (int i = 0; i < 4; i++)
        #pragma unroll
        for (int j = 0; j < 8; j++)
            #pragma unroll
            for (int r = 0; r < 4; r++) acc[i][j][r] = 0.f;

    uint32_t aBase = (uint32_t)((warp_m * 64 + (lane & 15)) * ASTR + (lane >> 4) * 16);
    uint32_t bBase = (uint32_t)(A_STAGE +
                     (warp_n * 64 + ((lane >> 4) << 3) + (lane & 7)) * ASTR +
                     ((lane >> 3) & 1) * 16);

    for (int kt = 0; kt < nk; kt++) {
        cp_wait<1>();
        __syncthreads();
        int nxt = kt + 2;
        if (nxt < nk) load_stage(kbase + nxt * 64, nxt % 3);

        uint32_t stb = sb + (kt % 3) * STAGE_BYTES;
        #pragma unroll
        for (int s = 0; s < 4; s++) {
            uint32_t afr[4][4], bfr[4][4];
            #pragma unroll
            for (int i = 0; i < 4; i++)
                ldsm_x4(afr[i], stb + aBase + i * 16 * ASTR + s * 32);
            #pragma unroll
            for (int ng = 0; ng < 4; ng++)
                ldsm_x4(bfr[ng], stb + bBase + ng * 16 * ASTR + s * 32);
            #pragma unroll
            for (int i = 0; i < 4; i++) {
                #pragma unroll
                for (int j = 0; j < 8; j++)
                    mma16816(acc[i][j], afr[i], &bfr[j >> 1][(j & 1) * 2]);
            }
        }
        __syncthreads();
    }

    int g = lane >> 2, tig = lane & 3;
    float* Cz = (MODE == 0) ? C + (size_t)blockIdx.z * M * N : C;
    #pragma unroll
    for (int i = 0; i < 4; i++) {
        #pragma unroll
        for (int half = 0; half < 2; half++) {
            int row = bm * 256 + warp_m * 64 + i * 16 + g + half * 8;
            #pragma unroll
            for (int j = 0; j < 8; j++) {
                int col = bn * 128 + warp_n * 64 + j * 8 + tig * 2;
                float v0 = acc[i][j][half * 2];
                float v1 = acc[i][j][half * 2 + 1];
                if (MODE == 2) {
                    __nv_bfloat162 hh;
                    hh.x = __float2bfloat16_rn(v0);
                    hh.y = __float2bfloat16_rn(v1);
                    *(__nv_bfloat162*)(Cs + (size_t)row * N + col) = hh;
                } else {
                    if (bias) { v0 += bias[col]; v1 += bias[col + 1]; }
                    size_t rb = (size_t)row * N;
                    if (res) {
                        float2 rr = *(const float2*)(res + rb + col);
                        v0 += rr.x; v1 += rr.y;
                    }
                    float2 o; o.x = v0; o.y = v1;
                    *(float2*)(Cz + rb + col) = o;
                }
            }
        }
    }
}

// ---------------- tf32 mma.sync GEMM (256x128 CTA, 64x64 warp, BK=32) ---------
// MODE 1: relu(x+bias) -> tf32 fp32. MODE 0: fp32 partials (split-K).
#define FSTR 36                               // floats per smem row (32 + 4 pad)
#define FA_STAGE (256 * FSTR * 4)             // 36864
#define FB_STAGE (128 * FSTR * 4)             // 18432
#define FSTAGE_BYTES (FA_STAGE + FB_STAGE)    // 55296
#define FGSM_TOTAL (3 * FSTAGE_BYTES)         // 165888

template<int MODE>
__global__ void __launch_bounds__(256, 1)
gemm_tf32(const float* __restrict__ A, const float* __restrict__ BT,
          float* __restrict__ C, const float* __restrict__ bias,
          int M, int N, int K, int ksplit)
{
    extern __shared__ char smem[];
    uint32_t sb = smem_u32(smem);
    int tid = threadIdx.x, wid = tid >> 5, lane = tid & 31;
    int g = lane >> 2, tig = lane & 3;
    int bm = blockIdx.y, bn = blockIdx.x;
    int warp_m = wid >> 1, warp_n = wid & 1;

    const int Kc = K / ksplit;
    const int kbase = blockIdx.z * Kc;
    const int nk = Kc / 32;

    auto load_stage = [&](int k0, int st) {
        uint32_t base = sb + st * FSTAGE_BYTES;
        #pragma unroll
        for (int i = 0; i < 8; i++) {            // A: 2048 chunks of 4 floats
            int c = tid + i * 256;
            int row = c >> 3, kc = c & 7;
            cp16(base + row * (FSTR * 4) + kc * 16,
                 A + (size_t)(bm * 256 + row) * K + k0 + kc * 4);
        }
        #pragma unroll
        for (int i = 0; i < 4; i++) {            // B: 1024 chunks
            int c = tid + i * 256;
            int row = c >> 3, kc = c & 7;
            cp16(base + FA_STAGE + row * (FSTR * 4) + kc * 16,
                 BT + (size_t)(bn * 128 + row) * K + k0 + kc * 4);
        }
        cp_commit();
    };

    load_stage(kbase, 0);
    load_stage(kbase + 32, 1);

    float acc[4][8][4];
    #pragma unroll
    for (int i = 0; i < 4; i++)
        #pragma unroll
        for (int j = 0; j < 8; j++)
            #pragma unroll
            for (int r = 0; r < 4; r++) acc[i][j][r] = 0.f;

    for (int kt = 0; kt < nk; kt++) {
        cp_wait<1>();
        __syncthreads();
        int nxt = kt + 2;
        if (nxt < nk) load_stage(kbase + nxt * 32, nxt % 3);

        const char* stb = smem + (kt % 3) * FSTAGE_BYTES;
        #pragma unroll
        for (int s = 0; s < 4; s++) {            // 4 x k8
            uint32_t afr[4][4], bfr[8][2];
            #pragma unroll
            for (int i = 0; i < 4; i++) {
                const float* ap = (const float*)(stb +
                    ((warp_m * 64 + i * 16 + g) * FSTR + s * 8 + tig) * 4);
                afr[i][0] = __float_as_uint(ap[0]);
                afr[i][1] = __float_as_uint(ap[8 * FSTR]);
                afr[i][2] = __float_as_uint(ap[4]);
                afr[i][3] = __float_as_uint(ap[8 * FSTR + 4]);
            }
            #pragma unroll
            for (int j = 0; j < 8; j++) {
                const float* bp = (const float*)(stb + FA_STAGE +
                    ((warp_n * 64 + j * 8 + g) * FSTR + s * 8 + tig) * 4);
                bfr[j][0] = __float_as_uint(bp[0]);
                bfr[j][1] = __float_as_uint(bp[4]);
            }
            #pragma unroll
            for (int i = 0; i < 4; i++)
                #pragma unroll
                for (int j = 0; j < 8; j++)
                    mma1688tf(acc[i][j], afr[i], bfr[j]);
        }
        __syncthreads();
    }

    float* Cz = C + (size_t)blockIdx.z * M * N;
    #pragma unroll
    for (int i = 0; i < 4; i++) {
        #pragma unroll
        for (int half = 0; half < 2; half++) {
            int row = bm * 256 + warp_m * 64 + i * 16 + g + half * 8;
            #pragma unroll
            for (int j = 0; j < 8; j++) {
                int col = bn * 128 + warp_n * 64 + j * 8 + tig * 2;
                float v0 = acc[i][j][half * 2];
                float v1 = acc[i][j][half * 2 + 1];
                if (MODE == 1) {
                    v0 = tf32r(fmaxf(v0 + bias[col], 0.f));
                    v1 = tf32r(fmaxf(v1 + bias[col + 1], 0.f));
                    float2 o; o.x = v0; o.y = v1;
                    *(float2*)(C + (size_t)row * N + col) = o;
                } else {
                    float2 o; o.x = v0; o.y = v1;
                    *(float2*)(Cz + (size_t)row * N + col) = o;
                }
            }
        }
    }
}

// ---------------- Tensor-core flash attention (unchanged) ----------------------
#define TSTR 144
#define AQOFF 0
#define AKOFF 18432
#define AVOFF 36864
#define AMOFF 55296
#define ATT_SMEM 63488

__global__ void __launch_bounds__(256, 1)
attn_tc(const __nv_bfloat16* __restrict__ qkv, const int* __restrict__ mask,
        __nv_bfloat16* __restrict__ ao)
{
    extern __shared__ char smem[];
    uint32_t sb = smem_u32(smem);
    int tid = threadIdx.x, wid = tid >> 5, lane = tid & 31;
    int g = lane >> 2, tig = lane & 3;
    int bh = blockIdx.y;
    int b = bh >> 4, hd = bh & 15;
    int q0 = blockIdx.x * 128;

    const __nv_bfloat16* qg = qkv + (size_t)(b * SEQ) * QKVW + hd * DKH;

    #pragma unroll
    for (int i = 0; i < 4; i++) {
        int c = tid + i * 256;
        int row = c >> 3, kc = c & 7;
        cp16(sb + AQOFF + row * TSTR + kc * 16,
             qg + (size_t)(q0 + row) * QKVW + kc * 8);
    }
    #pragma unroll
    for (int i = 0; i < 2; i++) {
        int c = tid + i * 256;
        cp16(sb + AMOFF + c * 16, mask + (size_t)b * SEQ + c * 4);
    }
    auto load_kv = [&](int jt, int buf) {
        #pragma unroll
        for (int i = 0; i < 2; i++) {
            int c = tid + i * 256;
            int row = c >> 3, kc = c & 7;
            cp16(sb + AKOFF + buf * 9216 + row * TSTR + kc * 16,
                 qg + (size_t)(jt * 64 + row) * QKVW + EMB + kc * 8);
            cp16(sb + AVOFF + buf * 9216 + row * TSTR + kc * 16,
                 qg + (size_t)(jt * 64 + row) * QKVW + 2 * EMB + kc * 8);
        }
    };
    load_kv(0, 0);
    cp_commit();

    uint32_t qfr[4][4];
    float ofr[8][4];
    #pragma unroll
    for (int j = 0; j < 8; j++)
        #pragma unroll
        for (int r = 0; r < 4; r++) ofr[j][r] = 0.f;
    float m0 = -3.0e38f, m1 = -3.0e38f, l0 = 0.f, l1 = 0.f;

    uint32_t aQ = (uint32_t)(AQOFF + (wid * 16 + (lane & 15)) * TSTR + (lane >> 4) * 16);
    uint32_t bK = (uint32_t)((((lane >> 4) << 3) + (lane & 7)) * TSTR + ((lane >> 3) & 1) * 16);
    uint32_t bV = (uint32_t)((((lane >> 3) & 1) * 8 + (lane & 7)) * TSTR + (lane >> 4) * 16);

    const int NJT = SEQ / 64;
    for (int jt = 0; jt < NJT; jt++) {
        cp_wait<0>();
        __syncthreads();
        if (jt == 0) {
            #pragma unroll
            for (int ks = 0; ks < 4; ks++) ldsm_x4(qfr[ks], sb + aQ + ks * 32);
        }
        if (jt + 1 < NJT) { load_kv(jt + 1, (jt + 1) & 1); cp_commit(); }

        uint32_t kb = sb + AKOFF + (jt & 1) * 9216;
        uint32_t vb = sb + AVOFF + (jt & 1) * 9216;

        float sfr[8][4];
        #pragma unroll
        for (int j = 0; j < 8; j++)
            #pragma unroll
            for (int r = 0; r < 4; r++) sfr[j][r] = 0.f;
        #pragma unroll
        for (int ks = 0; ks < 4; ks++) {
            uint32_t bfr[4][4];
            #pragma unroll
            for (int ng = 0; ng < 4; ng++)
                ldsm_x4(bfr[ng], kb + bK + ng * 16 * TSTR + ks * 32);
            #pragma unroll
            for (int j = 0; j < 8; j++)
                mma16816(sfr[j], qfr[ks], &bfr[j >> 1][(j & 1) * 2]);
        }

        #pragma unroll
        for (int j = 0; j < 8; j++) {
            int2 mv = *(const int2*)(smem + AMOFF + (jt * 64 + j * 8 + tig * 2) * 4);
            sfr[j][0] = (mv.x == 0) ? -1e30f : sfr[j][0] * 0.125f;
            sfr[j][1] = (mv.y == 0) ? -1e30f : sfr[j][1] * 0.125f;
            sfr[j][2] = (mv.x == 0) ? -1e30f : sfr[j][2] * 0.125f;
            sfr[j][3] = (mv.y == 0) ? -1e30f : sfr[j][3] * 0.125f;
        }

        float mx0 = -3.0e38f, mx1 = -3.0e38f;
        #pragma unroll
        for (int j = 0; j < 8; j++) {
            mx0 = fmaxf(mx0, fmaxf(sfr[j][0], sfr[j][1]));
            mx1 = fmaxf(mx1, fmaxf(sfr[j][2], sfr[j][3]));
        }
        #pragma unroll
        for (int off = 1; off < 4; off <<= 1) {
            mx0 = fmaxf(mx0, __shfl_xor_sync(0xffffffffu, mx0, off));
            mx1 = fmaxf(mx1, __shfl_xor_sync(0xffffffffu, mx1, off));
        }
        float mn0 = fmaxf(m0, mx0), mn1 = fmaxf(m1, mx1);
        float al0 = __expf(m0 - mn0), al1 = __expf(m1 - mn1);
        float ls0 = 0.f, ls1 = 0.f;
        #pragma unroll
        for (int j = 0; j < 8; j++) {
            sfr[j][0] = __expf(sfr[j][0] - mn0);
            sfr[j][1] = __expf(sfr[j][1] - mn0);
            sfr[j][2] = __expf(sfr[j][2] - mn1);
            sfr[j][3] = __expf(sfr[j][3] - mn1);
            ls0 += sfr[j][0] + sfr[j][1];
            ls1 += sfr[j][2] + sfr[j][3];
        }
        #pragma unroll
        for (int off = 1; off < 4; off <<= 1) {
            ls0 += __shfl_xor_sync(0xffffffffu, ls0, off);
            ls1 += __shfl_xor_sync(0xffffffffu, ls1, off);
        }
        l0 = l0 * al0 + ls0; l1 = l1 * al1 + ls1;
        m0 = mn0; m1 = mn1;
        #pragma unroll
        for (int j = 0; j < 8; j++) {
            ofr[j][0] *= al0; ofr[j][1] *= al0;
            ofr[j][2] *= al1; ofr[j][3] *= al1;
        }

        #pragma unroll
        for (int ks = 0; ks < 4; ks++) {
            uint32_t pa[4];
            pa[0] = packbf(sfr[2*ks][0],   sfr[2*ks][1]);
            pa[1] = packbf(sfr[2*ks][2],   sfr[2*ks][3]);
            pa[2] = packbf(sfr[2*ks+1][0], sfr[2*ks+1][1]);
            pa[3] = packbf(sfr[2*ks+1][2], sfr[2*ks+1][3]);
            #pragma unroll
            for (int jp = 0; jp < 4; jp++) {
                uint32_t vfr[4];
                ldsm_x4t(vfr, vb + bV + ks * 16 * TSTR + jp * 32);
                mma16816(ofr[2*jp],     pa, &vfr[0]);
                mma16816(ofr[2*jp + 1], pa, &vfr[2]);
            }
        }
        __syncthreads();
    }

    float inv0 = 1.f / l0, inv1 = 1.f / l1;
    int r0 = b * SEQ + q0 + wid * 16 + g;
    #pragma unroll
    for (int half = 0; half < 2; half++) {
        int grow = r0 + half * 8;
        float inv = half ? inv1 : inv0;
        __nv_bfloat16* base = ao + (size_t)grow * EMB + hd * DKH;
        #pragma unroll
        for (int j = 0; j < 8; j++) {
            int col = j * 8 + tig * 2;
            __nv_bfloat162 hh = __floats2bfloat162_rn(ofr[j][half * 2] * inv,
                                                      ofr[j][half * 2 + 1] * inv);
            *(__nv_bfloat162*)(base + col) = hh;
        }
    }
}

// ---------------- launch ------------------------------------------------------
extern "C" void kernel_launch(void* const* d_in, const int* in_sizes, int n_in,
                              void* d_out, int out_size)
{
    const float* x    = (const float*)d_in[0];
    const int*   mask = (const int*)  d_in[1];
    const float* wq   = (const float*)d_in[2];
    const float* wk   = (const float*)d_in[3];
    const float* wv   = (const float*)d_in[4];
    const float* wo   = (const float*)d_in[5];
    const float* ff1w = (const float*)d_in[6];
    const float* ff1b = (const float*)d_in[7];
    const float* ff2w = (const float*)d_in[8];
    const float* ff2b = (const float*)d_in[9];
    const float* ln1a = (const float*)d_in[10];
    const float* ln1b = (const float*)d_in[11];
    const float* ln2a = (const float*)d_in[12];
    const float* ln2b = (const float*)d_in[13];
    float* out = (float*)d_out;

    __nv_bfloat16 *ab, *wp, *qkvh;
    float *xn2, *ffa, *wt32, *h, *part;
    cudaGetSymbolAddress((void**)&ab,   g_ab);
    cudaGetSymbolAddress((void**)&xn2,  g_xn2);
    cudaGetSymbolAddress((void**)&ffa,  g_ffa);
    cudaGetSymbolAddress((void**)&wt32, g_wt32);
    cudaGetSymbolAddress((void**)&wp,   g_wp);
    cudaGetSymbolAddress((void**)&qkvh, g_qkvh);
    cudaGetSymbolAddress((void**)&h,    g_h);
    cudaGetSymbolAddress((void**)&part, g_part);
    __nv_bfloat16* wpo = wp + (size_t)(3 * EMB) * EMB;

    cudaFuncSetAttribute(attn_tc, cudaFuncAttributeMaxDynamicSharedMemorySize, ATT_SMEM);
    cudaFuncSetAttribute(gemm_mma<0>, cudaFuncAttributeMaxDynamicSharedMemorySize, GSM_TOTAL);
    cudaFuncSetAttribute(gemm_mma<2>, cudaFuncAttributeMaxDynamicSharedMemorySize, GSM_TOTAL);
    cudaFuncSetAttribute(gemm_tf32<0>, cudaFuncAttributeMaxDynamicSharedMemorySize, FGSM_TOTAL);
    cudaFuncSetAttribute(gemm_tf32<1>, cudaFuncAttributeMaxDynamicSharedMemorySize, FGSM_TOTAL);

    dim3 gQKV(QKVW / 128, MROWS / 256, 1);   // (24, 16)
    dim3 gWO (EMB / 128,  MROWS / 256, 2);   // (8, 16, 2) split-K
    dim3 gFF1(HID / 128,  MROWS / 256, 1);   // (32, 16)
    dim3 gFF2(EMB / 128,  MROWS / 256, 4);   // (8, 16, 4) split-K

    // 1) ln1(x) -> ab (plain bf16)
    ln_plain_kernel<<<MROWS, 256>>>(x, ab, ln1a, ln1b);
    // 2-5) plain transposed wq|wk|wv|wo
    wt_plain_kernel<<<dim3(EMB/128, EMB/32), 256>>>(wq, wp, EMB, EMB);
    wt_plain_kernel<<<dim3(EMB/128, EMB/32), 256>>>(wk, wp + (size_t)EMB * EMB, EMB, EMB);
    wt_plain_kernel<<<dim3(EMB/128, EMB/32), 256>>>(wv, wp + (size_t)(2 * EMB) * EMB, EMB, EMB);
    wt_plain_kernel<<<dim3(EMB/128, EMB/32), 256>>>(wo, wpo, EMB, EMB);
    // 6) fused QKV projection (bf16, K=1024)
    gemm_mma<2><<<gQKV, 256, GSM_TOTAL>>>(ab, wp, nullptr, qkvh, nullptr, nullptr, MROWS, QKVW, EMB, 1);
    // 7) attention -> ab (plain bf16, reuse)
    attn_tc<<<dim3(SEQ / 128, BATCH * NH), 256, ATT_SMEM>>>(qkvh, mask, ab);
    // 8-9) wo partials (bf16, split-K=2); h = x + p0 + p1
    gemm_mma<0><<<gWO, 256, GSM_TOTAL>>>(ab, wpo, part, nullptr, nullptr, nullptr, MROWS, EMB, EMB, 2);
    reduce_kernel<2><<<MROWS, 256>>>(part, x, nullptr, h);
    // 10) ln2(h) -> xn2 (tf32 fp32)
    ln_tf32_kernel<<<MROWS, 256>>>(h, xn2, ln2a, ln2b);
    // 11-12) ff1 = relu(xn2 @ ff1_w + b) in tf32, K=1024
    wt_tf32_kernel<<<dim3(HID/128, EMB/32), 256>>>(ff1w, wt32, EMB, HID);
    gemm_tf32<1><<<gFF1, 256, FGSM_TOTAL>>>(xn2, wt32, ffa, ff1b, MROWS, HID, EMB, 1);
    // 13-15) ff2 tf32 partials (split-K=4, K=4096); out = h + bias + parts
    wt_tf32_kernel<<<dim3(EMB/128, HID/32), 256>>>(ff2w, wt32, HID, EMB);
    gemm_tf32<0><<<gFF2, 256, FGSM_TOTAL>>>(ffa, wt32, part, nullptr, MROWS, EMB, HID, 4);
    reduce_kernel<4><<<MROWS, 256>>>(part, h, ff2b, out);
}

// round 11
// speedup vs baseline: 6.7255x; 1.3739x over previous
#include <cuda_runtime.h>
#include <cuda_bf16.h>
#include <cuda_fp16.h>
#include <math.h>
#include <stdint.h>

#define EMB 1024
#define HID 4096
#define NH 16
#define DKH 64
#define BATCH 2
#define SEQ 2048
#define MROWS (BATCH * SEQ)     // 4096
#define QKVW (3 * EMB)

// ---------------- scratch (__device__ globals, allocation-free) ---------------
__device__ __nv_bfloat16 g_ab  [MROWS * EMB];            // ln1 out, later attn out
__device__ uint16_t      g_xh  [MROWS * EMB];            // ln2 out (fp16)
__device__ uint16_t      g_ffh [(size_t)MROWS * HID];    // relu(ff1) (fp16)
__device__ uint16_t      g_wh  [(size_t)HID * EMB];      // fp16 transposed ff1/ff2
__device__ __nv_bfloat16 g_wp  [(size_t)(4 * EMB) * EMB];// plain transposed qkv|wo
__device__ __nv_bfloat16 g_qkvh[(size_t)MROWS * QKVW];   // packed q|k|v bf16
__device__ float g_h   [MROWS * EMB];
__device__ float g_part[(size_t)4 * MROWS * EMB];        // split-K partials

// ---------------- PTX helpers (base ISA only) ----------------------------------
__device__ __forceinline__ uint32_t smem_u32(const void* p) {
    return (uint32_t)__cvta_generic_to_shared(p);
}
__device__ __forceinline__ void cp16(uint32_t dst, const void* src) {
    asm volatile("cp.async.cg.shared.global [%0], [%1], 16;" :: "r"(dst), "l"(src));
}
__device__ __forceinline__ void cp_commit() {
    asm volatile("cp.async.commit_group;");
}
template<int N> __device__ __forceinline__ void cp_wait() {
    asm volatile("cp.async.wait_group %0;" :: "n"(N));
}
__device__ __forceinline__ void ldsm_x4(uint32_t* r, uint32_t addr) {
    asm volatile("ldmatrix.sync.aligned.m8n8.x4.shared.b16 {%0,%1,%2,%3}, [%4];"
                 : "=r"(r[0]), "=r"(r[1]), "=r"(r[2]), "=r"(r[3]) : "r"(addr));
}
__device__ __forceinline__ void ldsm_x4t(uint32_t* r, uint32_t addr) {
    asm volatile("ldmatrix.sync.aligned.m8n8.x4.trans.shared.b16 {%0,%1,%2,%3}, [%4];"
                 : "=r"(r[0]), "=r"(r[1]), "=r"(r[2]), "=r"(r[3]) : "r"(addr));
}
template<int FP16>
__device__ __forceinline__ void mma16(float* d, const uint32_t* a, const uint32_t* b) {
    if (FP16)
        asm volatile(
            "mma.sync.aligned.m16n8k16.row.col.f32.f16.f16.f32 "
            "{%0,%1,%2,%3}, {%4,%5,%6,%7}, {%8,%9}, {%0,%1,%2,%3};"
            : "+f"(d[0]), "+f"(d[1]), "+f"(d[2]), "+f"(d[3])
            : "r"(a[0]), "r"(a[1]), "r"(a[2]), "r"(a[3]), "r"(b[0]), "r"(b[1]));
    else
        asm volatile(
            "mma.sync.aligned.m16n8k16.row.col.f32.bf16.bf16.f32 "
            "{%0,%1,%2,%3}, {%4,%5,%6,%7}, {%8,%9}, {%0,%1,%2,%3};"
            : "+f"(d[0]), "+f"(d[1]), "+f"(d[2]), "+f"(d[3])
            : "r"(a[0]), "r"(a[1]), "r"(a[2]), "r"(a[3]), "r"(b[0]), "r"(b[1]));
}
template<int FP16>
__device__ __forceinline__ uint32_t pack2(float a, float b) {
    if (FP16) { __half2 h = __floats2half2_rn(a, b); return *(uint32_t*)&h; }
    __nv_bfloat162 h = __floats2bfloat162_rn(a, b); return *(uint32_t*)&h;
}

// ---------------- LayerNorm ----------------------------------------------------
__device__ __forceinline__ void ln_stats(float4 v, float& mean, float& inv,
                                         const float* al) {
    float s  = v.x + v.y + v.z + v.w;
    float ss = v.x*v.x + v.y*v.y + v.z*v.z + v.w*v.w;
    #pragma unroll
    for (int off = 16; off; off >>= 1) {
        s  += __shfl_xor_sync(0xffffffffu, s,  off);
        ss += __shfl_xor_sync(0xffffffffu, ss, off);
    }
    __shared__ float rs[8], rss[8];
    int warp = threadIdx.x >> 5, lane = threadIdx.x & 31;
    if (lane == 0) { rs[warp] = s; rss[warp] = ss; }
    __syncthreads();
    if (warp == 0) {
        s  = (lane < 8) ? rs[lane]  : 0.f;
        ss = (lane < 8) ? rss[lane] : 0.f;
        #pragma unroll
        for (int off = 16; off; off >>= 1) {
            s  += __shfl_xor_sync(0xffffffffu, s,  off);
            ss += __shfl_xor_sync(0xffffffffu, ss, off);
        }
        if (lane == 0) { rs[0] = s; rss[0] = ss; }
    }
    __syncthreads();
    s = rs[0]; ss = rss[0];
    mean = s * (1.0f / EMB);
    float var = fmaxf(ss - (float)EMB * mean * mean, 0.f) * (1.0f / (EMB - 1));
    inv = al[0] / (sqrtf(var) + 1e-6f);
}

// ln -> 16-bit (FP16=1: half, FP16=0: bf16)
template<int FP16>
__global__ void ln16_kernel(const float* __restrict__ x, uint16_t* __restrict__ y,
                            const float* __restrict__ al, const float* __restrict__ be)
{
    int row = blockIdx.x;
    float4 v = ((const float4*)(x + (size_t)row * EMB))[threadIdx.x];
    float mean, inv;
    ln_stats(v, mean, inv, al);
    float bb = be[0];
    int col = threadIdx.x * 4;
    uint16_t* rowp = y + (size_t)row * EMB;
    *(uint32_t*)(rowp + col)     = pack2<FP16>((v.x - mean) * inv + bb, (v.y - mean) * inv + bb);
    *(uint32_t*)(rowp + col + 2) = pack2<FP16>((v.z - mean) * inv + bb, (v.w - mean) * inv + bb);
}

// ---------------- weight transpose: W[K,N] -> WT[N,K] 16-bit -------------------
template<int FP16>
__global__ void wt16_kernel(const float* __restrict__ W, uint16_t* __restrict__ WT,
                            int K, int N)
{
    __shared__ float t[32][132];
    int k0 = blockIdx.y * 32, n0 = blockIdx.x * 128;
    int tid = threadIdx.x;
    int lr = tid >> 5, lc = (tid & 31) * 4;
    #pragma unroll
    for (int i = 0; i < 4; i++) {
        float4 v = *(const float4*)&W[(size_t)(k0 + lr + 8*i) * N + n0 + lc];
        t[lr + 8*i][lc]     = v.x;
        t[lr + 8*i][lc + 1] = v.y;
        t[lr + 8*i][lc + 2] = v.z;
        t[lr + 8*i][lc + 3] = v.w;
    }
    __syncthreads();
    int n = tid >> 1, ks = (tid & 1) * 16;
    uint16_t* dst = WT + (size_t)(n0 + n) * K + k0 + ks;
    #pragma unroll
    for (int j = 0; j < 8; j++) {
        int k = ks + 2*j;
        *(uint32_t*)(dst + 2*j) = pack2<FP16>(t[k][n], t[k + 1][n]);
    }
}

// ---------------- split-K reduce: out = res + bias + sum(parts) ---------------
template<int NP>
__global__ void reduce_kernel(const float* __restrict__ parts, const float* __restrict__ res,
                              const float* __restrict__ bias, float* __restrict__ out)
{
    int row = blockIdx.x, col = threadIdx.x * 4;
    size_t idx = (size_t)row * EMB + col;
    float4 a = *(const float4*)(res + idx);
    if (bias) {
        float4 bb = *(const float4*)(bias + col);
        a.x += bb.x; a.y += bb.y; a.z += bb.z; a.w += bb.w;
    }
    #pragma unroll
    for (int p = 0; p < NP; p++) {
        float4 pv = *(const float4*)(parts + (size_t)p * MROWS * EMB + idx);
        a.x += pv.x; a.y += pv.y; a.z += pv.z; a.w += pv.w;
    }
    *(float4*)(out + idx) = a;
}

// ---------------- 16-bit mma.sync GEMM (256x128 CTA, 64x64 warp, BK=64) -------
// MODE 0: fp32 out (+bias/res, split-K via blockIdx.z).
// MODE 2: plain 16-bit out.  MODE 3: relu(x+bias) -> 16-bit out.
#define ASTR 144
#define A_STAGE (256 * ASTR)
#define B_STAGE (128 * ASTR)
#define STAGE_BYTES (A_STAGE + B_STAGE)      // 55296
#define GSM_TOTAL (3 * STAGE_BYTES)          // 165888

template<int MODE, int FP16>
__global__ void __launch_bounds__(256, 1)
gemm_mma(const uint16_t* __restrict__ A3, const uint16_t* __restrict__ BT3,
         float* __restrict__ C, uint16_t* __restrict__ Cs,
         const float* __restrict__ bias, const float* __restrict__ res,
         int M, int N, int K3, int ksplit)
{
    extern __shared__ char smem[];
    uint32_t sb = smem_u32(smem);
    int tid = threadIdx.x, wid = tid >> 5, lane = tid & 31;
    int bm = blockIdx.y, bn = blockIdx.x;
    int warp_m = wid >> 1, warp_n = wid & 1;

    const int Kc = K3 / ksplit;
    const int kbase = blockIdx.z * Kc;
    const int nk = Kc / 64;

    auto load_stage = [&](int k0, int st) {
        uint32_t base = sb + st * STAGE_BYTES;
        #pragma unroll
        for (int i = 0; i < 8; i++) {
            int c = tid + i * 256;
            int row = c >> 3, kc = c & 7;
            cp16(base + row * ASTR + kc * 16,
                 A3 + (size_t)(bm * 256 + row) * K3 + k0 + kc * 8);
        }
        #pragma unroll
        for (int i = 0; i < 4; i++) {
            int c = tid + i * 256;
            int row = c >> 3, kc = c & 7;
            cp16(base + A_STAGE + row * ASTR + kc * 16,
                 BT3 + (size_t)(bn * 128 + row) * K3 + k0 + kc * 8);
        }
        cp_commit();
    };

    load_stage(kbase, 0);
    load_stage(kbase + 64, 1);

    float acc[4][8][4];
    #pragma unroll
    for (int i = 0; i < 4; i++)
        #pragma unroll
        for (int j = 0; j < 8; j++)
            #pragma unroll
            for (int r = 0; r < 4; r++) acc[i][j][r] = 0.f;

    uint32_t aBase = (uint32_t)((warp_m * 64 + (lane & 15)) * ASTR + (lane >> 4) * 16);
    uint32_t bBase = (uint32_t)(A_STAGE +
                     (warp_n * 64 + ((lane >> 4) << 3) + (lane & 7)) * ASTR +
                     ((lane >> 3) & 1) * 16);

    for (int kt = 0; kt < nk; kt++) {
        cp_wait<1>();
        __syncthreads();
        int nxt = kt + 2;
        if (nxt < nk) load_stage(kbase + nxt * 64, nxt % 3);

        uint32_t stb = sb + (kt % 3) * STAGE_BYTES;
        #pragma unroll
        for (int s = 0; s < 4; s++) {
            uint32_t afr[4][4], bfr[4][4];
            #pragma unroll
            for (int i = 0; i < 4; i++)
                ldsm_x4(afr[i], stb + aBase + i * 16 * ASTR + s * 32);
            #pragma unroll
            for (int ng = 0; ng < 4; ng++)
                ldsm_x4(bfr[ng], stb + bBase + ng * 16 * ASTR + s * 32);
            #pragma unroll
            for (int i = 0; i < 4; i++) {
                #pragma unroll
                for (int j = 0; j < 8; j++)
                    mma16<FP16>(acc[i][j], afr[i], &bfr[j >> 1][(j & 1) * 2]);
            }
        }
        __syncthreads();
    }

    int g = lane >> 2, tig = lane & 3;
    float* Cz = (MODE == 0) ? C + (size_t)blockIdx.z * M * N : C;
    #pragma unroll
    for (int i = 0; i < 4; i++) {
        #pragma unroll
        for (int half = 0; half < 2; half++) {
            int row = bm * 256 + warp_m * 64 + i * 16 + g + half * 8;
            #pragma unroll
            for (int j = 0; j < 8; j++) {
                int col = bn * 128 + warp_n * 64 + j * 8 + tig * 2;
                float v0 = acc[i][j][half * 2];
                float v1 = acc[i][j][half * 2 + 1];
                if (MODE == 2) {
                    *(uint32_t*)(Cs + (size_t)row * N + col) = pack2<FP16>(v0, v1);
                } else if (MODE == 3) {
                    v0 = fmaxf(v0 + bias[col],     0.f);
                    v1 = fmaxf(v1 + bias[col + 1], 0.f);
                    *(uint32_t*)(Cs + (size_t)row * N + col) = pack2<FP16>(v0, v1);
                } else {
                    if (bias) { v0 += bias[col]; v1 += bias[col + 1]; }
                    size_t rb = (size_t)row * N;
                    if (res) {
                        float2 rr = *(const float2*)(res + rb + col);
                        v0 += rr.x; v1 += rr.y;
                    }
                    float2 o; o.x = v0; o.y = v1;
                    *(float2*)(Cz + rb + col) = o;
                }
            }
        }
    }
}

// ---------------- Tensor-core flash attention (unchanged) ----------------------
#define TSTR 144
#define AQOFF 0
#define AKOFF 18432
#define AVOFF 36864
#define AMOFF 55296
#define ATT_SMEM 63488

__device__ __forceinline__ uint32_t packbf(float a, float b) {
    __nv_bfloat162 h = __floats2bfloat162_rn(a, b);
    return *(uint32_t*)&h;
}

__global__ void __launch_bounds__(256, 1)
attn_tc(const __nv_bfloat16* __restrict__ qkv, const int* __restrict__ mask,
        __nv_bfloat16* __restrict__ ao)
{
    extern __shared__ char smem[];
    uint32_t sb = smem_u32(smem);
    int tid = threadIdx.x, wid = tid >> 5, lane = tid & 31;
    int g = lane >> 2, tig = lane & 3;
    int bh = blockIdx.y;
    int b = bh >> 4, hd = bh & 15;
    int q0 = blockIdx.x * 128;

    const __nv_bfloat16* qg = qkv + (size_t)(b * SEQ) * QKVW + hd * DKH;

    #pragma unroll
    for (int i = 0; i < 4; i++) {
        int c = tid + i * 256;
        int row = c >> 3, kc = c & 7;
        cp16(sb + AQOFF + row * TSTR + kc * 16,
             qg + (size_t)(q0 + row) * QKVW + kc * 8);
    }
    #pragma unroll
    for (int i = 0; i < 2; i++) {
        int c = tid + i * 256;
        cp16(sb + AMOFF + c * 16, mask + (size_t)b * SEQ + c * 4);
    }
    auto load_kv = [&](int jt, int buf) {
        #pragma unroll
        for (int i = 0; i < 2; i++) {
            int c = tid + i * 256;
            int row = c >> 3, kc = c & 7;
            cp16(sb + AKOFF + buf * 9216 + row * TSTR + kc * 16,
                 qg + (size_t)(jt * 64 + row) * QKVW + EMB + kc * 8);
            cp16(sb + AVOFF + buf * 9216 + row * TSTR + kc * 16,
                 qg + (size_t)(jt * 64 + row) * QKVW + 2 * EMB + kc * 8);
        }
    };
    load_kv(0, 0);
    cp_commit();

    uint32_t qfr[4][4];
    float ofr[8][4];
    #pragma unroll
    for (int j = 0; j < 8; j++)
        #pragma unroll
        for (int r = 0; r < 4; r++) ofr[j][r] = 0.f;
    float m0 = -3.0e38f, m1 = -3.0e38f, l0 = 0.f, l1 = 0.f;

    uint32_t aQ = (uint32_t)(AQOFF + (wid * 16 + (lane & 15)) * TSTR + (lane >> 4) * 16);
    uint32_t bK = (uint32_t)((((lane >> 4) << 3) + (lane & 7)) * TSTR + ((lane >> 3) & 1) * 16);
    uint32_t bV = (uint32_t)((((lane >> 3) & 1) * 8 + (lane & 7)) * TSTR + (lane >> 4) * 16);

    const int NJT = SEQ / 64;
    for (int jt = 0; jt < NJT; jt++) {
        cp_wait<0>();
        __syncthreads();
        if (jt == 0) {
            #pragma unroll
            for (int ks = 0; ks < 4; ks++) ldsm_x4(qfr[ks], sb + aQ + ks * 32);
        }
        if (jt + 1 < NJT) { load_kv(jt + 1, (jt + 1) & 1); cp_commit(); }

        uint32_t kb = sb + AKOFF + (jt & 1) * 9216;
        uint32_t vb = sb + AVOFF + (jt & 1) * 9216;

        float sfr[8][4];
        #pragma unroll
        for (int j = 0; j < 8; j++)
            #pragma unroll
            for (int r = 0; r < 4; r++) sfr[j][r] = 0.f;
        #pragma unroll
        for (int ks = 0; ks < 4; ks++) {
            uint32_t bfr[4][4];
            #pragma unroll
            for (int ng = 0; ng < 4; ng++)
                ldsm_x4(bfr[ng], kb + bK + ng * 16 * TSTR + ks * 32);
            #pragma unroll
            for (int j = 0; j < 8; j++)
                mma16<0>(sfr[j], qfr[ks], &bfr[j >> 1][(j & 1) * 2]);
        }

        #pragma unroll
        for (int j = 0; j < 8; j++) {
            int2 mv = *(const int2*)(smem + AMOFF + (jt * 64 + j * 8 + tig * 2) * 4);
            sfr[j][0] = (mv.x == 0) ? -1e30f : sfr[j][0] * 0.125f;
            sfr[j][1] = (mv.y == 0) ? -1e30f : sfr[j][1] * 0.125f;
            sfr[j][2] = (mv.x == 0) ? -1e30f : sfr[j][2] * 0.125f;
            sfr[j][3] = (mv.y == 0) ? -1e30f : sfr[j][3] * 0.125f;
        }

        float mx0 = -3.0e38f, mx1 = -3.0e38f;
        #pragma unroll
        for (int j = 0; j < 8; j++) {
            mx0 = fmaxf(mx0, fmaxf(sfr[j][0], sfr[j][1]));
            mx1 = fmaxf(mx1, fmaxf(sfr[j][2], sfr[j][3]));
        }
        #pragma unroll
        for (int off = 1; off < 4; off <<= 1) {
            mx0 = fmaxf(mx0, __shfl_xor_sync(0xffffffffu, mx0, off));
            mx1 = fmaxf(mx1, __shfl_xor_sync(0xffffffffu, mx1, off));
        }
        float mn0 = fmaxf(m0, mx0), mn1 = fmaxf(m1, mx1);
        float al0 = __expf(m0 - mn0), al1 = __expf(m1 - mn1);
        float ls0 = 0.f, ls1 = 0.f;
        #pragma unroll
        for (int j = 0; j < 8; j++) {
            sfr[j][0] = __expf(sfr[j][0] - mn0);
            sfr[j][1] = __expf(sfr[j][1] - mn0);
            sfr[j][2] = __expf(sfr[j][2] - mn1);
            sfr[j][3] = __expf(sfr[j][3] - mn1);
            ls0 += sfr[j][0] + sfr[j][1];
            ls1 += sfr[j][2] + sfr[j][3];
        }
        #pragma unroll
        for (int off = 1; off < 4; off <<= 1) {
            ls0 += __shfl_xor_sync(0xffffffffu, ls0, off);
            ls1 += __shfl_xor_sync(0xffffffffu, ls1, off);
        }
        l0 = l0 * al0 + ls0; l1 = l1 * al1 + ls1;
        m0 = mn0; m1 = mn1;
        #pragma unroll
        for (int j = 0; j < 8; j++) {
            ofr[j][0] *= al0; ofr[j][1] *= al0;
            ofr[j][2] *= al1; ofr[j][3] *= al1;
        }

        #pragma unroll
        for (int ks = 0; ks < 4; ks++) {
            uint32_t pa[4];
            pa[0] = packbf(sfr[2*ks][0],   sfr[2*ks][1]);
            pa[1] = packbf(sfr[2*ks][2],   sfr[2*ks][3]);
            pa[2] = packbf(sfr[2*ks+1][0], sfr[2*ks+1][1]);
            pa[3] = packbf(sfr[2*ks+1][2], sfr[2*ks+1][3]);
            #pragma unroll
            for (int jp = 0; jp < 4; jp++) {
                uint32_t vfr[4];
                ldsm_x4t(vfr, vb + bV + ks * 16 * TSTR + jp * 32);
                mma16<0>(ofr[2*jp],     pa, &vfr[0]);
                mma16<0>(ofr[2*jp + 1], pa, &vfr[2]);
            }
        }
        __syncthreads();
    }

    float inv0 = 1.f / l0, inv1 = 1.f / l1;
    int r0 = b * SEQ + q0 + wid * 16 + g;
    #pragma unroll
    for (int half = 0; half < 2; half++) {
        int grow = r0 + half * 8;
        float inv = half ? inv1 : inv0;
        __nv_bfloat16* base = ao + (size_t)grow * EMB + hd * DKH;
        #pragma unroll
        for (int j = 0; j < 8; j++) {
            int col = j * 8 + tig * 2;
            __nv_bfloat162 hh = __floats2bfloat162_rn(ofr[j][half * 2] * inv,
                                                      ofr[j][half * 2 + 1] * inv);
            *(__nv_bfloat162*)(base + col) = hh;
        }
    }
}

// ---------------- launch ------------------------------------------------------
extern "C" void kernel_launch(void* const* d_in, const int* in_sizes, int n_in,
                              void* d_out, int out_size)
{
    const float* x    = (const float*)d_in[0];
    const int*   mask = (const int*)  d_in[1];
    const float* wq   = (const float*)d_in[2];
    const float* wk   = (const float*)d_in[3];
    const float* wv   = (const float*)d_in[4];
    const float* wo   = (const float*)d_in[5];
    const float* ff1w = (const float*)d_in[6];
    const float* ff1b = (const float*)d_in[7];
    const float* ff2w = (const float*)d_in[8];
    const float* ff2b = (const float*)d_in[9];
    const float* ln1a = (const float*)d_in[10];
    const float* ln1b = (const float*)d_in[11];
    const float* ln2a = (const float*)d_in[12];
    const float* ln2b = (const float*)d_in[13];
    float* out = (float*)d_out;

    __nv_bfloat16 *ab, *wp, *qkvh;
    uint16_t *xh, *ffh, *wh;
    float *h, *part;
    cudaGetSymbolAddress((void**)&ab,   g_ab);
    cudaGetSymbolAddress((void**)&xh,   g_xh);
    cudaGetSymbolAddress((void**)&ffh,  g_ffh);
    cudaGetSymbolAddress((void**)&wh,   g_wh);
    cudaGetSymbolAddress((void**)&wp,   g_wp);
    cudaGetSymbolAddress((void**)&qkvh, g_qkvh);
    cudaGetSymbolAddress((void**)&h,    g_h);
    cudaGetSymbolAddress((void**)&part, g_part);
    __nv_bfloat16* wpo = wp + (size_t)(3 * EMB) * EMB;

    cudaFuncSetAttribute(attn_tc, cudaFuncAttributeMaxDynamicSharedMemorySize, ATT_SMEM);
    cudaFuncSetAttribute(gemm_mma<0,0>, cudaFuncAttributeMaxDynamicSharedMemorySize, GSM_TOTAL);
    cudaFuncSetAttribute(gemm_mma<2,0>, cudaFuncAttributeMaxDynamicSharedMemorySize, GSM_TOTAL);
    cudaFuncSetAttribute(gemm_mma<0,1>, cudaFuncAttributeMaxDynamicSharedMemorySize, GSM_TOTAL);
    cudaFuncSetAttribute(gemm_mma<3,1>, cudaFuncAttributeMaxDynamicSharedMemorySize, GSM_TOTAL);

    dim3 gQKV(QKVW / 128, MROWS / 256, 1);   // (24, 16)
    dim3 gWO (EMB / 128,  MROWS / 256, 2);   // (8, 16, 2) split-K
    dim3 gFF1(HID / 128,  MROWS / 256, 1);   // (32, 16)
    dim3 gFF2(EMB / 128,  MROWS / 256, 4);   // (8, 16, 4) split-K

    // 1) ln1(x) -> ab (bf16)
    ln16_kernel<0><<<MROWS, 256>>>(x, (uint16_t*)ab, ln1a, ln1b);
    // 2-5) plain transposed wq|wk|wv|wo (bf16)
    wt16_kernel<0><<<dim3(EMB/128, EMB/32), 256>>>(wq, (uint16_t*)wp, EMB, EMB);
    wt16_kernel<0><<<dim3(EMB/128, EMB/32), 256>>>(wk, (uint16_t*)(wp + (size_t)EMB * EMB), EMB, EMB);
    wt16_kernel<0><<<dim3(EMB/128, EMB/32), 256>>>(wv, (uint16_t*)(wp + (size_t)(2 * EMB) * EMB), EMB, EMB);
    wt16_kernel<0><<<dim3(EMB/128, EMB/32), 256>>>(wo, (uint16_t*)wpo, EMB, EMB);
    // 6) fused QKV projection (bf16, K=1024)
    gemm_mma<2,0><<<gQKV, 256, GSM_TOTAL>>>((const uint16_t*)ab, (const uint16_t*)wp,
                                            nullptr, (uint16_t*)qkvh, nullptr, nullptr,
                                            MROWS, QKVW, EMB, 1);
    // 7) attention -> ab (bf16, reuse)
    attn_tc<<<dim3(SEQ / 128, BATCH * NH), 256, ATT_SMEM>>>(qkvh, mask, ab);
    // 8-9) wo partials (bf16, split-K=2); h = x + p0 + p1
    gemm_mma<0,0><<<gWO, 256, GSM_TOTAL>>>((const uint16_t*)ab, (const uint16_t*)wpo,
                                           part, nullptr, nullptr, nullptr,
                                           MROWS, EMB, EMB, 2);
    reduce_kernel<2><<<MROWS, 256>>>(part, x, nullptr, h);
    // 10) ln2(h) -> xh (fp16)
    ln16_kernel<1><<<MROWS, 256>>>(h, xh, ln2a, ln2b);
    // 11-12) ff1 = relu(xh @ ff1_w + b) in fp16, K=1024
    wt16_kernel<1><<<dim3(HID/128, EMB/32), 256>>>(ff1w, wh, EMB, HID);
    gemm_mma<3,1><<<gFF1, 256, GSM_TOTAL>>>(xh, wh, nullptr, ffh, ff1b, nullptr,
                                            MROWS, HID, EMB, 1);
    // 13-15) ff2 fp16 partials (split-K=4, K=4096); out = h + bias + parts
    wt16_kernel<1><<<dim3(EMB/128, HID/32), 256>>>(ff2w, wh, HID, EMB);
    gemm_mma<0,1><<<gFF2, 256, GSM_TOTAL>>>(ffh, wh, part, nullptr, nullptr, nullptr,
                                            MROWS, EMB, HID, 4);
    reduce_kernel<4><<<MROWS, 256>>>(part, h, ff2b, out);
}

// round 12
// speedup vs baseline: 7.1236x; 1.0592x over previous
#include <cuda_runtime.h>
#include <cuda_bf16.h>
#include <cuda_fp16.h>
#include <math.h>
#include <stdint.h>

#define EMB 1024
#define HID 4096
#define NH 16
#define DKH 64
#define BATCH 2
#define SEQ 2048
#define MROWS (BATCH * SEQ)     // 4096
#define QKVW (3 * EMB)

// ---------------- scratch (__device__ globals, allocation-free) ---------------
__device__ __nv_bfloat16 g_ab  [MROWS * EMB];            // ln1 out, later attn out
__device__ uint16_t      g_xh  [MROWS * EMB];            // ln2 out (fp16)
__device__ uint16_t      g_ffh [(size_t)MROWS * HID];    // relu(ff1) (fp16)
__device__ uint16_t      g_wh  [(size_t)HID * EMB];      // fp16 transposed ff1/ff2
__device__ __nv_bfloat16 g_wp  [(size_t)(4 * EMB) * EMB];// plain transposed qkv|wo
__device__ __nv_bfloat16 g_qkvh[(size_t)MROWS * QKVW];   // packed q|k|v bf16
__device__ float g_h   [MROWS * EMB];
__device__ float g_part[(size_t)4 * MROWS * EMB];        // split-K partials

// ---------------- PTX helpers (base ISA only) ----------------------------------
__device__ __forceinline__ uint32_t smem_u32(const void* p) {
    return (uint32_t)__cvta_generic_to_shared(p);
}
__device__ __forceinline__ void cp16(uint32_t dst, const void* src) {
    asm volatile("cp.async.cg.shared.global [%0], [%1], 16;" :: "r"(dst), "l"(src));
}
__device__ __forceinline__ void cp_commit() {
    asm volatile("cp.async.commit_group;");
}
template<int N> __device__ __forceinline__ void cp_wait() {
    asm volatile("cp.async.wait_group %0;" :: "n"(N));
}
__device__ __forceinline__ void ldsm_x4(uint32_t* r, uint32_t addr) {
    asm volatile("ldmatrix.sync.aligned.m8n8.x4.shared.b16 {%0,%1,%2,%3}, [%4];"
                 : "=r"(r[0]), "=r"(r[1]), "=r"(r[2]), "=r"(r[3]) : "r"(addr));
}
__device__ __forceinline__ void ldsm_x4t(uint32_t* r, uint32_t addr) {
    asm volatile("ldmatrix.sync.aligned.m8n8.x4.trans.shared.b16 {%0,%1,%2,%3}, [%4];"
                 : "=r"(r[0]), "=r"(r[1]), "=r"(r[2]), "=r"(r[3]) : "r"(addr));
}
template<int FP16>
__device__ __forceinline__ void mma16(float* d, const uint32_t* a, const uint32_t* b) {
    if (FP16)
        asm volatile(
            "mma.sync.aligned.m16n8k16.row.col.f32.f16.f16.f32 "
            "{%0,%1,%2,%3}, {%4,%5,%6,%7}, {%8,%9}, {%0,%1,%2,%3};"
            : "+f"(d[0]), "+f"(d[1]), "+f"(d[2]), "+f"(d[3])
            : "r"(a[0]), "r"(a[1]), "r"(a[2]), "r"(a[3]), "r"(b[0]), "r"(b[1]));
    else
        asm volatile(
            "mma.sync.aligned.m16n8k16.row.col.f32.bf16.bf16.f32 "
            "{%0,%1,%2,%3}, {%4,%5,%6,%7}, {%8,%9}, {%0,%1,%2,%3};"
            : "+f"(d[0]), "+f"(d[1]), "+f"(d[2]), "+f"(d[3])
            : "r"(a[0]), "r"(a[1]), "r"(a[2]), "r"(a[3]), "r"(b[0]), "r"(b[1]));
}
template<int FP16>
__device__ __forceinline__ uint32_t pack2(float a, float b) {
    if (FP16) { __half2 h = __floats2half2_rn(a, b); return *(uint32_t*)&h; }
    __nv_bfloat162 h = __floats2bfloat162_rn(a, b); return *(uint32_t*)&h;
}
__device__ __forceinline__ uint32_t packbf(float a, float b) {
    __nv_bfloat162 h = __floats2bfloat162_rn(a, b);
    return *(uint32_t*)&h;
}

// ---------------- LayerNorm ----------------------------------------------------
__device__ __forceinline__ void ln_stats(float4 v, float& mean, float& inv,
                                         const float* al) {
    float s  = v.x + v.y + v.z + v.w;
    float ss = v.x*v.x + v.y*v.y + v.z*v.z + v.w*v.w;
    #pragma unroll
    for (int off = 16; off; off >>= 1) {
        s  += __shfl_xor_sync(0xffffffffu, s,  off);
        ss += __shfl_xor_sync(0xffffffffu, ss, off);
    }
    __shared__ float rs[8], rss[8];
    int warp = threadIdx.x >> 5, lane = threadIdx.x & 31;
    if (lane == 0) { rs[warp] = s; rss[warp] = ss; }
    __syncthreads();
    if (warp == 0) {
        s  = (lane < 8) ? rs[lane]  : 0.f;
        ss = (lane < 8) ? rss[lane] : 0.f;
        #pragma unroll
        for (int off = 16; off; off >>= 1) {
            s  += __shfl_xor_sync(0xffffffffu, s,  off);
            ss += __shfl_xor_sync(0xffffffffu, ss, off);
        }
        if (lane == 0) { rs[0] = s; rss[0] = ss; }
    }
    __syncthreads();
    s = rs[0]; ss = rss[0];
    mean = s * (1.0f / EMB);
    float var = fmaxf(ss - (float)EMB * mean * mean, 0.f) * (1.0f / (EMB - 1));
    inv = al[0] / (sqrtf(var) + 1e-6f);
}

template<int FP16>
__global__ void ln16_kernel(const float* __restrict__ x, uint16_t* __restrict__ y,
                            const float* __restrict__ al, const float* __restrict__ be)
{
    int row = blockIdx.x;
    float4 v = ((const float4*)(x + (size_t)row * EMB))[threadIdx.x];
    float mean, inv;
    ln_stats(v, mean, inv, al);
    float bb = be[0];
    int col = threadIdx.x * 4;
    uint16_t* rowp = y + (size_t)row * EMB;
    *(uint32_t*)(rowp + col)     = pack2<FP16>((v.x - mean) * inv + bb, (v.y - mean) * inv + bb);
    *(uint32_t*)(rowp + col + 2) = pack2<FP16>((v.z - mean) * inv + bb, (v.w - mean) * inv + bb);
}

// fused: h = x + p0 + p1 ; xh = fp16(ln2(h))
__global__ void reduce2_ln_kernel(const float* __restrict__ parts, const float* __restrict__ x,
                                  float* __restrict__ hout, uint16_t* __restrict__ yh,
                                  const float* __restrict__ al, const float* __restrict__ be)
{
    int row = blockIdx.x, col = threadIdx.x * 4;
    size_t idx = (size_t)row * EMB + col;
    float4 a  = *(const float4*)(x + idx);
    float4 p0 = *(const float4*)(parts + idx);
    float4 p1 = *(const float4*)(parts + (size_t)MROWS * EMB + idx);
    a.x += p0.x + p1.x; a.y += p0.y + p1.y; a.z += p0.z + p1.z; a.w += p0.w + p1.w;
    *(float4*)(hout + idx) = a;
    float mean, inv;
    ln_stats(a, mean, inv, al);
    float bb = be[0];
    uint16_t* rowp = yh + (size_t)row * EMB;
    *(uint32_t*)(rowp + col)     = pack2<1>((a.x - mean) * inv + bb, (a.y - mean) * inv + bb);
    *(uint32_t*)(rowp + col + 2) = pack2<1>((a.z - mean) * inv + bb, (a.w - mean) * inv + bb);
}

// ---------------- weight transpose: W[K,N] -> WT[N,K] 16-bit -------------------
template<int FP16>
__global__ void wt16_kernel(const float* __restrict__ W, uint16_t* __restrict__ WT,
                            int K, int N)
{
    __shared__ float t[32][132];
    int k0 = blockIdx.y * 32, n0 = blockIdx.x * 128;
    int tid = threadIdx.x;
    int lr = tid >> 5, lc = (tid & 31) * 4;
    #pragma unroll
    for (int i = 0; i < 4; i++) {
        float4 v = *(const float4*)&W[(size_t)(k0 + lr + 8*i) * N + n0 + lc];
        t[lr + 8*i][lc]     = v.x;
        t[lr + 8*i][lc + 1] = v.y;
        t[lr + 8*i][lc + 2] = v.z;
        t[lr + 8*i][lc + 3] = v.w;
    }
    __syncthreads();
    int n = tid >> 1, ks = (tid & 1) * 16;
    uint16_t* dst = WT + (size_t)(n0 + n) * K + k0 + ks;
    #pragma unroll
    for (int j = 0; j < 8; j++) {
        int k = ks + 2*j;
        *(uint32_t*)(dst + 2*j) = pack2<FP16>(t[k][n], t[k + 1][n]);
    }
}

// ---------------- split-K reduce: out = res + bias + sum(parts) ---------------
template<int NP>
__global__ void reduce_kernel(const float* __restrict__ parts, const float* __restrict__ res,
                              const float* __restrict__ bias, float* __restrict__ out)
{
    int row = blockIdx.x, col = threadIdx.x * 4;
    size_t idx = (size_t)row * EMB + col;
    float4 a = *(const float4*)(res + idx);
    if (bias) {
        float4 bb = *(const float4*)(bias + col);
        a.x += bb.x; a.y += bb.y; a.z += bb.z; a.w += bb.w;
    }
    #pragma unroll
    for (int p = 0; p < NP; p++) {
        float4 pv = *(const float4*)(parts + (size_t)p * MROWS * EMB + idx);
        a.x += pv.x; a.y += pv.y; a.z += pv.z; a.w += pv.w;
    }
    *(float4*)(out + idx) = a;
}

// ---------------- 16-bit mma.sync GEMM (256x128 CTA, 64x64 warp, BK=64) -------
#define ASTR 144
#define A_STAGE (256 * ASTR)
#define B_STAGE (128 * ASTR)
#define STAGE_BYTES (A_STAGE + B_STAGE)      // 55296
#define GSM_TOTAL (3 * STAGE_BYTES)          // 165888

template<int MODE, int FP16>
__global__ void __launch_bounds__(256, 1)
gemm_mma(const uint16_t* __restrict__ A3, const uint16_t* __restrict__ BT3,
         float* __restrict__ C, uint16_t* __restrict__ Cs,
         const float* __restrict__ bias, const float* __restrict__ res,
         int M, int N, int K3, int ksplit)
{
    extern __shared__ char smem[];
    uint32_t sb = smem_u32(smem);
    int tid = threadIdx.x, wid = tid >> 5, lane = tid & 31;
    int bm = blockIdx.y, bn = blockIdx.x;
    int warp_m = wid >> 1, warp_n = wid & 1;

    const int Kc = K3 / ksplit;
    const int kbase = blockIdx.z * Kc;
    const int nk = Kc / 64;

    auto load_stage = [&](int k0, int st) {
        uint32_t base = sb + st * STAGE_BYTES;
        #pragma unroll
        for (int i = 0; i < 8; i++) {
            int c = tid + i * 256;
            int row = c >> 3, kc = c & 7;
            cp16(base + row * ASTR + kc * 16,
                 A3 + (size_t)(bm * 256 + row) * K3 + k0 + kc * 8);
        }
        #pragma unroll
        for (int i = 0; i < 4; i++) {
            int c = tid + i * 256;
            int row = c >> 3, kc = c & 7;
            cp16(base + A_STAGE + row * ASTR + kc * 16,
                 BT3 + (size_t)(bn * 128 + row) * K3 + k0 + kc * 8);
        }
        cp_commit();
    };

    load_stage(kbase, 0);
    load_stage(kbase + 64, 1);

    float acc[4][8][4];
    #pragma unroll
    for (int i = 0; i < 4; i++)
        #pragma unroll
        for (int j = 0; j < 8; j++)
            #pragma unroll
            for (int r = 0; r < 4; r++) acc[i][j][r] = 0.f;

    uint32_t aBase = (uint32_t)((warp_m * 64 + (lane & 15)) * ASTR + (lane >> 4) * 16);
    uint32_t bBase = (uint32_t)(A_STAGE +
                     (warp_n * 64 + ((lane >> 4) << 3) + (lane & 7)) * ASTR +
                     ((lane >> 3) & 1) * 16);

    for (int kt = 0; kt < nk; kt++) {
        cp_wait<1>();
        __syncthreads();
        int nxt = kt + 2;
        if (nxt < nk) load_stage(kbase + nxt * 64, nxt % 3);

        uint32_t stb = sb + (kt % 3) * STAGE_BYTES;
        #pragma unroll
        for (int s = 0; s < 4; s++) {
            uint32_t afr[4][4], bfr[4][4];
            #pragma unroll
            for (int i = 0; i < 4; i++)
                ldsm_x4(afr[i], stb + aBase + i * 16 * ASTR + s * 32);
            #pragma unroll
            for (int ng = 0; ng < 4; ng++)
                ldsm_x4(bfr[ng], stb + bBase + ng * 16 * ASTR + s * 32);
            #pragma unroll
            for (int i = 0; i < 4; i++) {
                #pragma unroll
                for (int j = 0; j < 8; j++)
                    mma16<FP16>(acc[i][j], afr[i], &bfr[j >> 1][(j & 1) * 2]);
            }
        }
        __syncthreads();
    }

    int g = lane >> 2, tig = lane & 3;
    float* Cz = (MODE == 0) ? C + (size_t)blockIdx.z * M * N : C;
    #pragma unroll
    for (int i = 0; i < 4; i++) {
        #pragma unroll
        for (int half = 0; half < 2; half++) {
            int row = bm * 256 + warp_m * 64 + i * 16 + g + half * 8;
            #pragma unroll
            for (int j = 0; j < 8; j++) {
                int col = bn * 128 + warp_n * 64 + j * 8 + tig * 2;
                float v0 = acc[i][j][half * 2];
                float v1 = acc[i][j][half * 2 + 1];
                if (MODE == 2) {
                    *(uint32_t*)(Cs + (size_t)row * N + col) = pack2<FP16>(v0, v1);
                } else if (MODE == 3) {
                    v0 = fmaxf(v0 + bias[col],     0.f);
                    v1 = fmaxf(v1 + bias[col + 1], 0.f);
                    *(uint32_t*)(Cs + (size_t)row * N + col) = pack2<FP16>(v0, v1);
                } else {
                    if (bias) { v0 += bias[col]; v1 += bias[col + 1]; }
                    size_t rb = (size_t)row * N;
                    if (res) {
                        float2 rr = *(const float2*)(res + rb + col);
                        v0 += rr.x; v1 += rr.y;
                    }
                    float2 o; o.x = v0; o.y = v1;
                    *(float2*)(Cz + rb + col) = o;
                }
            }
        }
    }
}

// ---------------- Tensor-core flash attention (256 q-rows/CTA, 32/warp) -------
#define TSTR 144
#define AQOFF 0                        // Q: 256 x 144 = 36864
#define AKOFF 36864                    // K: 2 x 64 x 144 = 18432
#define AVOFF 55296                    // V: 18432
#define AMOFF 73728                    // mask: 8192
#define ATT_SMEM 81920

__global__ void __launch_bounds__(256, 1)
attn_tc(const __nv_bfloat16* __restrict__ qkv, const int* __restrict__ mask,
        __nv_bfloat16* __restrict__ ao)
{
    extern __shared__ char smem[];
    uint32_t sb = smem_u32(smem);
    int tid = threadIdx.x, wid = tid >> 5, lane = tid & 31;
    int g = lane >> 2, tig = lane & 3;
    int bh = blockIdx.y;
    int b = bh >> 4, hd = bh & 15;
    int q0 = blockIdx.x * 256;

    const __nv_bfloat16* qg = qkv + (size_t)(b * SEQ) * QKVW + hd * DKH;

    #pragma unroll
    for (int i = 0; i < 8; i++) {                  // Q: 2048 chunks
        int c = tid + i * 256;
        int row = c >> 3, kc = c & 7;
        cp16(sb + AQOFF + row * TSTR + kc * 16,
             qg + (size_t)(q0 + row) * QKVW + kc * 8);
    }
    #pragma unroll
    for (int i = 0; i < 2; i++) {
        int c = tid + i * 256;
        cp16(sb + AMOFF + c * 16, mask + (size_t)b * SEQ + c * 4);
    }
    auto load_kv = [&](int jt, int buf) {
        #pragma unroll
        for (int i = 0; i < 2; i++) {
            int c = tid + i * 256;
            int row = c >> 3, kc = c & 7;
            cp16(sb + AKOFF + buf * 9216 + row * TSTR + kc * 16,
                 qg + (size_t)(jt * 64 + row) * QKVW + EMB + kc * 8);
            cp16(sb + AVOFF + buf * 9216 + row * TSTR + kc * 16,
                 qg + (size_t)(jt * 64 + row) * QKVW + 2 * EMB + kc * 8);
        }
    };
    load_kv(0, 0);
    cp_commit();

    uint32_t qfr[2][4][4];
    float ofr[2][8][4];
    #pragma unroll
    for (int rb = 0; rb < 2; rb++)
        #pragma unroll
        for (int j = 0; j < 8; j++)
            #pragma unroll
            for (int r = 0; r < 4; r++) ofr[rb][j][r] = 0.f;
    float mm[2][2], ll[2][2];
    #pragma unroll
    for (int rb = 0; rb < 2; rb++) { mm[rb][0] = mm[rb][1] = -3.0e38f; ll[rb][0] = ll[rb][1] = 0.f; }

    uint32_t aQ0 = (uint32_t)(AQOFF + (wid * 32 + (lane & 15)) * TSTR + (lane >> 4) * 16);
    uint32_t bK  = (uint32_t)((((lane >> 4) << 3) + (lane & 7)) * TSTR + ((lane >> 3) & 1) * 16);
    uint32_t bV  = (uint32_t)((((lane >> 3) & 1) * 8 + (lane & 7)) * TSTR + (lane >> 4) * 16);

    const int NJT = SEQ / 64;
    for (int jt = 0; jt < NJT; jt++) {
        cp_wait<0>();
        __syncthreads();
        if (jt == 0) {
            #pragma unroll
            for (int rb = 0; rb < 2; rb++)
                #pragma unroll
                for (int ks = 0; ks < 4; ks++)
                    ldsm_x4(qfr[rb][ks], sb + aQ0 + rb * 16 * TSTR + ks * 32);
        }
        if (jt + 1 < NJT) { load_kv(jt + 1, (jt + 1) & 1); cp_commit(); }

        uint32_t kb = sb + AKOFF + (jt & 1) * 9216;
        uint32_t vb = sb + AVOFF + (jt & 1) * 9216;

        // S = Q @ K^T for both row-blocks; K fragments loaded ONCE
        float sfr[2][8][4];
        #pragma unroll
        for (int rb = 0; rb < 2; rb++)
            #pragma unroll
            for (int j = 0; j < 8; j++)
                #pragma unroll
                for (int r = 0; r < 4; r++) sfr[rb][j][r] = 0.f;
        #pragma unroll
        for (int ks = 0; ks < 4; ks++) {
            uint32_t bfr[4][4];
            #pragma unroll
            for (int ng = 0; ng < 4; ng++)
                ldsm_x4(bfr[ng], kb + bK + ng * 16 * TSTR + ks * 32);
            #pragma unroll
            for (int rb = 0; rb < 2; rb++)
                #pragma unroll
                for (int j = 0; j < 8; j++)
                    mma16<0>(sfr[rb][j], qfr[rb][ks], &bfr[j >> 1][(j & 1) * 2]);
        }

        // scale + mask + online softmax per row-block
        #pragma unroll
        for (int rb = 0; rb < 2; rb++) {
            #pragma unroll
            for (int j = 0; j < 8; j++) {
                int2 mv = *(const int2*)(smem + AMOFF + (jt * 64 + j * 8 + tig * 2) * 4);
                sfr[rb][j][0] = (mv.x == 0) ? -1e30f : sfr[rb][j][0] * 0.125f;
                sfr[rb][j][1] = (mv.y == 0) ? -1e30f : sfr[rb][j][1] * 0.125f;
                sfr[rb][j][2] = (mv.x == 0) ? -1e30f : sfr[rb][j][2] * 0.125f;
                sfr[rb][j][3] = (mv.y == 0) ? -1e30f : sfr[rb][j][3] * 0.125f;
            }
            float mx0 = -3.0e38f, mx1 = -3.0e38f;
            #pragma unroll
            for (int j = 0; j < 8; j++) {
                mx0 = fmaxf(mx0, fmaxf(sfr[rb][j][0], sfr[rb][j][1]));
                mx1 = fmaxf(mx1, fmaxf(sfr[rb][j][2], sfr[rb][j][3]));
            }
            #pragma unroll
            for (int off = 1; off < 4; off <<= 1) {
                mx0 = fmaxf(mx0, __shfl_xor_sync(0xffffffffu, mx0, off));
                mx1 = fmaxf(mx1, __shfl_xor_sync(0xffffffffu, mx1, off));
            }
            float mn0 = fmaxf(mm[rb][0], mx0), mn1 = fmaxf(mm[rb][1], mx1);
            float al0 = __expf(mm[rb][0] - mn0), al1 = __expf(mm[rb][1] - mn1);
            float ls0 = 0.f, ls1 = 0.f;
            #pragma unroll
            for (int j = 0; j < 8; j++) {
                sfr[rb][j][0] = __expf(sfr[rb][j][0] - mn0);
                sfr[rb][j][1] = __expf(sfr[rb][j][1] - mn0);
                sfr[rb][j][2] = __expf(sfr[rb][j][2] - mn1);
                sfr[rb][j][3] = __expf(sfr[rb][j][3] - mn1);
                ls0 += sfr[rb][j][0] + sfr[rb][j][1];
                ls1 += sfr[rb][j][2] + sfr[rb][j][3];
            }
            #pragma unroll
            for (int off = 1; off < 4; off <<= 1) {
                ls0 += __shfl_xor_sync(0xffffffffu, ls0, off);
                ls1 += __shfl_xor_sync(0xffffffffu, ls1, off);
            }
            ll[rb][0] = ll[rb][0] * al0 + ls0;
            ll[rb][1] = ll[rb][1] * al1 + ls1;
            mm[rb][0] = mn0; mm[rb][1] = mn1;
            #pragma unroll
            for (int j = 0; j < 8; j++) {
                ofr[rb][j][0] *= al0; ofr[rb][j][1] *= al0;
                ofr[rb][j][2] *= al1; ofr[rb][j][3] *= al1;
            }
        }

        // O += P @ V ; V fragments loaded ONCE per (ks, jp)
        #pragma unroll
        for (int ks = 0; ks < 4; ks++) {
            uint32_t pa[2][4];
            #pragma unroll
            for (int rb = 0; rb < 2; rb++) {
                pa[rb][0] = packbf(sfr[rb][2*ks][0],   sfr[rb][2*ks][1]);
                pa[rb][1] = packbf(sfr[rb][2*ks][2],   sfr[rb][2*ks][3]);
                pa[rb][2] = packbf(sfr[rb][2*ks+1][0], sfr[rb][2*ks+1][1]);
                pa[rb][3] = packbf(sfr[rb][2*ks+1][2], sfr[rb][2*ks+1][3]);
            }
            #pragma unroll
            for (int jp = 0; jp < 4; jp++) {
                uint32_t vfr[4];
                ldsm_x4t(vfr, vb + bV + ks * 16 * TSTR + jp * 32);
                #pragma unroll
                for (int rb = 0; rb < 2; rb++) {
                    mma16<0>(ofr[rb][2*jp],     pa[rb], &vfr[0]);
                    mma16<0>(ofr[rb][2*jp + 1], pa[rb], &vfr[2]);
                }
            }
        }
        __syncthreads();
    }

    // epilogue
    #pragma unroll
    for (int rb = 0; rb < 2; rb++) {
        float inv0 = 1.f / ll[rb][0], inv1 = 1.f / ll[rb][1];
        int r0 = b * SEQ + q0 + wid * 32 + rb * 16 + g;
        #pragma unroll
        for (int half = 0; half < 2; half++) {
            int grow = r0 + half * 8;
            float inv = half ? inv1 : inv0;
            __nv_bfloat16* base = ao + (size_t)grow * EMB + hd * DKH;
            #pragma unroll
            for (int j = 0; j < 8; j++) {
                int col = j * 8 + tig * 2;
                __nv_bfloat162 hh = __floats2bfloat162_rn(ofr[rb][j][half * 2] * inv,
                                                          ofr[rb][j][half * 2 + 1] * inv);
                *(__nv_bfloat162*)(base + col) = hh;
            }
        }
    }
}

// ---------------- launch ------------------------------------------------------
extern "C" void kernel_launch(void* const* d_in, const int* in_sizes, int n_in,
                              void* d_out, int out_size)
{
    const float* x    = (const float*)d_in[0];
    const int*   mask = (const int*)  d_in[1];
    const float* wq   = (const float*)d_in[2];
    const float* wk   = (const float*)d_in[3];
    const float* wv   = (const float*)d_in[4];
    const float* wo   = (const float*)d_in[5];
    const float* ff1w = (const float*)d_in[6];
    const float* ff1b = (const float*)d_in[7];
    const float* ff2w = (const float*)d_in[8];
    const float* ff2b = (const float*)d_in[9];
    const float* ln1a = (const float*)d_in[10];
    const float* ln1b = (const float*)d_in[11];
    const float* ln2a = (const float*)d_in[12];
    const float* ln2b = (const float*)d_in[13];
    float* out = (float*)d_out;

    __nv_bfloat16 *ab, *wp, *qkvh;
    uint16_t *xh, *ffh, *wh;
    float *h, *part;
    cudaGetSymbolAddress((void**)&ab,   g_ab);
    cudaGetSymbolAddress((void**)&xh,   g_xh);
    cudaGetSymbolAddress((void**)&ffh,  g_ffh);
    cudaGetSymbolAddress((void**)&wh,   g_wh);
    cudaGetSymbolAddress((void**)&wp,   g_wp);
    cudaGetSymbolAddress((void**)&qkvh, g_qkvh);
    cudaGetSymbolAddress((void**)&h,    g_h);
    cudaGetSymbolAddress((void**)&part, g_part);
    __nv_bfloat16* wpo = wp + (size_t)(3 * EMB) * EMB;

    cudaFuncSetAttribute(attn_tc, cudaFuncAttributeMaxDynamicSharedMemorySize, ATT_SMEM);
    cudaFuncSetAttribute(gemm_mma<0,0>, cudaFuncAttributeMaxDynamicSharedMemorySize, GSM_TOTAL);
    cudaFuncSetAttribute(gemm_mma<2,0>, cudaFuncAttributeMaxDynamicSharedMemorySize, GSM_TOTAL);
    cudaFuncSetAttribute(gemm_mma<0,1>, cudaFuncAttributeMaxDynamicSharedMemorySize, GSM_TOTAL);
    cudaFuncSetAttribute(gemm_mma<3,1>, cudaFuncAttributeMaxDynamicSharedMemorySize, GSM_TOTAL);

    dim3 gQKV(QKVW / 128, MROWS / 256, 1);   // (24, 16)
    dim3 gWO (EMB / 128,  MROWS / 256, 2);   // (8, 16, 2) split-K
    dim3 gFF1(HID / 128,  MROWS / 256, 1);   // (32, 16)
    dim3 gFF2(EMB / 128,  MROWS / 256, 4);   // (8, 16, 4) split-K

    // 1) ln1(x) -> ab (bf16)
    ln16_kernel<0><<<MROWS, 256>>>(x, (uint16_t*)ab, ln1a, ln1b);
    // 2-5) plain transposed wq|wk|wv|wo (bf16)
    wt16_kernel<0><<<dim3(EMB/128, EMB/32), 256>>>(wq, (uint16_t*)wp, EMB, EMB);
    wt16_kernel<0><<<dim3(EMB/128, EMB/32), 256>>>(wk, (uint16_t*)(wp + (size_t)EMB * EMB), EMB, EMB);
    wt16_kernel<0><<<dim3(EMB/128, EMB/32), 256>>>(wv, (uint16_t*)(wp + (size_t)(2 * EMB) * EMB), EMB, EMB);
    wt16_kernel<0><<<dim3(EMB/128, EMB/32), 256>>>(wo, (uint16_t*)wpo, EMB, EMB);
    // 6) fused QKV projection (bf16, K=1024)
    gemm_mma<2,0><<<gQKV, 256, GSM_TOTAL>>>((const uint16_t*)ab, (const uint16_t*)wp,
                                            nullptr, (uint16_t*)qkvh, nullptr, nullptr,
                                            MROWS, QKVW, EMB, 1);
    // 7) attention -> ab (bf16, reuse), 256 q-rows per CTA
    attn_tc<<<dim3(SEQ / 256, BATCH * NH), 256, ATT_SMEM>>>(qkvh, mask, ab);
    // 8) wo partials (bf16, split-K=2)
    gemm_mma<0,0><<<gWO, 256, GSM_TOTAL>>>((const uint16_t*)ab, (const uint16_t*)wpo,
                                           part, nullptr, nullptr, nullptr,
                                           MROWS, EMB, EMB, 2);
    // 9) fused: h = x + p0 + p1 ; xh = fp16(ln2(h))
    reduce2_ln_kernel<<<MROWS, 256>>>(part, x, h, xh, ln2a, ln2b);
    // 10-11) ff1 = relu(xh @ ff1_w + b) in fp16, K=1024
    wt16_kernel<1><<<dim3(HID/128, EMB/32), 256>>>(ff1w, wh, EMB, HID);
    gemm_mma<3,1><<<gFF1, 256, GSM_TOTAL>>>(xh, wh, nullptr, ffh, ff1b, nullptr,
                                            MROWS, HID, EMB, 1);
    // 12-14) ff2 fp16 partials (split-K=4, K=4096); out = h + bias + parts
    wt16_kernel<1><<<dim3(EMB/128, HID/32), 256>>>(ff2w, wh, HID, EMB);
    gemm_mma<0,1><<<gFF2, 256, GSM_TOTAL>>>(ffh, wh, part, nullptr, nullptr, nullptr,
                                            MROWS, EMB, HID, 4);
    reduce_kernel<4><<<MROWS, 256>>>(part, h, ff2b, out);
}